// round 2
// baseline (speedup 1.0000x reference)
#include <cuda_runtime.h>
#include <cstdint>

// Bidirectional GRU (B=32768, T=18, I=2, H=64) + fc1(128->24) + reshape + fc2(18->2)
// R2: j-dimension packed fma.rn.f32x2 — h pairs in b64 regs, weight pairs via LDS.128.

#define BTOT   32768
#define TT     18
#define HH     64
#define NTHR   128

__device__ __forceinline__ float sig_(float x) {
    return 1.0f / (1.0f + __expf(-x));
}
__device__ __forceinline__ float tanh_(float x) {
    return 2.0f / (1.0f + __expf(-2.0f * x)) - 1.0f;
}

__device__ __forceinline__ uint64_t pack2(float lo, float hi) {
    uint64_t r; asm("mov.b64 %0, {%1, %2};" : "=l"(r) : "f"(lo), "f"(hi)); return r;
}
__device__ __forceinline__ float2 unpack2(uint64_t v) {
    float lo, hi; asm("mov.b64 {%0, %1}, %2;" : "=f"(lo), "=f"(hi) : "l"(v));
    return make_float2(lo, hi);
}
// packed dual-lane fma: acc.lo += a.lo*b.lo ; acc.hi += a.hi*b.hi
#define FFMA2(acc, a, b) asm("fma.rn.f32x2 %0, %1, %2, %0;" : "+l"(acc) : "l"(a), "l"(b))

extern __shared__ float smem[];

__global__ __launch_bounds__(NTHR)
void gru_fused_kernel(const float* __restrict__ x,
                      const float* __restrict__ w_ih_f, const float* __restrict__ w_hh_f,
                      const float* __restrict__ b_ih_f, const float* __restrict__ b_hh_f,
                      const float* __restrict__ w_ih_b, const float* __restrict__ w_hh_b,
                      const float* __restrict__ b_ih_b, const float* __restrict__ b_hh_b,
                      const float* __restrict__ fc1_w, const float* __restrict__ fc1_b,
                      const float* __restrict__ fc2_w, const float* __restrict__ fc2_b,
                      float* __restrict__ out)
{
    // ---- shared memory layout (floats) ----
    float* whh_sh  = smem;              // 12288  (192 x 64, current direction)
    float* wih_sh  = whh_sh + 12288;    // 384    (192 x 2)
    float* brz_sh  = wih_sh + 384;      // 128    (b_ih+b_hh for r,z gates)
    float* bnih_sh = brz_sh + 128;      // 64
    float* bnhh_sh = bnih_sh + 64;      // 64
    float* fc1w_sh = bnhh_sh + 64;      // 3072   (24 x 128)
    float* fc1b_sh = fc1w_sh + 3072;    // 32 (24 used)
    float* fc2w_sh = fc1b_sh + 32;      // 40 (36 used)
    float* fc2b_sh = fc2w_sh + 40;      // 8  (2 used)
    float* scratch = fc2b_sh + 8;       // 64*128 = 8192 (h_new staging, [i][tid])

    const int tid = threadIdx.x;
    const int b   = blockIdx.x * NTHR + tid;

    for (int idx = tid; idx < 3072; idx += NTHR) fc1w_sh[idx] = fc1_w[idx];
    if (tid < 24) fc1b_sh[tid] = fc1_b[tid];
    if (tid < 36) fc2w_sh[tid] = fc2_w[tid];
    if (tid < 2)  fc2b_sh[tid] = fc2_b[tid];

    // per-thread fc2 accumulator (dynamically indexed -> local memory; tiny traffic)
    float acc2[48];
    #pragma unroll
    for (int i = 0; i < 48; i++) acc2[i] = 0.0f;

    uint64_t hp[32];                      // packed h pairs: hp[p] = (h[2p], h[2p+1])
    const float* xb = x + (size_t)b * (TT * 2);

    for (int dir = 0; dir < 2; ++dir) {
        const float* whh = dir ? w_hh_b : w_hh_f;
        const float* wih = dir ? w_ih_b : w_ih_f;
        const float* bih = dir ? b_ih_b : b_ih_f;
        const float* bhh = dir ? b_hh_b : b_hh_f;

        __syncthreads();
        for (int idx = tid; idx < 12288; idx += NTHR) whh_sh[idx] = whh[idx];
        for (int idx = tid; idx < 384;   idx += NTHR) wih_sh[idx] = wih[idx];
        if (tid < 128) brz_sh[tid] = bih[tid] + bhh[tid];
        if (tid < 64) { bnih_sh[tid] = bih[128 + tid]; bnhh_sh[tid] = bhh[128 + tid]; }
        __syncthreads();

        #pragma unroll
        for (int p = 0; p < 32; p++) hp[p] = 0ULL;
        #pragma unroll
        for (int j = 0; j < HH; j++) scratch[j * NTHR + tid] = 0.0f;

        for (int s = 0; s < TT; ++s) {
            const int t = dir ? (TT - 1 - s) : s;
            const float2 xv = *(const float2*)(xb + t * 2);
            const float x0 = xv.x, x1 = xv.y;

            // ---- GRU gate update, packed f32x2 dot products ----
            #pragma unroll 1
            for (int i = 0; i < HH; i++) {
                const float aR = brz_sh[i]      + x0 * wih_sh[2*i]         + x1 * wih_sh[2*i + 1];
                const float aZ = brz_sh[64 + i] + x0 * wih_sh[2*(64 + i)]  + x1 * wih_sh[2*(64 + i) + 1];
                const float aN = bnih_sh[i]     + x0 * wih_sh[2*(128 + i)] + x1 * wih_sh[2*(128 + i) + 1];

                uint64_t accR0 = pack2(aR, 0.0f),         accR1 = 0ULL;
                uint64_t accZ0 = pack2(aZ, 0.0f),         accZ1 = 0ULL;
                uint64_t accN0 = pack2(bnhh_sh[i], 0.0f), accN1 = 0ULL;

                const ulonglong2* wr = (const ulonglong2*)(whh_sh + i * 64);
                const ulonglong2* wz = (const ulonglong2*)(whh_sh + (64 + i) * 64);
                const ulonglong2* wn = (const ulonglong2*)(whh_sh + (128 + i) * 64);
                #pragma unroll
                for (int q = 0; q < 16; q += 2) {
                    ulonglong2 A0 = wr[q], A1 = wr[q+1];
                    ulonglong2 C0 = wz[q], C1 = wz[q+1];
                    ulonglong2 E0 = wn[q], E1 = wn[q+1];
                    FFMA2(accR0, hp[2*q+0], A0.x); FFMA2(accR0, hp[2*q+1], A0.y);
                    FFMA2(accR1, hp[2*q+2], A1.x); FFMA2(accR1, hp[2*q+3], A1.y);
                    FFMA2(accZ0, hp[2*q+0], C0.x); FFMA2(accZ0, hp[2*q+1], C0.y);
                    FFMA2(accZ1, hp[2*q+2], C1.x); FFMA2(accZ1, hp[2*q+3], C1.y);
                    FFMA2(accN0, hp[2*q+0], E0.x); FFMA2(accN0, hp[2*q+1], E0.y);
                    FFMA2(accN1, hp[2*q+2], E1.x); FFMA2(accN1, hp[2*q+3], E1.y);
                }
                const float2 pR = unpack2(accR0), qR = unpack2(accR1);
                const float2 pZ = unpack2(accZ0), qZ = unpack2(accZ1);
                const float2 pN = unpack2(accN0), qN = unpack2(accN1);
                const float r = sig_((pR.x + pR.y) + (qR.x + qR.y));
                const float z = sig_((pZ.x + pZ.y) + (qZ.x + qZ.y));
                const float n = tanh_(aN + r * ((pN.x + pN.y) + (qN.x + qN.y)));
                const float hold = scratch[i * NTHR + tid];
                scratch[i * NTHR + tid] = n + z * (hold - n);   // (1-z)*n + z*h
            }

            // ---- repack h_new -> registers (same thread wrote it; no sync needed) ----
            #pragma unroll
            for (int p = 0; p < 32; p++)
                hp[p] = pack2(scratch[(2*p) * NTHR + tid], scratch[(2*p+1) * NTHR + tid]);

            // ---- fused fc1 (this direction's half) + fc2 scatter ----
            const float* w1 = fc1w_sh + dir * 64;
            #pragma unroll 1
            for (int k = 0; k < 24; k++) {
                uint64_t s0 = pack2(dir ? 0.0f : fc1b_sh[k], 0.0f), s1 = 0ULL;
                const ulonglong2* wk = (const ulonglong2*)(w1 + k * 128);
                #pragma unroll
                for (int q = 0; q < 16; q += 2) {
                    ulonglong2 A0 = wk[q], A1 = wk[q+1];
                    FFMA2(s0, hp[2*q+0], A0.x); FFMA2(s0, hp[2*q+1], A0.y);
                    FFMA2(s1, hp[2*q+2], A1.x); FFMA2(s1, hp[2*q+3], A1.y);
                }
                const float2 u0 = unpack2(s0), u1 = unpack2(s1);
                const float sacc = (u0.x + u0.y) + (u1.x + u1.y);

                const int n_ = t * 24 + k;         // flat index in (T,24)
                const int r_ = n_ / 18;            // row of (24,18) reshape
                const int j_ = n_ - r_ * 18;       // col
                acc2[2*r_ + 0] += sacc * fc2w_sh[j_];
                acc2[2*r_ + 1] += sacc * fc2w_sh[18 + j_];
            }
        }
    }

    float* ob = out + (size_t)b * 48;
    #pragma unroll
    for (int m = 0; m < 48; m++) ob[m] = acc2[m] + fc2b_sh[m & 1];
}

extern "C" void kernel_launch(void* const* d_in, const int* in_sizes, int n_in,
                              void* d_out, int out_size)
{
    const float* x      = (const float*)d_in[0];
    const float* w_ih_f = (const float*)d_in[1];
    const float* w_hh_f = (const float*)d_in[2];
    const float* b_ih_f = (const float*)d_in[3];
    const float* b_hh_f = (const float*)d_in[4];
    const float* w_ih_b = (const float*)d_in[5];
    const float* w_hh_b = (const float*)d_in[6];
    const float* b_ih_b = (const float*)d_in[7];
    const float* b_hh_b = (const float*)d_in[8];
    const float* fc1_w  = (const float*)d_in[9];
    const float* fc1_b  = (const float*)d_in[10];
    const float* fc2_w  = (const float*)d_in[11];
    const float* fc2_b  = (const float*)d_in[12];
    float* out = (float*)d_out;

    const int smem_bytes = 24272 * (int)sizeof(float);
    cudaFuncSetAttribute(gru_fused_kernel,
                         cudaFuncAttributeMaxDynamicSharedMemorySize, smem_bytes);

    gru_fused_kernel<<<BTOT / NTHR, NTHR, smem_bytes>>>(
        x, w_ih_f, w_hh_f, b_ih_f, b_hh_f,
        w_ih_b, w_hh_b, b_ih_b, b_hh_b,
        fc1_w, fc1_b, fc2_w, fc2_b, out);
}

// round 3
// speedup vs baseline: 1.2455x; 1.2455x over previous
#include <cuda_runtime.h>

// Bidirectional GRU (B=32768, T=18, I=2, H=64) + fc1(128->24) + reshape + fc2(18->2)
// R3: 2 threads per batch element (lane pair). Thread s owns h[32s..32s+32) and
// gate rows i in [32s..32s+32) with full-width dot products; h halves exchanged
// once per step via SHFL.BFLY. Weights pre-permuted in smem (pair-interleaved,
// own-half-first) so all register indexing is static. (n,z) staged in local mem.
// smem ~51KB -> 4 CTAs/SM, grid 512 -> ~3.5 warps/SMSP.

#define NTHR   128
#define EPB    64          // elements per block (NTHR/2)
#define TT     18

// ---- smem layout (float offsets) ----
#define OFF_WHH   0        // 12288 floats (3072 float4, permuted)
#define OFF_WIH   12288    // 384 floats (192 float2, permuted)
#define OFF_BR    12672    // 64
#define OFF_BZ    12736    // 64
#define OFF_BNIH  12800    // 64
#define OFF_BNHH  12864    // 64
#define OFF_FC2W  12928    // 40 (36 used)
#define OFF_FC2B  12968    // 2
#define SMEM_FLOATS 12970

__device__ __forceinline__ float sig_(float x) {
    return 1.0f / (1.0f + __expf(-x));
}
__device__ __forceinline__ float tanh_(float x) {
    return 2.0f / (1.0f + __expf(-2.0f * x)) - 1.0f;
}

extern __shared__ float smem[];

__global__ __launch_bounds__(NTHR, 4)
void gru_pair_kernel(const float* __restrict__ x,
                     const float* __restrict__ w_ih_f, const float* __restrict__ w_hh_f,
                     const float* __restrict__ b_ih_f, const float* __restrict__ b_hh_f,
                     const float* __restrict__ w_ih_b, const float* __restrict__ w_hh_b,
                     const float* __restrict__ b_ih_b, const float* __restrict__ b_hh_b,
                     const float* __restrict__ fc1_w, const float* __restrict__ fc1_b,
                     const float* __restrict__ fc2_w, const float* __restrict__ fc2_b,
                     float* __restrict__ out)
{
    float4* whh4  = (float4*)(smem + OFF_WHH);
    float2* wihp  = (float2*)(smem + OFF_WIH);
    float*  bRs   = smem + OFF_BR;
    float*  bZs   = smem + OFF_BZ;
    float*  bNihs = smem + OFF_BNIH;
    float*  bNhhs = smem + OFF_BNHH;
    float*  fc2ws = smem + OFF_FC2W;
    float*  fc2bs = smem + OFF_FC2B;

    const int tid  = threadIdx.x;
    const int s    = tid & 1;          // which half of h / which gate rows
    const int pr   = tid >> 1;         // pair index within block
    const int elem = blockIdx.x * EPB + pr;

    if (tid < 36) fc2ws[tid] = fc2_w[tid];
    if (tid < 2)  fc2bs[tid] = fc2_b[tid];

    float acc2[48];                    // dynamic-indexed -> local mem (tiny traffic)
    #pragma unroll
    for (int i = 0; i < 48; i++) acc2[i] = 0.0f;

    float h_own[32], h_peer[32];
    const float* xb = x + (size_t)elem * (TT * 2);

    for (int dir = 0; dir < 2; ++dir) {
        const float* whh = dir ? w_hh_b : w_hh_f;
        const float* wih = dir ? w_ih_b : w_ih_f;
        const float* bih = dir ? b_ih_b : b_ih_f;
        const float* bhh = dir ? b_hh_b : b_hh_f;

        __syncthreads();   // previous direction's smem reads done
        // ---- W_hh: permute into [g][m] rows of 32 float4 slots:
        //      slot = 2*j4p + sl, where j4p is own-half-first order for thread sl ----
        const float4* whhg = (const float4*)whh;
        for (int d = tid; d < 3072; d += NTHR) {
            int gm  = d >> 5, rem = d & 31;
            int j4p = rem >> 1, sl = rem & 1;
            int g   = gm >> 5, m = gm & 31;
            int j4  = (j4p < 8) ? (8 * sl + j4p) : (8 * (1 - sl) + (j4p - 8));
            whh4[d] = whhg[(g * 64 + 32 * sl + m) * 16 + j4];
        }
        // ---- W_ih: float2 per row, dest (g*32+m)*2 + sl ----
        const float2* wihg = (const float2*)wih;
        for (int p = tid; p < 192; p += NTHR) {
            int gm = p >> 1, sl = p & 1;
            int g  = gm >> 5, m = gm & 31;
            wihp[p] = wihg[g * 64 + 32 * sl + m];
        }
        // ---- biases, dest 2*m + sl ----
        for (int idx = tid; idx < 64; idx += NTHR) {
            int m = idx >> 1, sl = idx & 1;
            int gi = 32 * sl + m;
            bRs[idx]   = bih[gi]       + bhh[gi];
            bZs[idx]   = bih[64 + gi]  + bhh[64 + gi];
            bNihs[idx] = bih[128 + gi];
            bNhhs[idx] = bhh[128 + gi];
        }
        __syncthreads();

        #pragma unroll
        for (int m = 0; m < 32; m++) { h_own[m] = 0.0f; h_peer[m] = 0.0f; }

        for (int st = 0; st < TT; ++st) {
            const int t = dir ? (TT - 1 - st) : st;
            const float2 xv = *(const float2*)(xb + t * 2);

            float2 nz[32];             // dynamic store -> local mem

            #pragma unroll 1
            for (int m = 0; m < 32; m++) {
                const int bi = 2 * m + s;
                const float2 wR = wihp[bi];
                const float2 wZ = wihp[64 + bi];
                const float2 wN = wihp[128 + bi];
                const float aR = bRs[bi]   + xv.x * wR.x + xv.y * wR.y;
                const float aZ = bZs[bi]   + xv.x * wZ.x + xv.y * wZ.y;
                const float aN = bNihs[bi] + xv.x * wN.x + xv.y * wN.y;

                const float4* pR = whh4 + m * 32 + s;
                const float4* pZ = whh4 + (32 + m) * 32 + s;
                const float4* pN = whh4 + (64 + m) * 32 + s;

                float hR0 = aR,  hZ0 = aZ,  hN0 = bNhhs[bi];
                float hR1 = 0.f, hZ1 = 0.f, hN1 = 0.f;
                #pragma unroll
                for (int q = 0; q < 8; q++) {        // own half
                    float4 a = pR[2*q], c = pZ[2*q], e = pN[2*q];
                    const float h0 = h_own[4*q+0], h1 = h_own[4*q+1];
                    const float h2 = h_own[4*q+2], h3 = h_own[4*q+3];
                    hR0 += h0*a.x + h1*a.y + h2*a.z + h3*a.w;
                    hZ0 += h0*c.x + h1*c.y + h2*c.z + h3*c.w;
                    hN0 += h0*e.x + h1*e.y + h2*e.z + h3*e.w;
                }
                #pragma unroll
                for (int q = 0; q < 8; q++) {        // peer half
                    float4 a = pR[2*(8+q)], c = pZ[2*(8+q)], e = pN[2*(8+q)];
                    const float h0 = h_peer[4*q+0], h1 = h_peer[4*q+1];
                    const float h2 = h_peer[4*q+2], h3 = h_peer[4*q+3];
                    hR1 += h0*a.x + h1*a.y + h2*a.z + h3*a.w;
                    hZ1 += h0*c.x + h1*c.y + h2*c.z + h3*c.w;
                    hN1 += h0*e.x + h1*e.y + h2*e.z + h3*e.w;
                }
                const float r = sig_(hR0 + hR1);
                const float z = sig_(hZ0 + hZ1);
                const float n = tanh_(aN + r * (hN0 + hN1));
                nz[m] = make_float2(n, z);
            }

            // ---- blend (static h index) + exchange halves ----
            #pragma unroll
            for (int m = 0; m < 32; m++) {
                const float2 f = nz[m];
                h_own[m] = f.x + f.y * (h_own[m] - f.x);   // (1-z)*n + z*h
            }
            #pragma unroll
            for (int m = 0; m < 32; m++)
                h_peer[m] = __shfl_xor_sync(0xffffffffu, h_own[m], 1);

            // ---- fused fc1 (12 k's per thread) + fc2 scatter ----
            #pragma unroll 1
            for (int kl = 0; kl < 12; kl++) {
                const int k = 12 * s + kl;
                const float* row = fc1_w + k * 128 + dir * 64;
                const float4* rowo = (const float4*)(row + 32 * s);
                const float4* rowp = (const float4*)(row + 32 * (1 - s));
                float s0 = dir ? 0.0f : __ldg(fc1_b + k);
                float s1 = 0.0f;
                #pragma unroll
                for (int q = 0; q < 8; q++) {
                    float4 a = __ldg(rowo + q);
                    float4 b = __ldg(rowp + q);
                    s0 += h_own[4*q+0]*a.x + h_own[4*q+1]*a.y
                        + h_own[4*q+2]*a.z + h_own[4*q+3]*a.w;
                    s1 += h_peer[4*q+0]*b.x + h_peer[4*q+1]*b.y
                        + h_peer[4*q+2]*b.z + h_peer[4*q+3]*b.w;
                }
                const float sacc = s0 + s1;
                const int n_ = t * 24 + k;
                const int r_ = n_ / 18;
                const int j_ = n_ - r_ * 18;
                acc2[2*r_ + 0] += sacc * fc2ws[j_];
                acc2[2*r_ + 1] += sacc * fc2ws[18 + j_];
            }
        }
    }

    // ---- merge pair partials and write ----
    const int lo = 24 * s;
    float* ob = out + (size_t)elem * 48;
    #pragma unroll
    for (int m = 0; m < 48; m++) {
        float v = acc2[m];
        v += __shfl_xor_sync(0xffffffffu, v, 1);
        if (m >= lo && m < lo + 24)
            ob[m] = v + fc2bs[m & 1];
    }
}

extern "C" void kernel_launch(void* const* d_in, const int* in_sizes, int n_in,
                              void* d_out, int out_size)
{
    const float* x      = (const float*)d_in[0];
    const float* w_ih_f = (const float*)d_in[1];
    const float* w_hh_f = (const float*)d_in[2];
    const float* b_ih_f = (const float*)d_in[3];
    const float* b_hh_f = (const float*)d_in[4];
    const float* w_ih_b = (const float*)d_in[5];
    const float* w_hh_b = (const float*)d_in[6];
    const float* b_ih_b = (const float*)d_in[7];
    const float* b_hh_b = (const float*)d_in[8];
    const float* fc1_w  = (const float*)d_in[9];
    const float* fc1_b  = (const float*)d_in[10];
    const float* fc2_w  = (const float*)d_in[11];
    const float* fc2_b  = (const float*)d_in[12];
    float* out = (float*)d_out;

    const int smem_bytes = SMEM_FLOATS * (int)sizeof(float);
    cudaFuncSetAttribute(gru_pair_kernel,
                         cudaFuncAttributeMaxDynamicSharedMemorySize, smem_bytes);

    gru_pair_kernel<<<32768 / EPB, NTHR, smem_bytes>>>(
        x, w_ih_f, w_hh_f, b_ih_f, b_hh_f,
        w_ih_b, w_hh_b, b_ih_b, b_hh_b,
        fc1_w, fc1_b, fc2_w, fc2_b, out);
}

// round 4
// speedup vs baseline: 3.4657x; 2.7826x over previous
#include <cuda_runtime.h>
#include <cstdint>

// Bidirectional GRU (B=32768, T=18, I=2, H=64) + fc1(128->24) + reshape + fc2(18->2)
// R4: tensor-core formulation. Per step, per warp:
//   D[16,280] = H'[16,80] @ W'^T   via mma.sync.m16n8k16.bf16, 3-product split
// H' = [h(64) | x0 x1 1 | pad13], W' cols = r(64) z(64) n_h(64) n_x(64) fc1(24).
// h_new D-fragments map 1:1 to next-step A-fragments (no shuffles, no smem h).
// fc1 partials -> global scratch; kernel2 does reshape+fc2.

#define NT 35            // n-tiles (280 cols / 8)
#define KT 5             // k-tiles (80 / 16)
#define WSTRIDE 40       // u32 per n-row in packed W (= KT*8)
#define WSIZE  (280 * WSTRIDE)   // 11200 u32 per array per dir

__device__ uint32_t Whi_g[2 * WSIZE];
__device__ uint32_t Wlo_g[2 * WSIZE];
__device__ float    fc1scr_g[2 * 32768 * 432];   // [dir][b][t(18)][24]

// ---------- helpers ----------
__device__ __forceinline__ uint32_t pack_bf16x2(float lo, float hi) {
    uint32_t r;
    asm("cvt.rn.bf16x2.f32 %0, %1, %2;" : "=r"(r) : "f"(hi), "f"(lo));
    return r;
}
__device__ __forceinline__ float lo_f32(uint32_t p) { return __uint_as_float(p << 16); }
__device__ __forceinline__ float hi_f32(uint32_t p) { return __uint_as_float(p & 0xFFFF0000u); }

__device__ __forceinline__ float sigf(float x) {
    float e, r;
    asm("ex2.approx.f32 %0, %1;" : "=f"(e) : "f"(x * -1.4426950408889634f));
    asm("rcp.approx.f32 %0, %1;" : "=f"(r) : "f"(1.0f + e));
    return r;
}
__device__ __forceinline__ float tanhf2(float x) { return 2.0f * sigf(2.0f * x) - 1.0f; }

__device__ __forceinline__ void mma_bf16(float& c0, float& c1, float& c2, float& c3,
                                         uint32_t a0, uint32_t a1, uint32_t a2, uint32_t a3,
                                         uint32_t b0, uint32_t b1) {
    asm volatile("mma.sync.aligned.m16n8k16.row.col.f32.bf16.bf16.f32 "
                 "{%0,%1,%2,%3}, {%4,%5,%6,%7}, {%8,%9}, {%0,%1,%2,%3};"
                 : "+f"(c0), "+f"(c1), "+f"(c2), "+f"(c3)
                 : "r"(a0), "r"(a1), "r"(a2), "r"(a3), "r"(b0), "r"(b1));
}

__device__ __forceinline__ void tile_mma(float c[4],
                                         const uint32_t* __restrict__ sWhi,
                                         const uint32_t* __restrict__ sWlo,
                                         int nt, int kt,
                                         const uint32_t ah[4], const uint32_t al[4],
                                         int lane) {
    const int off = (nt * 8 + (lane >> 2)) * WSTRIDE + kt * 8 + (lane & 3) * 2;
    const uint2 bh = *(const uint2*)(sWhi + off);
    mma_bf16(c[0], c[1], c[2], c[3], ah[0], ah[1], ah[2], ah[3], bh.x, bh.y);
    mma_bf16(c[0], c[1], c[2], c[3], al[0], al[1], al[2], al[3], bh.x, bh.y);
    const uint2 bl = *(const uint2*)(sWlo + off);
    mma_bf16(c[0], c[1], c[2], c[3], ah[0], ah[1], ah[2], ah[3], bl.x, bl.y);
}

// ---------- weight prep: W'[n][k], split to bf16 hi/lo, B-fragment packed ----------
__device__ float wprime(int dir, int n, int k,
                        const float* wih, const float* whh,
                        const float* bih, const float* bhh,
                        const float* fc1w, const float* fc1b) {
    if (k >= 67) return 0.0f;
    if (n < 128) {                     // r rows (0..63) and z rows (64..127): full
        if (k < 64)  return whh[n * 64 + k];
        if (k == 64) return wih[n * 2];
        if (k == 65) return wih[n * 2 + 1];
        return bih[n] + bhh[n];
    }
    if (n < 192) {                     // n_h: h-product + b_hh_n in const col
        if (k < 64)  return whh[n * 64 + k];
        if (k == 66) return bhh[n];
        return 0.0f;
    }
    if (n < 256) {                     // n_x: x-proj + b_ih_n
        const int g = n - 64;          // gate row 128 + (n-192)
        if (k == 64) return wih[g * 2];
        if (k == 65) return wih[g * 2 + 1];
        if (k == 66) return bih[g];
        return 0.0f;
    }
    {                                  // fc1 rows 256..279
        const int kk = n - 256;
        if (kk >= 24) return 0.0f;
        if (k < 64)  return fc1w[kk * 128 + 64 * dir + k];
        if (k == 66) return (dir == 0) ? fc1b[kk] : 0.0f;
        return 0.0f;
    }
}

__global__ void prep_kernel(const float* __restrict__ w_ih_f, const float* __restrict__ w_hh_f,
                            const float* __restrict__ b_ih_f, const float* __restrict__ b_hh_f,
                            const float* __restrict__ w_ih_b, const float* __restrict__ w_hh_b,
                            const float* __restrict__ b_ih_b, const float* __restrict__ b_hh_b,
                            const float* __restrict__ fc1_w, const float* __restrict__ fc1_b) {
    const int idx = blockIdx.x * blockDim.x + threadIdx.x;
    if (idx >= 2 * WSIZE) return;
    const int dir = idx / WSIZE;
    const int rem = idx % WSIZE;
    const int n  = rem / WSTRIDE;
    const int w  = rem % WSTRIDE;
    const int kt = w >> 3, q = (w >> 1) & 3, r_ = w & 1;
    const int p  = q + 8 * kt + (r_ ? 4 : 0);   // bf16-pair index within W' row
    const int k0 = 2 * p;

    const float* wih = dir ? w_ih_b : w_ih_f;
    const float* whh = dir ? w_hh_b : w_hh_f;
    const float* bih = dir ? b_ih_b : b_ih_f;
    const float* bhh = dir ? b_hh_b : b_hh_f;

    const float e0 = wprime(dir, n, k0,     wih, whh, bih, bhh, fc1_w, fc1_b);
    const float e1 = wprime(dir, n, k0 + 1, wih, whh, bih, bhh, fc1_w, fc1_b);
    const uint32_t hi = pack_bf16x2(e0, e1);
    const float l0 = e0 - lo_f32(hi);
    const float l1 = e1 - hi_f32(hi);
    Whi_g[idx] = hi;
    Wlo_g[idx] = pack_bf16x2(l0, l1);
}

// ---------- main kernel ----------
extern __shared__ uint32_t smem_u[];

__global__ __launch_bounds__(128)
void gru_mma_kernel(const float* __restrict__ x) {
    uint32_t* sWhi = smem_u;
    uint32_t* sWlo = smem_u + WSIZE;

    const int tid  = threadIdx.x;
    const int warp = tid >> 5;
    const int lane = tid & 31;
    const int qd   = lane & 3;
    const int row0 = blockIdx.x * 64 + warp * 16 + (lane >> 2);   // rows row0, row0+8

    #pragma unroll 1
    for (int dir = 0; dir < 2; ++dir) {
        __syncthreads();
        {   // copy packed weights to smem (straight uint4 copy)
            const uint4* gh = (const uint4*)(Whi_g + dir * WSIZE);
            const uint4* gl = (const uint4*)(Wlo_g + dir * WSIZE);
            uint4* shh = (uint4*)sWhi;
            uint4* shl = (uint4*)sWlo;
            for (int i = tid; i < WSIZE / 4; i += 128) { shh[i] = gh[i]; shl[i] = gl[i]; }
        }
        __syncthreads();

        float    hprev[8][4];
        uint32_t Ahi[5][4], Alo[5][4];
        #pragma unroll
        for (int g = 0; g < 8; g++)
            #pragma unroll
            for (int i = 0; i < 4; i++) hprev[g][i] = 0.0f;
        #pragma unroll
        for (int kt = 0; kt < 5; kt++)
            #pragma unroll
            for (int i = 0; i < 4; i++) { Ahi[kt][i] = 0u; Alo[kt][i] = 0u; }

        #pragma unroll 1
        for (int s = 0; s < 19; ++s) {
            int t = dir ? (17 - s) : s;
            int tx = t < 0 ? 0 : (t > 17 ? 17 : t);

            // ---- x/const k-tile (kt=4) A fragments ----
            const float2 xa = *(const float2*)(x + (size_t)row0 * 36 + tx * 2);
            const float2 xb = *(const float2*)(x + (size_t)(row0 + 8) * 36 + tx * 2);
            uint32_t a4h0 = 0, a4h1 = 0, a4l0 = 0, a4l1 = 0;
            if (qd == 0) {
                a4h0 = pack_bf16x2(xa.x, xa.y);
                a4l0 = pack_bf16x2(xa.x - lo_f32(a4h0), xa.y - hi_f32(a4h0));
                a4h1 = pack_bf16x2(xb.x, xb.y);
                a4l1 = pack_bf16x2(xb.x - lo_f32(a4h1), xb.y - hi_f32(a4h1));
            } else if (qd == 1) {
                a4h0 = a4h1 = pack_bf16x2(1.0f, 0.0f);
            }
            Ahi[4][0] = a4h0; Ahi[4][1] = a4h1; Ahi[4][2] = 0u; Ahi[4][3] = 0u;
            Alo[4][0] = a4l0; Alo[4][1] = a4l1; Alo[4][2] = 0u; Alo[4][3] = 0u;

            uint32_t Anh[4][4], Anl[4][4];

            // ---- gate groups: tiles {g, g+8, g+16, g+24} = r, z, n_h, n_x ----
            #pragma unroll
            for (int g = 0; g < 8; g++) {
                float cr[4] = {0, 0, 0, 0}, cz[4] = {0, 0, 0, 0};
                float ch[4] = {0, 0, 0, 0}, cx[4] = {0, 0, 0, 0};
                #pragma unroll
                for (int kt = 0; kt < 5; kt++) {
                    tile_mma(cr, sWhi, sWlo, g,      kt, Ahi[kt], Alo[kt], lane);
                    tile_mma(cz, sWhi, sWlo, g + 8,  kt, Ahi[kt], Alo[kt], lane);
                    tile_mma(ch, sWhi, sWlo, g + 16, kt, Ahi[kt], Alo[kt], lane);
                    tile_mma(cx, sWhi, sWlo, g + 24, kt, Ahi[kt], Alo[kt], lane);
                }
                #pragma unroll
                for (int i = 0; i < 4; i++) {
                    const float r = sigf(cr[i]);
                    const float z = sigf(cz[i]);
                    const float n = tanhf2(cx[i] + r * ch[i]);
                    if (s < 18) hprev[g][i] = n + z * (hprev[g][i] - n);
                }
                // pack h_new into next-step A fragments (kt=g/2, half=g&1)
                const uint32_t ph01 = pack_bf16x2(hprev[g][0], hprev[g][1]);
                const uint32_t pl01 = pack_bf16x2(hprev[g][0] - lo_f32(ph01),
                                                  hprev[g][1] - hi_f32(ph01));
                const uint32_t ph23 = pack_bf16x2(hprev[g][2], hprev[g][3]);
                const uint32_t pl23 = pack_bf16x2(hprev[g][2] - lo_f32(ph23),
                                                  hprev[g][3] - hi_f32(ph23));
                if ((g & 1) == 0) {
                    Anh[g >> 1][0] = ph01; Anh[g >> 1][1] = ph23;
                    Anl[g >> 1][0] = pl01; Anl[g >> 1][1] = pl23;
                } else {
                    Anh[g >> 1][2] = ph01; Anh[g >> 1][3] = ph23;
                    Anl[g >> 1][2] = pl01; Anl[g >> 1][3] = pl23;
                }
            }

            // ---- fc1 tiles (32..34) on H' = h_{s-1} ----
            float f0[4] = {0, 0, 0, 0}, f1[4] = {0, 0, 0, 0}, f2[4] = {0, 0, 0, 0};
            #pragma unroll
            for (int kt = 0; kt < 5; kt++) {
                tile_mma(f0, sWhi, sWlo, 32, kt, Ahi[kt], Alo[kt], lane);
                tile_mma(f1, sWhi, sWlo, 33, kt, Ahi[kt], Alo[kt], lane);
                tile_mma(f2, sWhi, sWlo, 34, kt, Ahi[kt], Alo[kt], lane);
            }
            if (s >= 1) {
                const int tf = dir ? (18 - s) : (s - 1);
                float* bp = fc1scr_g + ((size_t)dir * 32768 + row0) * 432 + tf * 24 + qd * 2;
                *(float2*)(bp)      = make_float2(f0[0], f0[1]);
                *(float2*)(bp + 8)  = make_float2(f1[0], f1[1]);
                *(float2*)(bp + 16) = make_float2(f2[0], f2[1]);
                float* bp2 = bp + (size_t)8 * 432;
                *(float2*)(bp2)      = make_float2(f0[2], f0[3]);
                *(float2*)(bp2 + 8)  = make_float2(f1[2], f1[3]);
                *(float2*)(bp2 + 16) = make_float2(f2[2], f2[3]);
            }

            // ---- rotate A fragments ----
            #pragma unroll
            for (int kt = 0; kt < 4; kt++)
                #pragma unroll
                for (int i = 0; i < 4; i++) { Ahi[kt][i] = Anh[kt][i]; Alo[kt][i] = Anl[kt][i]; }
        }
    }
}

// ---------- fc2 epilogue ----------
__global__ void fc2_kernel(const float* __restrict__ fc2_w, const float* __restrict__ fc2_b,
                           float* __restrict__ out) {
    const int b = blockIdx.x * blockDim.x + threadIdx.x;
    const float* p0 = fc1scr_g + (size_t)b * 432;
    const float* p1 = fc1scr_g + (size_t)32768 * 432 + (size_t)b * 432;

    float w2[36];
    #pragma unroll
    for (int j = 0; j < 36; j++) w2[j] = __ldg(fc2_w + j);

    float acc[48];
    #pragma unroll
    for (int m = 0; m < 48; m++) acc[m] = 0.0f;

    #pragma unroll
    for (int n_ = 0; n_ < 432; n_++) {
        const float v = p0[n_] + p1[n_];
        const int rr = n_ / 18;
        const int jj = n_ % 18;
        acc[2 * rr + 0] += v * w2[jj];
        acc[2 * rr + 1] += v * w2[18 + jj];
    }

    float* ob = out + (size_t)b * 48;
    const float b0 = __ldg(fc2_b), b1 = __ldg(fc2_b + 1);
    #pragma unroll
    for (int m = 0; m < 48; m++) ob[m] = acc[m] + ((m & 1) ? b1 : b0);
}

extern "C" void kernel_launch(void* const* d_in, const int* in_sizes, int n_in,
                              void* d_out, int out_size)
{
    const float* x      = (const float*)d_in[0];
    const float* w_ih_f = (const float*)d_in[1];
    const float* w_hh_f = (const float*)d_in[2];
    const float* b_ih_f = (const float*)d_in[3];
    const float* b_hh_f = (const float*)d_in[4];
    const float* w_ih_b = (const float*)d_in[5];
    const float* w_hh_b = (const float*)d_in[6];
    const float* b_ih_b = (const float*)d_in[7];
    const float* b_hh_b = (const float*)d_in[8];
    const float* fc1_w  = (const float*)d_in[9];
    const float* fc1_b  = (const float*)d_in[10];
    const float* fc2_w  = (const float*)d_in[11];
    const float* fc2_b  = (const float*)d_in[12];
    float* out = (float*)d_out;

    prep_kernel<<<(2 * WSIZE + 127) / 128, 128>>>(
        w_ih_f, w_hh_f, b_ih_f, b_hh_f,
        w_ih_b, w_hh_b, b_ih_b, b_hh_b, fc1_w, fc1_b);

    const int smem_bytes = 2 * WSIZE * (int)sizeof(uint32_t);   // 89600
    cudaFuncSetAttribute(gru_mma_kernel,
                         cudaFuncAttributeMaxDynamicSharedMemorySize, smem_bytes);
    gru_mma_kernel<<<512, 128, smem_bytes>>>(x);

    fc2_kernel<<<32768 / 256, 256>>>(fc2_w, fc2_b, out);
}

// round 5
// speedup vs baseline: 3.6794x; 1.0617x over previous
#include <cuda_runtime.h>
#include <cstdint>

// Bidirectional GRU (B=32768, T=18, I=2, H=64) + fc1(128->24) + reshape + fc2(18->2)
// R5: same mma.sync bf16 3-product formulation as R4, restructured for latency:
//  - 512-thread CTAs, grid 128 -> 1 CTA/SM, single wave, 4 warps/SMSP
//  - gate accumulation split into two chains (bh-products / bl-product), merged by FADD

#define KT 5             // k-tiles (80 / 16)
#define WSTRIDE 40       // u32 per n-row in packed W (= KT*8)
#define WSIZE  (280 * WSTRIDE)   // 11200 u32 per array per dir

__device__ uint32_t Whi_g[2 * WSIZE];
__device__ uint32_t Wlo_g[2 * WSIZE];
__device__ float    fc1scr_g[2 * 32768 * 432];   // [dir][b][t(18)][24]

// ---------- helpers ----------
__device__ __forceinline__ uint32_t pack_bf16x2(float lo, float hi) {
    uint32_t r;
    asm("cvt.rn.bf16x2.f32 %0, %1, %2;" : "=r"(r) : "f"(hi), "f"(lo));
    return r;
}
__device__ __forceinline__ float lo_f32(uint32_t p) { return __uint_as_float(p << 16); }
__device__ __forceinline__ float hi_f32(uint32_t p) { return __uint_as_float(p & 0xFFFF0000u); }

__device__ __forceinline__ float sigf(float x) {
    float e, r;
    asm("ex2.approx.f32 %0, %1;" : "=f"(e) : "f"(x * -1.4426950408889634f));
    asm("rcp.approx.f32 %0, %1;" : "=f"(r) : "f"(1.0f + e));
    return r;
}
__device__ __forceinline__ float tanhf2(float x) { return 2.0f * sigf(2.0f * x) - 1.0f; }

__device__ __forceinline__ void mma_bf16(float& c0, float& c1, float& c2, float& c3,
                                         uint32_t a0, uint32_t a1, uint32_t a2, uint32_t a3,
                                         uint32_t b0, uint32_t b1) {
    asm volatile("mma.sync.aligned.m16n8k16.row.col.f32.bf16.bf16.f32 "
                 "{%0,%1,%2,%3}, {%4,%5,%6,%7}, {%8,%9}, {%0,%1,%2,%3};"
                 : "+f"(c0), "+f"(c1), "+f"(c2), "+f"(c3)
                 : "r"(a0), "r"(a1), "r"(a2), "r"(a3), "r"(b0), "r"(b1));
}

// two-chain tile mma: ca accumulates the two bh products, cb the bl product
__device__ __forceinline__ void tile_mma2(float ca[4], float cb[4],
                                          const uint32_t* __restrict__ sWhi,
                                          const uint32_t* __restrict__ sWlo,
                                          int nt, int kt,
                                          const uint32_t ah[4], const uint32_t al[4],
                                          int lane) {
    const int off = (nt * 8 + (lane >> 2)) * WSTRIDE + kt * 8 + (lane & 3) * 2;
    const uint2 bh = *(const uint2*)(sWhi + off);
    mma_bf16(ca[0], ca[1], ca[2], ca[3], ah[0], ah[1], ah[2], ah[3], bh.x, bh.y);
    mma_bf16(ca[0], ca[1], ca[2], ca[3], al[0], al[1], al[2], al[3], bh.x, bh.y);
    const uint2 bl = *(const uint2*)(sWlo + off);
    mma_bf16(cb[0], cb[1], cb[2], cb[3], ah[0], ah[1], ah[2], ah[3], bl.x, bl.y);
}

// ---------- weight prep: W'[n][k], split to bf16 hi/lo, B-fragment packed ----------
__device__ float wprime(int dir, int n, int k,
                        const float* wih, const float* whh,
                        const float* bih, const float* bhh,
                        const float* fc1w, const float* fc1b) {
    if (k >= 67) return 0.0f;
    if (n < 128) {                     // r rows (0..63) and z rows (64..127): full
        if (k < 64)  return whh[n * 64 + k];
        if (k == 64) return wih[n * 2];
        if (k == 65) return wih[n * 2 + 1];
        return bih[n] + bhh[n];
    }
    if (n < 192) {                     // n_h: h-product + b_hh_n in const col
        if (k < 64)  return whh[n * 64 + k];
        if (k == 66) return bhh[n];
        return 0.0f;
    }
    if (n < 256) {                     // n_x: x-proj + b_ih_n
        const int g = n - 64;
        if (k == 64) return wih[g * 2];
        if (k == 65) return wih[g * 2 + 1];
        if (k == 66) return bih[g];
        return 0.0f;
    }
    {                                  // fc1 rows 256..279
        const int kk = n - 256;
        if (kk >= 24) return 0.0f;
        if (k < 64)  return fc1w[kk * 128 + 64 * dir + k];
        if (k == 66) return (dir == 0) ? fc1b[kk] : 0.0f;
        return 0.0f;
    }
}

__global__ void prep_kernel(const float* __restrict__ w_ih_f, const float* __restrict__ w_hh_f,
                            const float* __restrict__ b_ih_f, const float* __restrict__ b_hh_f,
                            const float* __restrict__ w_ih_b, const float* __restrict__ w_hh_b,
                            const float* __restrict__ b_ih_b, const float* __restrict__ b_hh_b,
                            const float* __restrict__ fc1_w, const float* __restrict__ fc1_b) {
    const int idx = blockIdx.x * blockDim.x + threadIdx.x;
    if (idx >= 2 * WSIZE) return;
    const int dir = idx / WSIZE;
    const int rem = idx % WSIZE;
    const int n  = rem / WSTRIDE;
    const int w  = rem % WSTRIDE;
    const int kt = w >> 3, q = (w >> 1) & 3, r_ = w & 1;
    const int p  = q + 8 * kt + (r_ ? 4 : 0);
    const int k0 = 2 * p;

    const float* wih = dir ? w_ih_b : w_ih_f;
    const float* whh = dir ? w_hh_b : w_hh_f;
    const float* bih = dir ? b_ih_b : b_ih_f;
    const float* bhh = dir ? b_hh_b : b_hh_f;

    const float e0 = wprime(dir, n, k0,     wih, whh, bih, bhh, fc1_w, fc1_b);
    const float e1 = wprime(dir, n, k0 + 1, wih, whh, bih, bhh, fc1_w, fc1_b);
    const uint32_t hi = pack_bf16x2(e0, e1);
    const float l0 = e0 - lo_f32(hi);
    const float l1 = e1 - hi_f32(hi);
    Whi_g[idx] = hi;
    Wlo_g[idx] = pack_bf16x2(l0, l1);
}

// ---------- main kernel: 512 threads, grid 128 (1 CTA/SM, single wave) ----------
extern __shared__ uint32_t smem_u[];

__global__ __launch_bounds__(512)
void gru_mma_kernel(const float* __restrict__ x) {
    uint32_t* sWhi = smem_u;
    uint32_t* sWlo = smem_u + WSIZE;

    const int tid  = threadIdx.x;
    const int warp = tid >> 5;
    const int lane = tid & 31;
    const int qd   = lane & 3;
    const int row0 = blockIdx.x * 256 + warp * 16 + (lane >> 2);   // rows row0, row0+8

    #pragma unroll 1
    for (int dir = 0; dir < 2; ++dir) {
        __syncthreads();
        {   // copy packed weights to smem (straight uint4 copy)
            const uint4* gh = (const uint4*)(Whi_g + dir * WSIZE);
            const uint4* gl = (const uint4*)(Wlo_g + dir * WSIZE);
            uint4* shh = (uint4*)sWhi;
            uint4* shl = (uint4*)sWlo;
            for (int i = tid; i < WSIZE / 4; i += 512) { shh[i] = gh[i]; shl[i] = gl[i]; }
        }
        __syncthreads();

        float    hprev[8][4];
        uint32_t Ahi[5][4], Alo[5][4];
        #pragma unroll
        for (int g = 0; g < 8; g++)
            #pragma unroll
            for (int i = 0; i < 4; i++) hprev[g][i] = 0.0f;
        #pragma unroll
        for (int kt = 0; kt < 5; kt++)
            #pragma unroll
            for (int i = 0; i < 4; i++) { Ahi[kt][i] = 0u; Alo[kt][i] = 0u; }

        #pragma unroll 1
        for (int s = 0; s < 19; ++s) {
            int t = dir ? (17 - s) : s;
            int tx = t < 0 ? 0 : (t > 17 ? 17 : t);

            // ---- x/const k-tile (kt=4) A fragments ----
            const float2 xa = *(const float2*)(x + (size_t)row0 * 36 + tx * 2);
            const float2 xb = *(const float2*)(x + (size_t)(row0 + 8) * 36 + tx * 2);
            uint32_t a4h0 = 0, a4h1 = 0, a4l0 = 0, a4l1 = 0;
            if (qd == 0) {
                a4h0 = pack_bf16x2(xa.x, xa.y);
                a4l0 = pack_bf16x2(xa.x - lo_f32(a4h0), xa.y - hi_f32(a4h0));
                a4h1 = pack_bf16x2(xb.x, xb.y);
                a4l1 = pack_bf16x2(xb.x - lo_f32(a4h1), xb.y - hi_f32(a4h1));
            } else if (qd == 1) {
                a4h0 = a4h1 = pack_bf16x2(1.0f, 0.0f);
            }
            Ahi[4][0] = a4h0; Ahi[4][1] = a4h1; Ahi[4][2] = 0u; Ahi[4][3] = 0u;
            Alo[4][0] = a4l0; Alo[4][1] = a4l1; Alo[4][2] = 0u; Alo[4][3] = 0u;

            uint32_t Anh[4][4], Anl[4][4];

            // ---- gate groups: tiles {g, g+8, g+16, g+24} = r, z, n_h, n_x ----
            #pragma unroll
            for (int g = 0; g < 8; g++) {
                float cra[4] = {0,0,0,0}, crb[4] = {0,0,0,0};
                float cza[4] = {0,0,0,0}, czb[4] = {0,0,0,0};
                float cha[4] = {0,0,0,0}, chb[4] = {0,0,0,0};
                float cxa[4] = {0,0,0,0}, cxb[4] = {0,0,0,0};
                #pragma unroll
                for (int kt = 0; kt < 5; kt++) {
                    tile_mma2(cra, crb, sWhi, sWlo, g,      kt, Ahi[kt], Alo[kt], lane);
                    tile_mma2(cza, czb, sWhi, sWlo, g + 8,  kt, Ahi[kt], Alo[kt], lane);
                    tile_mma2(cha, chb, sWhi, sWlo, g + 16, kt, Ahi[kt], Alo[kt], lane);
                    tile_mma2(cxa, cxb, sWhi, sWlo, g + 24, kt, Ahi[kt], Alo[kt], lane);
                }
                #pragma unroll
                for (int i = 0; i < 4; i++) {
                    const float r = sigf(cra[i] + crb[i]);
                    const float z = sigf(cza[i] + czb[i]);
                    const float n = tanhf2((cxa[i] + cxb[i]) + r * (cha[i] + chb[i]));
                    if (s < 18) hprev[g][i] = n + z * (hprev[g][i] - n);
                }
                // pack h_new into next-step A fragments (kt=g/2, half=g&1)
                const uint32_t ph01 = pack_bf16x2(hprev[g][0], hprev[g][1]);
                const uint32_t pl01 = pack_bf16x2(hprev[g][0] - lo_f32(ph01),
                                                  hprev[g][1] - hi_f32(ph01));
                const uint32_t ph23 = pack_bf16x2(hprev[g][2], hprev[g][3]);
                const uint32_t pl23 = pack_bf16x2(hprev[g][2] - lo_f32(ph23),
                                                  hprev[g][3] - hi_f32(ph23));
                if ((g & 1) == 0) {
                    Anh[g >> 1][0] = ph01; Anh[g >> 1][1] = ph23;
                    Anl[g >> 1][0] = pl01; Anl[g >> 1][1] = pl23;
                } else {
                    Anh[g >> 1][2] = ph01; Anh[g >> 1][3] = ph23;
                    Anl[g >> 1][2] = pl01; Anl[g >> 1][3] = pl23;
                }
            }

            // ---- fc1 tiles (32..34) on H' = h_{s-1} ----
            float f0a[4] = {0,0,0,0}, f0b[4] = {0,0,0,0};
            float f1a[4] = {0,0,0,0}, f1b[4] = {0,0,0,0};
            float f2a[4] = {0,0,0,0}, f2b[4] = {0,0,0,0};
            #pragma unroll
            for (int kt = 0; kt < 5; kt++) {
                tile_mma2(f0a, f0b, sWhi, sWlo, 32, kt, Ahi[kt], Alo[kt], lane);
                tile_mma2(f1a, f1b, sWhi, sWlo, 33, kt, Ahi[kt], Alo[kt], lane);
                tile_mma2(f2a, f2b, sWhi, sWlo, 34, kt, Ahi[kt], Alo[kt], lane);
            }
            if (s >= 1) {
                const int tf = dir ? (18 - s) : (s - 1);
                float* bp = fc1scr_g + ((size_t)dir * 32768 + row0) * 432 + tf * 24 + qd * 2;
                *(float2*)(bp)      = make_float2(f0a[0] + f0b[0], f0a[1] + f0b[1]);
                *(float2*)(bp + 8)  = make_float2(f1a[0] + f1b[0], f1a[1] + f1b[1]);
                *(float2*)(bp + 16) = make_float2(f2a[0] + f2b[0], f2a[1] + f2b[1]);
                float* bp2 = bp + (size_t)8 * 432;
                *(float2*)(bp2)      = make_float2(f0a[2] + f0b[2], f0a[3] + f0b[3]);
                *(float2*)(bp2 + 8)  = make_float2(f1a[2] + f1b[2], f1a[3] + f1b[3]);
                *(float2*)(bp2 + 16) = make_float2(f2a[2] + f2b[2], f2a[3] + f2b[3]);
            }

            // ---- rotate A fragments ----
            #pragma unroll
            for (int kt = 0; kt < 4; kt++)
                #pragma unroll
                for (int i = 0; i < 4; i++) { Ahi[kt][i] = Anh[kt][i]; Alo[kt][i] = Anl[kt][i]; }
        }
    }
}

// ---------- fc2 epilogue ----------
__global__ void fc2_kernel(const float* __restrict__ fc2_w, const float* __restrict__ fc2_b,
                           float* __restrict__ out) {
    const int b = blockIdx.x * blockDim.x + threadIdx.x;
    const float* p0 = fc1scr_g + (size_t)b * 432;
    const float* p1 = fc1scr_g + (size_t)32768 * 432 + (size_t)b * 432;

    float w2[36];
    #pragma unroll
    for (int j = 0; j < 36; j++) w2[j] = __ldg(fc2_w + j);

    float acc[48];
    #pragma unroll
    for (int m = 0; m < 48; m++) acc[m] = 0.0f;

    #pragma unroll
    for (int n_ = 0; n_ < 432; n_++) {
        const float v = p0[n_] + p1[n_];
        const int rr = n_ / 18;
        const int jj = n_ % 18;
        acc[2 * rr + 0] += v * w2[jj];
        acc[2 * rr + 1] += v * w2[18 + jj];
    }

    float* ob = out + (size_t)b * 48;
    const float b0 = __ldg(fc2_b), b1 = __ldg(fc2_b + 1);
    #pragma unroll
    for (int m = 0; m < 48; m++) ob[m] = acc[m] + ((m & 1) ? b1 : b0);
}

extern "C" void kernel_launch(void* const* d_in, const int* in_sizes, int n_in,
                              void* d_out, int out_size)
{
    const float* x      = (const float*)d_in[0];
    const float* w_ih_f = (const float*)d_in[1];
    const float* w_hh_f = (const float*)d_in[2];
    const float* b_ih_f = (const float*)d_in[3];
    const float* b_hh_f = (const float*)d_in[4];
    const float* w_ih_b = (const float*)d_in[5];
    const float* w_hh_b = (const float*)d_in[6];
    const float* b_ih_b = (const float*)d_in[7];
    const float* b_hh_b = (const float*)d_in[8];
    const float* fc1_w  = (const float*)d_in[9];
    const float* fc1_b  = (const float*)d_in[10];
    const float* fc2_w  = (const float*)d_in[11];
    const float* fc2_b  = (const float*)d_in[12];
    float* out = (float*)d_out;

    prep_kernel<<<(2 * WSIZE + 127) / 128, 128>>>(
        w_ih_f, w_hh_f, b_ih_f, b_hh_f,
        w_ih_b, w_hh_b, b_ih_b, b_hh_b, fc1_w, fc1_b);

    const int smem_bytes = 2 * WSIZE * (int)sizeof(uint32_t);   // 89600
    cudaFuncSetAttribute(gru_mma_kernel,
                         cudaFuncAttributeMaxDynamicSharedMemorySize, smem_bytes);
    gru_mma_kernel<<<128, 512, smem_bytes>>>(x);

    fc2_kernel<<<32768 / 256, 256>>>(fc2_w, fc2_b, out);
}

// round 6
// speedup vs baseline: 4.0199x; 1.0925x over previous
#include <cuda_runtime.h>
#include <cstdint>

// Bidirectional GRU (B=32768, T=18, I=2, H=64) + fc1(128->24) + reshape + fc2(18->2)
// R6: mma.sync bf16 3-product formulation with structural-zero cuts:
//  - n_x tiles use only kt=4 (h-range of those rows is all zero)
//  - s=0: gates kt=4 only (h=0), no fc1 ; s=18: fc1 only (gates unused)
//  - weight prep folded into the main kernel (per-CTA pack into smem)

#define KT 5             // k-tiles (80 / 16)
#define WSTRIDE 40       // u32 per n-row in packed W (= KT*8)
#define WSIZE  (280 * WSTRIDE)   // 11200 u32 per array per dir

__device__ float fc1scr_g[2 * 32768 * 432];   // [dir][b][t(18)][24]

// ---------- helpers ----------
__device__ __forceinline__ uint32_t pack_bf16x2(float lo, float hi) {
    uint32_t r;
    asm("cvt.rn.bf16x2.f32 %0, %1, %2;" : "=r"(r) : "f"(hi), "f"(lo));
    return r;
}
__device__ __forceinline__ float lo_f32(uint32_t p) { return __uint_as_float(p << 16); }
__device__ __forceinline__ float hi_f32(uint32_t p) { return __uint_as_float(p & 0xFFFF0000u); }

__device__ __forceinline__ float sigf(float x) {
    float e, r;
    asm("ex2.approx.f32 %0, %1;" : "=f"(e) : "f"(x * -1.4426950408889634f));
    asm("rcp.approx.f32 %0, %1;" : "=f"(r) : "f"(1.0f + e));
    return r;
}
__device__ __forceinline__ float tanhf2(float x) { return 2.0f * sigf(2.0f * x) - 1.0f; }

__device__ __forceinline__ void mma_bf16(float& c0, float& c1, float& c2, float& c3,
                                         uint32_t a0, uint32_t a1, uint32_t a2, uint32_t a3,
                                         uint32_t b0, uint32_t b1) {
    asm volatile("mma.sync.aligned.m16n8k16.row.col.f32.bf16.bf16.f32 "
                 "{%0,%1,%2,%3}, {%4,%5,%6,%7}, {%8,%9}, {%0,%1,%2,%3};"
                 : "+f"(c0), "+f"(c1), "+f"(c2), "+f"(c3)
                 : "r"(a0), "r"(a1), "r"(a2), "r"(a3), "r"(b0), "r"(b1));
}

// two-chain tile mma: ca accumulates the two bh products, cb the bl product
__device__ __forceinline__ void tile_mma2(float ca[4], float cb[4],
                                          const uint32_t* __restrict__ sWhi,
                                          const uint32_t* __restrict__ sWlo,
                                          int nt, int kt,
                                          const uint32_t ah[4], const uint32_t al[4],
                                          int lane) {
    const int off = (nt * 8 + (lane >> 2)) * WSTRIDE + kt * 8 + (lane & 3) * 2;
    const uint2 bh = *(const uint2*)(sWhi + off);
    mma_bf16(ca[0], ca[1], ca[2], ca[3], ah[0], ah[1], ah[2], ah[3], bh.x, bh.y);
    mma_bf16(ca[0], ca[1], ca[2], ca[3], al[0], al[1], al[2], al[3], bh.x, bh.y);
    const uint2 bl = *(const uint2*)(sWlo + off);
    mma_bf16(cb[0], cb[1], cb[2], cb[3], ah[0], ah[1], ah[2], ah[3], bl.x, bl.y);
}

// ---------- W'[n][k] generator (fp32) ----------
__device__ float wprime(int dir, int n, int k,
                        const float* wih, const float* whh,
                        const float* bih, const float* bhh,
                        const float* fc1w, const float* fc1b) {
    if (k >= 67) return 0.0f;
    if (n < 128) {                     // r rows (0..63) and z rows (64..127): full
        if (k < 64)  return whh[n * 64 + k];
        if (k == 64) return wih[n * 2];
        if (k == 65) return wih[n * 2 + 1];
        return bih[n] + bhh[n];
    }
    if (n < 192) {                     // n_h: h-product + b_hh_n in const col
        if (k < 64)  return whh[n * 64 + k];
        if (k == 66) return bhh[n];
        return 0.0f;
    }
    if (n < 256) {                     // n_x: x-proj + b_ih_n (h-range all zero)
        const int g = n - 64;
        if (k == 64) return wih[g * 2];
        if (k == 65) return wih[g * 2 + 1];
        if (k == 66) return bih[g];
        return 0.0f;
    }
    {                                  // fc1 rows 256..279
        const int kk = n - 256;
        if (kk >= 24) return 0.0f;
        if (k < 64)  return fc1w[kk * 128 + 64 * dir + k];
        if (k == 66) return (dir == 0) ? fc1b[kk] : 0.0f;
        return 0.0f;
    }
}

// ---------- main kernel: 512 threads, grid 128 (1 CTA/SM, single wave) ----------
extern __shared__ uint32_t smem_u[];

__global__ __launch_bounds__(512)
void gru_mma_kernel(const float* __restrict__ x,
                    const float* __restrict__ w_ih_f, const float* __restrict__ w_hh_f,
                    const float* __restrict__ b_ih_f, const float* __restrict__ b_hh_f,
                    const float* __restrict__ w_ih_b, const float* __restrict__ w_hh_b,
                    const float* __restrict__ b_ih_b, const float* __restrict__ b_hh_b,
                    const float* __restrict__ fc1_w, const float* __restrict__ fc1_b) {
    uint32_t* sWhi = smem_u;
    uint32_t* sWlo = smem_u + WSIZE;

    const int tid  = threadIdx.x;
    const int warp = tid >> 5;
    const int lane = tid & 31;
    const int qd   = lane & 3;
    const int row0 = blockIdx.x * 256 + warp * 16 + (lane >> 2);   // rows row0, row0+8

    #pragma unroll 1
    for (int dir = 0; dir < 2; ++dir) {
        const float* wih = dir ? w_ih_b : w_ih_f;
        const float* whh = dir ? w_hh_b : w_hh_f;
        const float* bih = dir ? b_ih_b : b_ih_f;
        const float* bhh = dir ? b_hh_b : b_hh_f;

        __syncthreads();
        // ---- pack this direction's weights into smem (hi/lo bf16 split) ----
        #pragma unroll 1
        for (int i = tid; i < WSIZE; i += 512) {
            const int n  = i / WSTRIDE;
            const int w  = i % WSTRIDE;
            const int kt = w >> 3, q = (w >> 1) & 3, r_ = w & 1;
            const int k0 = 2 * (q + 8 * kt + (r_ ? 4 : 0));
            const float e0 = wprime(dir, n, k0,     wih, whh, bih, bhh, fc1_w, fc1_b);
            const float e1 = wprime(dir, n, k0 + 1, wih, whh, bih, bhh, fc1_w, fc1_b);
            const uint32_t hi = pack_bf16x2(e0, e1);
            sWhi[i] = hi;
            sWlo[i] = pack_bf16x2(e0 - lo_f32(hi), e1 - hi_f32(hi));
        }
        __syncthreads();

        float    hprev[8][4];
        uint32_t Ahi[5][4], Alo[5][4];
        #pragma unroll
        for (int g = 0; g < 8; g++)
            #pragma unroll
            for (int i = 0; i < 4; i++) hprev[g][i] = 0.0f;
        #pragma unroll
        for (int kt = 0; kt < 5; kt++)
            #pragma unroll
            for (int i = 0; i < 4; i++) { Ahi[kt][i] = 0u; Alo[kt][i] = 0u; }

        #pragma unroll 1
        for (int s = 0; s < 19; ++s) {
            int t = dir ? (17 - s) : s;
            int tx = t < 0 ? 0 : (t > 17 ? 17 : t);

            // ---- x/const k-tile (kt=4) A fragments ----
            const float2 xa = *(const float2*)(x + (size_t)row0 * 36 + tx * 2);
            const float2 xb = *(const float2*)(x + (size_t)(row0 + 8) * 36 + tx * 2);
            uint32_t a4h0 = 0, a4h1 = 0, a4l0 = 0, a4l1 = 0;
            if (qd == 0) {
                a4h0 = pack_bf16x2(xa.x, xa.y);
                a4l0 = pack_bf16x2(xa.x - lo_f32(a4h0), xa.y - hi_f32(a4h0));
                a4h1 = pack_bf16x2(xb.x, xb.y);
                a4l1 = pack_bf16x2(xb.x - lo_f32(a4h1), xb.y - hi_f32(a4h1));
            } else if (qd == 1) {
                a4h0 = a4h1 = pack_bf16x2(1.0f, 0.0f);
            }
            Ahi[4][0] = a4h0; Ahi[4][1] = a4h1; Ahi[4][2] = 0u; Ahi[4][3] = 0u;
            Alo[4][0] = a4l0; Alo[4][1] = a4l1; Alo[4][2] = 0u; Alo[4][3] = 0u;

            if (s < 18) {
                const int kt0 = (s == 0) ? 4 : 0;    // h=0 at s=0: only kt=4 matters
                uint32_t Anh[4][4], Anl[4][4];

                // ---- gate groups: tiles {g, g+8, g+16} full-k; n_x (g+24) kt=4 only ----
                #pragma unroll
                for (int g = 0; g < 8; g++) {
                    float cra[4] = {0,0,0,0}, crb[4] = {0,0,0,0};
                    float cza[4] = {0,0,0,0}, czb[4] = {0,0,0,0};
                    float cha[4] = {0,0,0,0}, chb[4] = {0,0,0,0};
                    float cxa[4] = {0,0,0,0}, cxb[4] = {0,0,0,0};
                    #pragma unroll
                    for (int kt = 4; kt >= 0; kt--) {
                        if (kt < kt0) break;
                        tile_mma2(cra, crb, sWhi, sWlo, g,      kt, Ahi[kt], Alo[kt], lane);
                        tile_mma2(cza, czb, sWhi, sWlo, g + 8,  kt, Ahi[kt], Alo[kt], lane);
                        tile_mma2(cha, chb, sWhi, sWlo, g + 16, kt, Ahi[kt], Alo[kt], lane);
                    }
                    tile_mma2(cxa, cxb, sWhi, sWlo, g + 24, 4, Ahi[4], Alo[4], lane);

                    #pragma unroll
                    for (int i = 0; i < 4; i++) {
                        const float r = sigf(cra[i] + crb[i]);
                        const float z = sigf(cza[i] + czb[i]);
                        const float n = tanhf2((cxa[i] + cxb[i]) + r * (cha[i] + chb[i]));
                        hprev[g][i] = n + z * (hprev[g][i] - n);
                    }
                    // pack h_new into next-step A fragments (kt=g/2, half=g&1)
                    const uint32_t ph01 = pack_bf16x2(hprev[g][0], hprev[g][1]);
                    const uint32_t pl01 = pack_bf16x2(hprev[g][0] - lo_f32(ph01),
                                                      hprev[g][1] - hi_f32(ph01));
                    const uint32_t ph23 = pack_bf16x2(hprev[g][2], hprev[g][3]);
                    const uint32_t pl23 = pack_bf16x2(hprev[g][2] - lo_f32(ph23),
                                                      hprev[g][3] - hi_f32(ph23));
                    if ((g & 1) == 0) {
                        Anh[g >> 1][0] = ph01; Anh[g >> 1][1] = ph23;
                        Anl[g >> 1][0] = pl01; Anl[g >> 1][1] = pl23;
                    } else {
                        Anh[g >> 1][2] = ph01; Anh[g >> 1][3] = ph23;
                        Anl[g >> 1][2] = pl01; Anl[g >> 1][3] = pl23;
                    }
                }

                // ---- fc1 tiles (32..34) on H' = h_{s-1} (skip at s=0: unused) ----
                if (s >= 1) {
                    float f0a[4] = {0,0,0,0}, f0b[4] = {0,0,0,0};
                    float f1a[4] = {0,0,0,0}, f1b[4] = {0,0,0,0};
                    float f2a[4] = {0,0,0,0}, f2b[4] = {0,0,0,0};
                    #pragma unroll
                    for (int kt = 0; kt < 5; kt++) {
                        tile_mma2(f0a, f0b, sWhi, sWlo, 32, kt, Ahi[kt], Alo[kt], lane);
                        tile_mma2(f1a, f1b, sWhi, sWlo, 33, kt, Ahi[kt], Alo[kt], lane);
                        tile_mma2(f2a, f2b, sWhi, sWlo, 34, kt, Ahi[kt], Alo[kt], lane);
                    }
                    const int tf = dir ? (18 - s) : (s - 1);
                    float* bp = fc1scr_g + ((size_t)dir * 32768 + row0) * 432 + tf * 24 + qd * 2;
                    *(float2*)(bp)      = make_float2(f0a[0] + f0b[0], f0a[1] + f0b[1]);
                    *(float2*)(bp + 8)  = make_float2(f1a[0] + f1b[0], f1a[1] + f1b[1]);
                    *(float2*)(bp + 16) = make_float2(f2a[0] + f2b[0], f2a[1] + f2b[1]);
                    float* bp2 = bp + (size_t)8 * 432;
                    *(float2*)(bp2)      = make_float2(f0a[2] + f0b[2], f0a[3] + f0b[3]);
                    *(float2*)(bp2 + 8)  = make_float2(f1a[2] + f1b[2], f1a[3] + f1b[3]);
                    *(float2*)(bp2 + 16) = make_float2(f2a[2] + f2b[2], f2a[3] + f2b[3]);
                }

                // ---- rotate A fragments ----
                #pragma unroll
                for (int kt = 0; kt < 4; kt++)
                    #pragma unroll
                    for (int i = 0; i < 4; i++) { Ahi[kt][i] = Anh[kt][i]; Alo[kt][i] = Anl[kt][i]; }
            } else {
                // ---- s=18: fc1 on h_17 only ----
                float f0a[4] = {0,0,0,0}, f0b[4] = {0,0,0,0};
                float f1a[4] = {0,0,0,0}, f1b[4] = {0,0,0,0};
                float f2a[4] = {0,0,0,0}, f2b[4] = {0,0,0,0};
                #pragma unroll
                for (int kt = 0; kt < 5; kt++) {
                    tile_mma2(f0a, f0b, sWhi, sWlo, 32, kt, Ahi[kt], Alo[kt], lane);
                    tile_mma2(f1a, f1b, sWhi, sWlo, 33, kt, Ahi[kt], Alo[kt], lane);
                    tile_mma2(f2a, f2b, sWhi, sWlo, 34, kt, Ahi[kt], Alo[kt], lane);
                }
                const int tf = dir ? 0 : 17;
                float* bp = fc1scr_g + ((size_t)dir * 32768 + row0) * 432 + tf * 24 + qd * 2;
                *(float2*)(bp)      = make_float2(f0a[0] + f0b[0], f0a[1] + f0b[1]);
                *(float2*)(bp + 8)  = make_float2(f1a[0] + f1b[0], f1a[1] + f1b[1]);
                *(float2*)(bp + 16) = make_float2(f2a[0] + f2b[0], f2a[1] + f2b[1]);
                float* bp2 = bp + (size_t)8 * 432;
                *(float2*)(bp2)      = make_float2(f0a[2] + f0b[2], f0a[3] + f0b[3]);
                *(float2*)(bp2 + 8)  = make_float2(f1a[2] + f1b[2], f1a[3] + f1b[3]);
                *(float2*)(bp2 + 16) = make_float2(f2a[2] + f2b[2], f2a[3] + f2b[3]);
            }
        }
    }
}

// ---------- fc2 epilogue ----------
__global__ void fc2_kernel(const float* __restrict__ fc2_w, const float* __restrict__ fc2_b,
                           float* __restrict__ out) {
    const int b = blockIdx.x * blockDim.x + threadIdx.x;
    const float* p0 = fc1scr_g + (size_t)b * 432;
    const float* p1 = fc1scr_g + (size_t)32768 * 432 + (size_t)b * 432;

    float w2[36];
    #pragma unroll
    for (int j = 0; j < 36; j++) w2[j] = __ldg(fc2_w + j);

    float acc[48];
    #pragma unroll
    for (int m = 0; m < 48; m++) acc[m] = 0.0f;

    #pragma unroll
    for (int n_ = 0; n_ < 432; n_++) {
        const float v = p0[n_] + p1[n_];
        const int rr = n_ / 18;
        const int jj = n_ % 18;
        acc[2 * rr + 0] += v * w2[jj];
        acc[2 * rr + 1] += v * w2[18 + jj];
    }

    float* ob = out + (size_t)b * 48;
    const float b0 = __ldg(fc2_b), b1 = __ldg(fc2_b + 1);
    #pragma unroll
    for (int m = 0; m < 48; m++) ob[m] = acc[m] + ((m & 1) ? b1 : b0);
}

extern "C" void kernel_launch(void* const* d_in, const int* in_sizes, int n_in,
                              void* d_out, int out_size)
{
    const float* x      = (const float*)d_in[0];
    const float* w_ih_f = (const float*)d_in[1];
    const float* w_hh_f = (const float*)d_in[2];
    const float* b_ih_f = (const float*)d_in[3];
    const float* b_hh_f = (const float*)d_in[4];
    const float* w_ih_b = (const float*)d_in[5];
    const float* w_hh_b = (const float*)d_in[6];
    const float* b_ih_b = (const float*)d_in[7];
    const float* b_hh_b = (const float*)d_in[8];
    const float* fc1_w  = (const float*)d_in[9];
    const float* fc1_b  = (const float*)d_in[10];
    const float* fc2_w  = (const float*)d_in[11];
    const float* fc2_b  = (const float*)d_in[12];
    float* out = (float*)d_out;

    const int smem_bytes = 2 * WSIZE * (int)sizeof(uint32_t);   // 89600
    cudaFuncSetAttribute(gru_mma_kernel,
                         cudaFuncAttributeMaxDynamicSharedMemorySize, smem_bytes);
    gru_mma_kernel<<<128, 512, smem_bytes>>>(
        x, w_ih_f, w_hh_f, b_ih_f, b_hh_f,
        w_ih_b, w_hh_b, b_ih_b, b_hh_b, fc1_w, fc1_b);

    fc2_kernel<<<32768 / 256, 256>>>(fc2_w, fc2_b, out);
}

// round 7
// speedup vs baseline: 4.5948x; 1.1430x over previous
#include <cuda_runtime.h>
#include <cstdint>

// Bidirectional GRU (B=32768, T=18, I=2, H=64) + fc1(128->24) + reshape + fc2(18->2)
// R7: mma.sync bf16 3-product, h-only tensor work:
//  - all x/bias (rank-3) contributions computed scalar from smem const tables
//  - W' table = 216 rows (r,z,n_h,fc1) x k0..63 only; stride 36 u32 (bank-safe)
//  - fc1 scratch transposed [dir][col][b] -> coalesced fc2 ; fc1 bias folded into fc2

#define WSTRIDE 36              // u32 per n-row (32 used + 4 pad, bank-safe)
#define NROWS   216             // r(64) z(64) n_h(64) fc1(24)
#define WSIZE   (NROWS * WSTRIDE)
#define BB      32768

__device__ float fc1scr_g[2 * 432 * BB];   // [dir][col(t*24+k)][b]

// ---------- helpers ----------
__device__ __forceinline__ uint32_t pack_bf16x2(float lo, float hi) {
    uint32_t r;
    asm("cvt.rn.bf16x2.f32 %0, %1, %2;" : "=r"(r) : "f"(hi), "f"(lo));
    return r;
}
__device__ __forceinline__ float lo_f32(uint32_t p) { return __uint_as_float(p << 16); }
__device__ __forceinline__ float hi_f32(uint32_t p) { return __uint_as_float(p & 0xFFFF0000u); }

__device__ __forceinline__ float sigf(float x) {
    float e, r;
    asm("ex2.approx.f32 %0, %1;" : "=f"(e) : "f"(x * -1.4426950408889634f));
    asm("rcp.approx.f32 %0, %1;" : "=f"(r) : "f"(1.0f + e));
    return r;
}
__device__ __forceinline__ float tanhf2(float x) { return 2.0f * sigf(2.0f * x) - 1.0f; }

__device__ __forceinline__ void mma_bf16(float& c0, float& c1, float& c2, float& c3,
                                         uint32_t a0, uint32_t a1, uint32_t a2, uint32_t a3,
                                         uint32_t b0, uint32_t b1) {
    asm volatile("mma.sync.aligned.m16n8k16.row.col.f32.bf16.bf16.f32 "
                 "{%0,%1,%2,%3}, {%4,%5,%6,%7}, {%8,%9}, {%0,%1,%2,%3};"
                 : "+f"(c0), "+f"(c1), "+f"(c2), "+f"(c3)
                 : "r"(a0), "r"(a1), "r"(a2), "r"(a3), "r"(b0), "r"(b1));
}

__device__ __forceinline__ void tile_mma2(float ca[4], float cb[4],
                                          const uint32_t* __restrict__ sWhi,
                                          const uint32_t* __restrict__ sWlo,
                                          int nt, int kt,
                                          const uint32_t ah[4], const uint32_t al[4],
                                          int lane) {
    const int off = (nt * 8 + (lane >> 2)) * WSTRIDE + kt * 8 + (lane & 3) * 2;
    const uint2 bh = *(const uint2*)(sWhi + off);
    mma_bf16(ca[0], ca[1], ca[2], ca[3], ah[0], ah[1], ah[2], ah[3], bh.x, bh.y);
    mma_bf16(ca[0], ca[1], ca[2], ca[3], al[0], al[1], al[2], al[3], bh.x, bh.y);
    const uint2 bl = *(const uint2*)(sWlo + off);
    mma_bf16(cb[0], cb[1], cb[2], cb[3], ah[0], ah[1], ah[2], ah[3], bl.x, bl.y);
}

// ---------- main kernel: 512 threads, grid 128 ----------
extern __shared__ uint32_t smem_u[];

__global__ __launch_bounds__(512)
void gru_mma_kernel(const float* __restrict__ x,
                    const float* __restrict__ w_ih_f, const float* __restrict__ w_hh_f,
                    const float* __restrict__ b_ih_f, const float* __restrict__ b_hh_f,
                    const float* __restrict__ w_ih_b, const float* __restrict__ w_hh_b,
                    const float* __restrict__ b_ih_b, const float* __restrict__ b_hh_b,
                    const float* __restrict__ fc1_w) {
    uint32_t* sWhi = smem_u;                       // WSIZE
    uint32_t* sWlo = smem_u + WSIZE;               // WSIZE
    float4*   gcR  = (float4*)(smem_u + 2 * WSIZE);          // 64
    float4*   gcZ  = gcR + 64;                               // 64
    float4*   gcN  = gcZ + 64;                               // 64 {w0,w1,bih_n,bhh_n}

    const int tid  = threadIdx.x;
    const int warp = tid >> 5;
    const int lane = tid & 31;
    const int qd   = lane & 3;
    const int row0 = blockIdx.x * 256 + warp * 16 + (lane >> 2);   // rows row0, row0+8

    #pragma unroll 1
    for (int dir = 0; dir < 2; ++dir) {
        const float* wih = dir ? w_ih_b : w_ih_f;
        const float* whh = dir ? w_hh_b : w_hh_f;
        const float* bih = dir ? b_ih_b : b_ih_f;
        const float* bhh = dir ? b_hh_b : b_hh_f;

        __syncthreads();
        // ---- pack W' (h-part rows only) into smem, bf16 hi/lo split ----
        #pragma unroll 1
        for (int i = tid; i < NROWS * 32; i += 512) {
            const int n  = i >> 5;
            const int w  = i & 31;
            const int kt = w >> 3, q = (w >> 1) & 3, r_ = w & 1;
            const int k  = 2 * (q + 8 * kt + (r_ ? 4 : 0));
            float e0, e1;
            if (n < 192) { e0 = whh[n * 64 + k]; e1 = whh[n * 64 + k + 1]; }
            else {
                const int kk = n - 192;
                e0 = fc1_w[kk * 128 + 64 * dir + k];
                e1 = fc1_w[kk * 128 + 64 * dir + k + 1];
            }
            const uint32_t hi = pack_bf16x2(e0, e1);
            const int dst = n * WSTRIDE + w;
            sWhi[dst] = hi;
            sWlo[dst] = pack_bf16x2(e0 - lo_f32(hi), e1 - hi_f32(hi));
        }
        // ---- per-column gate constant tables ----
        if (tid < 64) {
            const int c = tid;
            gcR[c] = make_float4(wih[2*c],         wih[2*c+1],         bih[c] + bhh[c], 0.0f);
            gcZ[c] = make_float4(wih[2*(64+c)],    wih[2*(64+c)+1],    bih[64+c] + bhh[64+c], 0.0f);
            gcN[c] = make_float4(wih[2*(128+c)],   wih[2*(128+c)+1],   bih[128+c], bhh[128+c]);
        }
        __syncthreads();

        float    hprev[8][4];
        uint32_t Ahi[4][4], Alo[4][4];
        #pragma unroll
        for (int g = 0; g < 8; g++)
            #pragma unroll
            for (int i = 0; i < 4; i++) hprev[g][i] = 0.0f;
        #pragma unroll
        for (int kt = 0; kt < 4; kt++)
            #pragma unroll
            for (int i = 0; i < 4; i++) { Ahi[kt][i] = 0u; Alo[kt][i] = 0u; }

        #pragma unroll 1
        for (int s = 0; s < 19; ++s) {
            const int t = dir ? (17 - s) : s;

            if (s < 18) {
                const float2 xa = *(const float2*)(x + (size_t)row0 * 36 + t * 2);
                const float2 xb = *(const float2*)(x + (size_t)(row0 + 8) * 36 + t * 2);
                uint32_t Anh[4][4], Anl[4][4];

                #pragma unroll
                for (int g = 0; g < 8; g++) {
                    const int c0 = g * 8 + qd * 2;
                    const float4 r0 = gcR[c0], r1 = gcR[c0 + 1];
                    const float4 z0 = gcZ[c0], z1 = gcZ[c0 + 1];
                    const float4 n0 = gcN[c0], n1 = gcN[c0 + 1];
                    // x/bias parts (exact fp32), element order: (row0,c0)(row0,c1)(row0+8,c0)(row0+8,c1)
                    float aR[4], aZ[4], aN[4];
                    aR[0] = r0.z + xa.x * r0.x + xa.y * r0.y;
                    aR[1] = r1.z + xa.x * r1.x + xa.y * r1.y;
                    aR[2] = r0.z + xb.x * r0.x + xb.y * r0.y;
                    aR[3] = r1.z + xb.x * r1.x + xb.y * r1.y;
                    aZ[0] = z0.z + xa.x * z0.x + xa.y * z0.y;
                    aZ[1] = z1.z + xa.x * z1.x + xa.y * z1.y;
                    aZ[2] = z0.z + xb.x * z0.x + xb.y * z0.y;
                    aZ[3] = z1.z + xb.x * z1.x + xb.y * z1.y;
                    aN[0] = n0.z + xa.x * n0.x + xa.y * n0.y;
                    aN[1] = n1.z + xa.x * n1.x + xa.y * n1.y;
                    aN[2] = n0.z + xb.x * n0.x + xb.y * n0.y;
                    aN[3] = n1.z + xb.x * n1.x + xb.y * n1.y;

                    float cra[4] = {0,0,0,0}, crb[4] = {0,0,0,0};
                    float cza[4] = {0,0,0,0}, czb[4] = {0,0,0,0};
                    float cha[4] = {0,0,0,0}, chb[4] = {0,0,0,0};
                    if (s > 0) {
                        #pragma unroll
                        for (int kt = 0; kt < 4; kt++) {
                            tile_mma2(cra, crb, sWhi, sWlo, g,      kt, Ahi[kt], Alo[kt], lane);
                            tile_mma2(cza, czb, sWhi, sWlo, g + 8,  kt, Ahi[kt], Alo[kt], lane);
                            tile_mma2(cha, chb, sWhi, sWlo, g + 16, kt, Ahi[kt], Alo[kt], lane);
                        }
                    }
                    #pragma unroll
                    for (int i = 0; i < 4; i++) {
                        const float bnhh = (i & 1) ? n1.w : n0.w;
                        const float r = sigf(cra[i] + crb[i] + aR[i]);
                        const float z = sigf(cza[i] + czb[i] + aZ[i]);
                        const float n = tanhf2(aN[i] + r * (cha[i] + chb[i] + bnhh));
                        hprev[g][i] = n + z * (hprev[g][i] - n);
                    }
                    // pack h_new into next-step A fragments (kt=g/2, half=g&1)
                    const uint32_t ph01 = pack_bf16x2(hprev[g][0], hprev[g][1]);
                    const uint32_t pl01 = pack_bf16x2(hprev[g][0] - lo_f32(ph01),
                                                      hprev[g][1] - hi_f32(ph01));
                    const uint32_t ph23 = pack_bf16x2(hprev[g][2], hprev[g][3]);
                    const uint32_t pl23 = pack_bf16x2(hprev[g][2] - lo_f32(ph23),
                                                      hprev[g][3] - hi_f32(ph23));
                    if ((g & 1) == 0) {
                        Anh[g >> 1][0] = ph01; Anh[g >> 1][1] = ph23;
                        Anl[g >> 1][0] = pl01; Anl[g >> 1][1] = pl23;
                    } else {
                        Anh[g >> 1][2] = ph01; Anh[g >> 1][3] = ph23;
                        Anl[g >> 1][2] = pl01; Anl[g >> 1][3] = pl23;
                    }
                }

                // ---- fc1 tiles (24..26) on h_{s-1}; skip at s=0 ----
                if (s >= 1) {
                    float f0a[4] = {0,0,0,0}, f0b[4] = {0,0,0,0};
                    float f1a[4] = {0,0,0,0}, f1b[4] = {0,0,0,0};
                    float f2a[4] = {0,0,0,0}, f2b[4] = {0,0,0,0};
                    #pragma unroll
                    for (int kt = 0; kt < 4; kt++) {
                        tile_mma2(f0a, f0b, sWhi, sWlo, 24, kt, Ahi[kt], Alo[kt], lane);
                        tile_mma2(f1a, f1b, sWhi, sWlo, 25, kt, Ahi[kt], Alo[kt], lane);
                        tile_mma2(f2a, f2b, sWhi, sWlo, 26, kt, Ahi[kt], Alo[kt], lane);
                    }
                    const int tf = dir ? (18 - s) : (s - 1);
                    float* bp = fc1scr_g + ((size_t)(dir * 432 + tf * 24 + qd * 2)) * BB + row0;
                    bp[0]           = f0a[0] + f0b[0];
                    bp[BB]          = f0a[1] + f0b[1];
                    bp[8]           = f0a[2] + f0b[2];
                    bp[BB + 8]      = f0a[3] + f0b[3];
                    float* b1p = bp + (size_t)8 * BB;
                    b1p[0]          = f1a[0] + f1b[0];
                    b1p[BB]         = f1a[1] + f1b[1];
                    b1p[8]          = f1a[2] + f1b[2];
                    b1p[BB + 8]     = f1a[3] + f1b[3];
                    float* b2p = bp + (size_t)16 * BB;
                    b2p[0]          = f2a[0] + f2b[0];
                    b2p[BB]         = f2a[1] + f2b[1];
                    b2p[8]          = f2a[2] + f2b[2];
                    b2p[BB + 8]     = f2a[3] + f2b[3];
                }

                // ---- rotate A fragments ----
                #pragma unroll
                for (int kt = 0; kt < 4; kt++)
                    #pragma unroll
                    for (int i = 0; i < 4; i++) { Ahi[kt][i] = Anh[kt][i]; Alo[kt][i] = Anl[kt][i]; }
            } else {
                // ---- s=18: fc1 on h_17 only ----
                float f0a[4] = {0,0,0,0}, f0b[4] = {0,0,0,0};
                float f1a[4] = {0,0,0,0}, f1b[4] = {0,0,0,0};
                float f2a[4] = {0,0,0,0}, f2b[4] = {0,0,0,0};
                #pragma unroll
                for (int kt = 0; kt < 4; kt++) {
                    tile_mma2(f0a, f0b, sWhi, sWlo, 24, kt, Ahi[kt], Alo[kt], lane);
                    tile_mma2(f1a, f1b, sWhi, sWlo, 25, kt, Ahi[kt], Alo[kt], lane);
                    tile_mma2(f2a, f2b, sWhi, sWlo, 26, kt, Ahi[kt], Alo[kt], lane);
                }
                const int tf = dir ? 0 : 17;
                float* bp = fc1scr_g + ((size_t)(dir * 432 + tf * 24 + qd * 2)) * BB + row0;
                bp[0]       = f0a[0] + f0b[0];
                bp[BB]      = f0a[1] + f0b[1];
                bp[8]       = f0a[2] + f0b[2];
                bp[BB + 8]  = f0a[3] + f0b[3];
                float* b1p = bp + (size_t)8 * BB;
                b1p[0]      = f1a[0] + f1b[0];
                b1p[BB]     = f1a[1] + f1b[1];
                b1p[8]      = f1a[2] + f1b[2];
                b1p[BB + 8] = f1a[3] + f1b[3];
                float* b2p = bp + (size_t)16 * BB;
                b2p[0]      = f2a[0] + f2b[0];
                b2p[BB]     = f2a[1] + f2b[1];
                b2p[8]      = f2a[2] + f2b[2];
                b2p[BB + 8] = f2a[3] + f2b[3];
            }
        }
    }
}

// ---------- fc2 epilogue (coalesced reads) ----------
__global__ __launch_bounds__(256)
void fc2_kernel(const float* __restrict__ fc1_b,
                const float* __restrict__ fc2_w, const float* __restrict__ fc2_b,
                float* __restrict__ out) {
    const int b = blockIdx.x * blockDim.x + threadIdx.x;
    const float* base = fc1scr_g + b;

    float w2[36];
    #pragma unroll
    for (int j = 0; j < 36; j++) w2[j] = __ldg(fc2_w + j);
    float fb[24];
    #pragma unroll
    for (int k = 0; k < 24; k++) fb[k] = __ldg(fc1_b + k);

    float acc[48];
    #pragma unroll
    for (int m = 0; m < 48; m++) acc[m] = 0.0f;

    #pragma unroll
    for (int n_ = 0; n_ < 432; n_++) {
        const float v = base[(size_t)n_ * BB] + base[(size_t)(432 + n_) * BB] + fb[n_ % 24];
        const int rr = n_ / 18;
        const int jj = n_ % 18;
        acc[2 * rr + 0] += v * w2[jj];
        acc[2 * rr + 1] += v * w2[18 + jj];
    }

    float* ob = out + (size_t)b * 48;
    const float b0 = __ldg(fc2_b), b1 = __ldg(fc2_b + 1);
    #pragma unroll
    for (int m = 0; m < 48; m++) ob[m] = acc[m] + ((m & 1) ? b1 : b0);
}

extern "C" void kernel_launch(void* const* d_in, const int* in_sizes, int n_in,
                              void* d_out, int out_size)
{
    const float* x      = (const float*)d_in[0];
    const float* w_ih_f = (const float*)d_in[1];
    const float* w_hh_f = (const float*)d_in[2];
    const float* b_ih_f = (const float*)d_in[3];
    const float* b_hh_f = (const float*)d_in[4];
    const float* w_ih_b = (const float*)d_in[5];
    const float* w_hh_b = (const float*)d_in[6];
    const float* b_ih_b = (const float*)d_in[7];
    const float* b_hh_b = (const float*)d_in[8];
    const float* fc1_w  = (const float*)d_in[9];
    const float* fc1_b  = (const float*)d_in[10];
    const float* fc2_w  = (const float*)d_in[11];
    const float* fc2_b  = (const float*)d_in[12];
    float* out = (float*)d_out;

    const int smem_bytes = (2 * WSIZE) * (int)sizeof(uint32_t) + 3 * 64 * (int)sizeof(float4);
    cudaFuncSetAttribute(gru_mma_kernel,
                         cudaFuncAttributeMaxDynamicSharedMemorySize, smem_bytes);
    gru_mma_kernel<<<128, 512, smem_bytes>>>(
        x, w_ih_f, w_hh_f, b_ih_f, b_hh_f,
        w_ih_b, w_hh_b, b_ih_b, b_hh_b, fc1_w);

    fc2_kernel<<<BB / 256, 256>>>(fc1_b, fc2_w, fc2_b, out);
}

// round 8
// speedup vs baseline: 4.7789x; 1.0401x over previous
#include <cuda_runtime.h>
#include <cstdint>

// Bidirectional GRU (B=32768, T=18, I=2, H=64) + fc1(128->24) + reshape + fc2(18->2)
// R8: single fused kernel. mma.sync bf16 3-product for h-recurrence + fc1;
// x/bias parts scalar; fc2 contraction fused via per-thread 48-float accumulators
// (quad shfl-reduce at end). No scratch global, no second kernel.

#define WSTRIDE 36              // u32 per n-row (32 used + 4 pad, bank-safe)
#define NROWS   216             // r(64) z(64) n_h(64) fc1(24)
#define WSIZE   (NROWS * WSTRIDE)
#define BB      32768

// ---------- helpers ----------
__device__ __forceinline__ uint32_t pack_bf16x2(float lo, float hi) {
    uint32_t r;
    asm("cvt.rn.bf16x2.f32 %0, %1, %2;" : "=r"(r) : "f"(hi), "f"(lo));
    return r;
}
__device__ __forceinline__ float lo_f32(uint32_t p) { return __uint_as_float(p << 16); }
__device__ __forceinline__ float hi_f32(uint32_t p) { return __uint_as_float(p & 0xFFFF0000u); }

__device__ __forceinline__ float sigf(float x) {
    float e, r;
    asm("ex2.approx.f32 %0, %1;" : "=f"(e) : "f"(x * -1.4426950408889634f));
    asm("rcp.approx.f32 %0, %1;" : "=f"(r) : "f"(1.0f + e));
    return r;
}
__device__ __forceinline__ float tanhf2(float x) { return 2.0f * sigf(2.0f * x) - 1.0f; }

__device__ __forceinline__ void mma_bf16(float& c0, float& c1, float& c2, float& c3,
                                         uint32_t a0, uint32_t a1, uint32_t a2, uint32_t a3,
                                         uint32_t b0, uint32_t b1) {
    asm volatile("mma.sync.aligned.m16n8k16.row.col.f32.bf16.bf16.f32 "
                 "{%0,%1,%2,%3}, {%4,%5,%6,%7}, {%8,%9}, {%0,%1,%2,%3};"
                 : "+f"(c0), "+f"(c1), "+f"(c2), "+f"(c3)
                 : "r"(a0), "r"(a1), "r"(a2), "r"(a3), "r"(b0), "r"(b1));
}

__device__ __forceinline__ void tile_mma2(float ca[4], float cb[4],
                                          const uint32_t* __restrict__ sWhi,
                                          const uint32_t* __restrict__ sWlo,
                                          int nt, int kt,
                                          const uint32_t ah[4], const uint32_t al[4],
                                          int lane) {
    const int off = (nt * 8 + (lane >> 2)) * WSTRIDE + kt * 8 + (lane & 3) * 2;
    const uint2 bh = *(const uint2*)(sWhi + off);
    mma_bf16(ca[0], ca[1], ca[2], ca[3], ah[0], ah[1], ah[2], ah[3], bh.x, bh.y);
    mma_bf16(ca[0], ca[1], ca[2], ca[3], al[0], al[1], al[2], al[3], bh.x, bh.y);
    const uint2 bl = *(const uint2*)(sWlo + off);
    mma_bf16(cb[0], cb[1], cb[2], cb[3], ah[0], ah[1], ah[2], ah[3], bl.x, bl.y);
}

// ---------- fused kernel: 512 threads, grid 128 ----------
extern __shared__ uint32_t smem_u[];

__global__ __launch_bounds__(512)
void gru_mma_kernel(const float* __restrict__ x,
                    const float* __restrict__ w_ih_f, const float* __restrict__ w_hh_f,
                    const float* __restrict__ b_ih_f, const float* __restrict__ b_hh_f,
                    const float* __restrict__ w_ih_b, const float* __restrict__ w_hh_b,
                    const float* __restrict__ b_ih_b, const float* __restrict__ b_hh_b,
                    const float* __restrict__ fc1_w, const float* __restrict__ fc1_b,
                    const float* __restrict__ fc2_w, const float* __restrict__ fc2_b,
                    float* __restrict__ out) {
    uint32_t* sWhi = smem_u;                       // WSIZE
    uint32_t* sWlo = smem_u + WSIZE;               // WSIZE
    float4*   gcR  = (float4*)(smem_u + 2 * WSIZE);          // 64
    float4*   gcZ  = gcR + 64;                               // 64
    float4*   gcN  = gcZ + 64;                               // 64 {w0,w1,bih_n,bhh_n}
    float*    fc2ws = (float*)(gcN + 64);                    // 36

    const int tid  = threadIdx.x;
    const int warp = tid >> 5;
    const int lane = tid & 31;
    const int qd   = lane & 3;
    const int row0 = blockIdx.x * 256 + warp * 16 + (lane >> 2);   // rows row0, row0+8

    if (tid < 36) fc2ws[tid] = fc2_w[tid];

    // per-thread fixed fc1 column indices + biases
    const int kk0 = qd * 2;
    int kk[6] = {kk0, kk0 + 1, kk0 + 8, kk0 + 9, kk0 + 16, kk0 + 17};
    float fbv[6];
    #pragma unroll
    for (int j = 0; j < 6; j++) fbv[j] = __ldg(fc1_b + kk[j]);

    // fc2 accumulators (dynamic-indexed -> local mem)
    float a2r0[48], a2r8[48];
    #pragma unroll
    for (int m = 0; m < 48; m++) { a2r0[m] = 0.0f; a2r8[m] = 0.0f; }

    #pragma unroll 1
    for (int dir = 0; dir < 2; ++dir) {
        const float* wih = dir ? w_ih_b : w_ih_f;
        const float* whh = dir ? w_hh_b : w_hh_f;
        const float* bih = dir ? b_ih_b : b_ih_f;
        const float* bhh = dir ? b_hh_b : b_hh_f;

        __syncthreads();
        // ---- pack W' (h-part rows only) into smem, bf16 hi/lo split ----
        #pragma unroll 1
        for (int i = tid; i < NROWS * 32; i += 512) {
            const int n  = i >> 5;
            const int w  = i & 31;
            const int kt = w >> 3, q = (w >> 1) & 3, r_ = w & 1;
            const int k  = 2 * (q + 8 * kt + (r_ ? 4 : 0));
            float e0, e1;
            if (n < 192) { e0 = whh[n * 64 + k]; e1 = whh[n * 64 + k + 1]; }
            else {
                const int kq = n - 192;
                e0 = fc1_w[kq * 128 + 64 * dir + k];
                e1 = fc1_w[kq * 128 + 64 * dir + k + 1];
            }
            const uint32_t hi = pack_bf16x2(e0, e1);
            const int dst = n * WSTRIDE + w;
            sWhi[dst] = hi;
            sWlo[dst] = pack_bf16x2(e0 - lo_f32(hi), e1 - hi_f32(hi));
        }
        // ---- per-column gate constant tables ----
        if (tid < 64) {
            const int c = tid;
            gcR[c] = make_float4(wih[2*c],       wih[2*c+1],       bih[c] + bhh[c], 0.0f);
            gcZ[c] = make_float4(wih[2*(64+c)],  wih[2*(64+c)+1],  bih[64+c] + bhh[64+c], 0.0f);
            gcN[c] = make_float4(wih[2*(128+c)], wih[2*(128+c)+1], bih[128+c], bhh[128+c]);
        }
        __syncthreads();

        float    hprev[8][4];
        uint32_t Ahi[4][4], Alo[4][4];
        #pragma unroll
        for (int g = 0; g < 8; g++)
            #pragma unroll
            for (int i = 0; i < 4; i++) hprev[g][i] = 0.0f;
        #pragma unroll
        for (int kt = 0; kt < 4; kt++)
            #pragma unroll
            for (int i = 0; i < 4; i++) { Ahi[kt][i] = 0u; Alo[kt][i] = 0u; }

        #pragma unroll 1
        for (int s = 0; s < 19; ++s) {
            const int t = dir ? (17 - s) : s;

            if (s < 18) {
                const float2 xa = *(const float2*)(x + (size_t)row0 * 36 + t * 2);
                const float2 xb = *(const float2*)(x + (size_t)(row0 + 8) * 36 + t * 2);
                uint32_t Anh[4][4], Anl[4][4];

                #pragma unroll
                for (int g = 0; g < 8; g++) {
                    const int c0 = g * 8 + qd * 2;
                    const float4 r0 = gcR[c0], r1 = gcR[c0 + 1];
                    const float4 z0 = gcZ[c0], z1 = gcZ[c0 + 1];
                    const float4 n0 = gcN[c0], n1 = gcN[c0 + 1];
                    float aR[4], aZ[4], aN[4];
                    aR[0] = r0.z + xa.x * r0.x + xa.y * r0.y;
                    aR[1] = r1.z + xa.x * r1.x + xa.y * r1.y;
                    aR[2] = r0.z + xb.x * r0.x + xb.y * r0.y;
                    aR[3] = r1.z + xb.x * r1.x + xb.y * r1.y;
                    aZ[0] = z0.z + xa.x * z0.x + xa.y * z0.y;
                    aZ[1] = z1.z + xa.x * z1.x + xa.y * z1.y;
                    aZ[2] = z0.z + xb.x * z0.x + xb.y * z0.y;
                    aZ[3] = z1.z + xb.x * z1.x + xb.y * z1.y;
                    aN[0] = n0.z + xa.x * n0.x + xa.y * n0.y;
                    aN[1] = n1.z + xa.x * n1.x + xa.y * n1.y;
                    aN[2] = n0.z + xb.x * n0.x + xb.y * n0.y;
                    aN[3] = n1.z + xb.x * n1.x + xb.y * n1.y;

                    float cra[4] = {0,0,0,0}, crb[4] = {0,0,0,0};
                    float cza[4] = {0,0,0,0}, czb[4] = {0,0,0,0};
                    float cha[4] = {0,0,0,0}, chb[4] = {0,0,0,0};
                    if (s > 0) {
                        #pragma unroll
                        for (int kt = 0; kt < 4; kt++) {
                            tile_mma2(cra, crb, sWhi, sWlo, g,      kt, Ahi[kt], Alo[kt], lane);
                            tile_mma2(cza, czb, sWhi, sWlo, g + 8,  kt, Ahi[kt], Alo[kt], lane);
                            tile_mma2(cha, chb, sWhi, sWlo, g + 16, kt, Ahi[kt], Alo[kt], lane);
                        }
                    }
                    #pragma unroll
                    for (int i = 0; i < 4; i++) {
                        const float bnhh = (i & 1) ? n1.w : n0.w;
                        const float r = sigf(cra[i] + crb[i] + aR[i]);
                        const float z = sigf(cza[i] + czb[i] + aZ[i]);
                        const float n = tanhf2(aN[i] + r * (cha[i] + chb[i] + bnhh));
                        hprev[g][i] = n + z * (hprev[g][i] - n);
                    }
                    const uint32_t ph01 = pack_bf16x2(hprev[g][0], hprev[g][1]);
                    const uint32_t pl01 = pack_bf16x2(hprev[g][0] - lo_f32(ph01),
                                                      hprev[g][1] - hi_f32(ph01));
                    const uint32_t ph23 = pack_bf16x2(hprev[g][2], hprev[g][3]);
                    const uint32_t pl23 = pack_bf16x2(hprev[g][2] - lo_f32(ph23),
                                                      hprev[g][3] - hi_f32(ph23));
                    if ((g & 1) == 0) {
                        Anh[g >> 1][0] = ph01; Anh[g >> 1][1] = ph23;
                        Anl[g >> 1][0] = pl01; Anl[g >> 1][1] = pl23;
                    } else {
                        Anh[g >> 1][2] = ph01; Anh[g >> 1][3] = ph23;
                        Anl[g >> 1][2] = pl01; Anl[g >> 1][3] = pl23;
                    }
                }

                // ---- fc1 tiles (24..26) on h_{s-1} + fused fc2 scatter ----
                if (s >= 1) {
                    float f0a[4] = {0,0,0,0}, f0b[4] = {0,0,0,0};
                    float f1a[4] = {0,0,0,0}, f1b[4] = {0,0,0,0};
                    float f2a[4] = {0,0,0,0}, f2b[4] = {0,0,0,0};
                    #pragma unroll
                    for (int kt = 0; kt < 4; kt++) {
                        tile_mma2(f0a, f0b, sWhi, sWlo, 24, kt, Ahi[kt], Alo[kt], lane);
                        tile_mma2(f1a, f1b, sWhi, sWlo, 25, kt, Ahi[kt], Alo[kt], lane);
                        tile_mma2(f2a, f2b, sWhi, sWlo, 26, kt, Ahi[kt], Alo[kt], lane);
                    }
                    const int tf = dir ? (18 - s) : (s - 1);
                    const float vv0[6] = {f0a[0]+f0b[0], f0a[1]+f0b[1], f1a[0]+f1b[0],
                                          f1a[1]+f1b[1], f2a[0]+f2b[0], f2a[1]+f2b[1]};
                    const float vv8[6] = {f0a[2]+f0b[2], f0a[3]+f0b[3], f1a[2]+f1b[2],
                                          f1a[3]+f1b[3], f2a[2]+f2b[2], f2a[3]+f2b[3]};
                    #pragma unroll
                    for (int j = 0; j < 6; j++) {
                        const int n_ = tf * 24 + kk[j];
                        const int rr = n_ / 18;
                        const int jj = n_ - rr * 18;
                        const float wl = fc2ws[jj], wh = fc2ws[18 + jj];
                        const float fb = dir ? 0.0f : fbv[j];
                        const float va = vv0[j] + fb;
                        const float vb = vv8[j] + fb;
                        a2r0[2*rr]     += va * wl;
                        a2r0[2*rr + 1] += va * wh;
                        a2r8[2*rr]     += vb * wl;
                        a2r8[2*rr + 1] += vb * wh;
                    }
                }

                #pragma unroll
                for (int kt = 0; kt < 4; kt++)
                    #pragma unroll
                    for (int i = 0; i < 4; i++) { Ahi[kt][i] = Anh[kt][i]; Alo[kt][i] = Anl[kt][i]; }
            } else {
                // ---- s=18: fc1 on h_17 + fused fc2 scatter ----
                float f0a[4] = {0,0,0,0}, f0b[4] = {0,0,0,0};
                float f1a[4] = {0,0,0,0}, f1b[4] = {0,0,0,0};
                float f2a[4] = {0,0,0,0}, f2b[4] = {0,0,0,0};
                #pragma unroll
                for (int kt = 0; kt < 4; kt++) {
                    tile_mma2(f0a, f0b, sWhi, sWlo, 24, kt, Ahi[kt], Alo[kt], lane);
                    tile_mma2(f1a, f1b, sWhi, sWlo, 25, kt, Ahi[kt], Alo[kt], lane);
                    tile_mma2(f2a, f2b, sWhi, sWlo, 26, kt, Ahi[kt], Alo[kt], lane);
                }
                const int tf = dir ? 0 : 17;
                const float vv0[6] = {f0a[0]+f0b[0], f0a[1]+f0b[1], f1a[0]+f1b[0],
                                      f1a[1]+f1b[1], f2a[0]+f2b[0], f2a[1]+f2b[1]};
                const float vv8[6] = {f0a[2]+f0b[2], f0a[3]+f0b[3], f1a[2]+f1b[2],
                                      f1a[3]+f1b[3], f2a[2]+f2b[2], f2a[3]+f2b[3]};
                #pragma unroll
                for (int j = 0; j < 6; j++) {
                    const int n_ = tf * 24 + kk[j];
                    const int rr = n_ / 18;
                    const int jj = n_ - rr * 18;
                    const float wl = fc2ws[jj], wh = fc2ws[18 + jj];
                    const float fb = dir ? 0.0f : fbv[j];
                    const float va = vv0[j] + fb;
                    const float vb = vv8[j] + fb;
                    a2r0[2*rr]     += va * wl;
                    a2r0[2*rr + 1] += va * wh;
                    a2r8[2*rr]     += vb * wl;
                    a2r8[2*rr + 1] += vb * wh;
                }
            }
        }
    }

    // ---- quad reduce + write (qd==0 lane per row) ----
    const float b0v = __ldg(fc2_b), b1v = __ldg(fc2_b + 1);
    float* o0 = out + (size_t)row0 * 48;
    float* o8 = out + (size_t)(row0 + 8) * 48;
    #pragma unroll
    for (int m = 0; m < 48; m++) {
        float r0v = a2r0[m];
        r0v += __shfl_xor_sync(0xffffffffu, r0v, 1);
        r0v += __shfl_xor_sync(0xffffffffu, r0v, 2);
        float r8v = a2r8[m];
        r8v += __shfl_xor_sync(0xffffffffu, r8v, 1);
        r8v += __shfl_xor_sync(0xffffffffu, r8v, 2);
        if (qd == 0) {
            const float bb = (m & 1) ? b1v : b0v;
            o0[m] = r0v + bb;
            o8[m] = r8v + bb;
        }
    }
}

extern "C" void kernel_launch(void* const* d_in, const int* in_sizes, int n_in,
                              void* d_out, int out_size)
{
    const float* x      = (const float*)d_in[0];
    const float* w_ih_f = (const float*)d_in[1];
    const float* w_hh_f = (const float*)d_in[2];
    const float* b_ih_f = (const float*)d_in[3];
    const float* b_hh_f = (const float*)d_in[4];
    const float* w_ih_b = (const float*)d_in[5];
    const float* w_hh_b = (const float*)d_in[6];
    const float* b_ih_b = (const float*)d_in[7];
    const float* b_hh_b = (const float*)d_in[8];
    const float* fc1_w  = (const float*)d_in[9];
    const float* fc1_b  = (const float*)d_in[10];
    const float* fc2_w  = (const float*)d_in[11];
    const float* fc2_b  = (const float*)d_in[12];
    float* out = (float*)d_out;

    const int smem_bytes = (2 * WSIZE) * (int)sizeof(uint32_t)
                         + 3 * 64 * (int)sizeof(float4) + 40 * (int)sizeof(float);
    cudaFuncSetAttribute(gru_mma_kernel,
                         cudaFuncAttributeMaxDynamicSharedMemorySize, smem_bytes);
    gru_mma_kernel<<<128, 512, smem_bytes>>>(
        x, w_ih_f, w_hh_f, b_ih_f, b_hh_f,
        w_ih_b, w_hh_b, b_ih_b, b_hh_b, fc1_w, fc1_b, fc2_w, fc2_b, out);
}

// round 9
// speedup vs baseline: 5.2126x; 1.0908x over previous
#include <cuda_runtime.h>
#include <cstdint>

// Bidirectional GRU (B=32768, T=18, I=2, H=64) + fc1(128->24) + reshape + fc2(18->2)
// R9: same mma.sync bf16 3-product math as R8, LSU-dieted:
//  - W hi/lo interleaved in one uint4 -> 1 LDS.128 per tile (was 2 LDS.64)
//  - row stride 20 uint4 (bank-conflict-free 128-bit phases)
//  - fc2 scatter via float2 accumulators + paired fc2 weights (halved LDL/STL)

#define W4STRIDE 20             // uint4 per n-row (16 used + 4 pad)
#define NROWS    216            // r(64) z(64) n_h(64) fc1(24)
#define W4SIZE   (NROWS * W4STRIDE)   // 4320 uint4

// ---------- helpers ----------
__device__ __forceinline__ uint32_t pack_bf16x2(float lo, float hi) {
    uint32_t r;
    asm("cvt.rn.bf16x2.f32 %0, %1, %2;" : "=r"(r) : "f"(hi), "f"(lo));
    return r;
}
__device__ __forceinline__ float lo_f32(uint32_t p) { return __uint_as_float(p << 16); }
__device__ __forceinline__ float hi_f32(uint32_t p) { return __uint_as_float(p & 0xFFFF0000u); }

__device__ __forceinline__ float sigf(float x) {
    float e, r;
    asm("ex2.approx.f32 %0, %1;" : "=f"(e) : "f"(x * -1.4426950408889634f));
    asm("rcp.approx.f32 %0, %1;" : "=f"(r) : "f"(1.0f + e));
    return r;
}
__device__ __forceinline__ float tanhf2(float x) { return 2.0f * sigf(2.0f * x) - 1.0f; }

__device__ __forceinline__ void mma_bf16(float& c0, float& c1, float& c2, float& c3,
                                         uint32_t a0, uint32_t a1, uint32_t a2, uint32_t a3,
                                         uint32_t b0, uint32_t b1) {
    asm volatile("mma.sync.aligned.m16n8k16.row.col.f32.bf16.bf16.f32 "
                 "{%0,%1,%2,%3}, {%4,%5,%6,%7}, {%8,%9}, {%0,%1,%2,%3};"
                 : "+f"(c0), "+f"(c1), "+f"(c2), "+f"(c3)
                 : "r"(a0), "r"(a1), "r"(a2), "r"(a3), "r"(b0), "r"(b1));
}

// one LDS.128 per tile: w = {bh0, bh1, bl0, bl1}
__device__ __forceinline__ void tile_mma2(float ca[4], float cb[4],
                                          const uint4* __restrict__ sW4th,
                                          int nt, int kt,
                                          const uint32_t ah[4], const uint32_t al[4]) {
    const uint4 w = sW4th[nt * (8 * W4STRIDE) + kt * 4];
    mma_bf16(ca[0], ca[1], ca[2], ca[3], ah[0], ah[1], ah[2], ah[3], w.x, w.y);
    mma_bf16(ca[0], ca[1], ca[2], ca[3], al[0], al[1], al[2], al[3], w.x, w.y);
    mma_bf16(cb[0], cb[1], cb[2], cb[3], ah[0], ah[1], ah[2], ah[3], w.z, w.w);
}

// ---------- fused kernel: 512 threads, grid 128 ----------
extern __shared__ uint32_t smem_u[];

__global__ __launch_bounds__(512)
void gru_mma_kernel(const float* __restrict__ x,
                    const float* __restrict__ w_ih_f, const float* __restrict__ w_hh_f,
                    const float* __restrict__ b_ih_f, const float* __restrict__ b_hh_f,
                    const float* __restrict__ w_ih_b, const float* __restrict__ w_hh_b,
                    const float* __restrict__ b_ih_b, const float* __restrict__ b_hh_b,
                    const float* __restrict__ fc1_w, const float* __restrict__ fc1_b,
                    const float* __restrict__ fc2_w, const float* __restrict__ fc2_b,
                    float* __restrict__ out) {
    uint4*  sW4  = (uint4*)smem_u;                       // W4SIZE uint4
    float4* gcR  = (float4*)(sW4 + W4SIZE);              // 64
    float4* gcZ  = gcR + 64;                             // 64
    float4* gcN  = gcZ + 64;                             // 64 {w0,w1,bih_n,bhh_n}
    float2* fc2p = (float2*)(gcN + 64);                  // 18 {w_row0[j], w_row1[j]}

    const int tid  = threadIdx.x;
    const int warp = tid >> 5;
    const int lane = tid & 31;
    const int qd   = lane & 3;
    const int row0 = blockIdx.x * 256 + warp * 16 + (lane >> 2);   // rows row0, row0+8
    const uint4* sW4th = sW4 + (lane >> 2) * W4STRIDE + qd;

    if (tid < 18) fc2p[tid] = make_float2(fc2_w[tid], fc2_w[18 + tid]);

    // per-thread fixed fc1 column indices + biases
    const int kk0 = qd * 2;
    int kk[6] = {kk0, kk0 + 1, kk0 + 8, kk0 + 9, kk0 + 16, kk0 + 17};
    float fbv[6];
    #pragma unroll
    for (int j = 0; j < 6; j++) fbv[j] = __ldg(fc1_b + kk[j]);

    // fc2 accumulators (dynamic-indexed -> local mem), float2 granularity
    float2 a2r0[24], a2r8[24];
    #pragma unroll
    for (int m = 0; m < 24; m++) {
        a2r0[m] = make_float2(0.0f, 0.0f);
        a2r8[m] = make_float2(0.0f, 0.0f);
    }

    #pragma unroll 1
    for (int dir = 0; dir < 2; ++dir) {
        const float* wih = dir ? w_ih_b : w_ih_f;
        const float* whh = dir ? w_hh_b : w_hh_f;
        const float* bih = dir ? b_ih_b : b_ih_f;
        const float* bhh = dir ? b_hh_b : b_hh_f;

        __syncthreads();
        // ---- pack W' rows into smem: uint4 {hi0, hi1, lo0, lo1} per (row, kt, quad) ----
        #pragma unroll 1
        for (int i = tid; i < NROWS * 16; i += 512) {
            const int n   = i >> 4;
            const int rem = i & 15;
            const int kt  = rem >> 2, q = rem & 3;
            const int kA  = 2 * (q + 8 * kt);      // b0 k-pair
            const int kB  = kA + 8;                // b1 k-pair
            float e0, e1, e2, e3;
            if (n < 192) {
                e0 = whh[n * 64 + kA]; e1 = whh[n * 64 + kA + 1];
                e2 = whh[n * 64 + kB]; e3 = whh[n * 64 + kB + 1];
            } else {
                const int kq = n - 192;
                const float* fr = fc1_w + kq * 128 + 64 * dir;
                e0 = fr[kA]; e1 = fr[kA + 1];
                e2 = fr[kB]; e3 = fr[kB + 1];
            }
            const uint32_t hi0 = pack_bf16x2(e0, e1);
            const uint32_t hi1 = pack_bf16x2(e2, e3);
            uint4 w;
            w.x = hi0;
            w.y = hi1;
            w.z = pack_bf16x2(e0 - lo_f32(hi0), e1 - hi_f32(hi0));
            w.w = pack_bf16x2(e2 - lo_f32(hi1), e3 - hi_f32(hi1));
            sW4[n * W4STRIDE + kt * 4 + q] = w;
        }
        // ---- per-column gate constant tables ----
        if (tid < 64) {
            const int c = tid;
            gcR[c] = make_float4(wih[2*c],       wih[2*c+1],       bih[c] + bhh[c], 0.0f);
            gcZ[c] = make_float4(wih[2*(64+c)],  wih[2*(64+c)+1],  bih[64+c] + bhh[64+c], 0.0f);
            gcN[c] = make_float4(wih[2*(128+c)], wih[2*(128+c)+1], bih[128+c], bhh[128+c]);
        }
        __syncthreads();

        float    hprev[8][4];
        uint32_t Ahi[4][4], Alo[4][4];
        #pragma unroll
        for (int g = 0; g < 8; g++)
            #pragma unroll
            for (int i = 0; i < 4; i++) hprev[g][i] = 0.0f;
        #pragma unroll
        for (int kt = 0; kt < 4; kt++)
            #pragma unroll
            for (int i = 0; i < 4; i++) { Ahi[kt][i] = 0u; Alo[kt][i] = 0u; }

        #pragma unroll 1
        for (int s = 0; s < 19; ++s) {
            const int t = dir ? (17 - s) : s;

            if (s < 18) {
                const float2 xa = *(const float2*)(x + (size_t)row0 * 36 + t * 2);
                const float2 xb = *(const float2*)(x + (size_t)(row0 + 8) * 36 + t * 2);
                uint32_t Anh[4][4], Anl[4][4];

                #pragma unroll
                for (int g = 0; g < 8; g++) {
                    const int c0 = g * 8 + qd * 2;
                    const float4 r0 = gcR[c0], r1 = gcR[c0 + 1];
                    const float4 z0 = gcZ[c0], z1 = gcZ[c0 + 1];
                    const float4 n0 = gcN[c0], n1 = gcN[c0 + 1];
                    float aR[4], aZ[4], aN[4];
                    aR[0] = r0.z + xa.x * r0.x + xa.y * r0.y;
                    aR[1] = r1.z + xa.x * r1.x + xa.y * r1.y;
                    aR[2] = r0.z + xb.x * r0.x + xb.y * r0.y;
                    aR[3] = r1.z + xb.x * r1.x + xb.y * r1.y;
                    aZ[0] = z0.z + xa.x * z0.x + xa.y * z0.y;
                    aZ[1] = z1.z + xa.x * z1.x + xa.y * z1.y;
                    aZ[2] = z0.z + xb.x * z0.x + xb.y * z0.y;
                    aZ[3] = z1.z + xb.x * z1.x + xb.y * z1.y;
                    aN[0] = n0.z + xa.x * n0.x + xa.y * n0.y;
                    aN[1] = n1.z + xa.x * n1.x + xa.y * n1.y;
                    aN[2] = n0.z + xb.x * n0.x + xb.y * n0.y;
                    aN[3] = n1.z + xb.x * n1.x + xb.y * n1.y;

                    float cra[4] = {0,0,0,0}, crb[4] = {0,0,0,0};
                    float cza[4] = {0,0,0,0}, czb[4] = {0,0,0,0};
                    float cha[4] = {0,0,0,0}, chb[4] = {0,0,0,0};
                    if (s > 0) {
                        #pragma unroll
                        for (int kt = 0; kt < 4; kt++) {
                            tile_mma2(cra, crb, sW4th, g,      kt, Ahi[kt], Alo[kt]);
                            tile_mma2(cza, czb, sW4th, g + 8,  kt, Ahi[kt], Alo[kt]);
                            tile_mma2(cha, chb, sW4th, g + 16, kt, Ahi[kt], Alo[kt]);
                        }
                    }
                    #pragma unroll
                    for (int i = 0; i < 4; i++) {
                        const float bnhh = (i & 1) ? n1.w : n0.w;
                        const float r = sigf(cra[i] + crb[i] + aR[i]);
                        const float z = sigf(cza[i] + czb[i] + aZ[i]);
                        const float n = tanhf2(aN[i] + r * (cha[i] + chb[i] + bnhh));
                        hprev[g][i] = n + z * (hprev[g][i] - n);
                    }
                    const uint32_t ph01 = pack_bf16x2(hprev[g][0], hprev[g][1]);
                    const uint32_t pl01 = pack_bf16x2(hprev[g][0] - lo_f32(ph01),
                                                      hprev[g][1] - hi_f32(ph01));
                    const uint32_t ph23 = pack_bf16x2(hprev[g][2], hprev[g][3]);
                    const uint32_t pl23 = pack_bf16x2(hprev[g][2] - lo_f32(ph23),
                                                      hprev[g][3] - hi_f32(ph23));
                    if ((g & 1) == 0) {
                        Anh[g >> 1][0] = ph01; Anh[g >> 1][1] = ph23;
                        Anl[g >> 1][0] = pl01; Anl[g >> 1][1] = pl23;
                    } else {
                        Anh[g >> 1][2] = ph01; Anh[g >> 1][3] = ph23;
                        Anl[g >> 1][2] = pl01; Anl[g >> 1][3] = pl23;
                    }
                }

                // ---- fc1 tiles (24..26) on h_{s-1} + fused fc2 scatter ----
                if (s >= 1) {
                    float f0a[4] = {0,0,0,0}, f0b[4] = {0,0,0,0};
                    float f1a[4] = {0,0,0,0}, f1b[4] = {0,0,0,0};
                    float f2a[4] = {0,0,0,0}, f2b[4] = {0,0,0,0};
                    #pragma unroll
                    for (int kt = 0; kt < 4; kt++) {
                        tile_mma2(f0a, f0b, sW4th, 24, kt, Ahi[kt], Alo[kt]);
                        tile_mma2(f1a, f1b, sW4th, 25, kt, Ahi[kt], Alo[kt]);
                        tile_mma2(f2a, f2b, sW4th, 26, kt, Ahi[kt], Alo[kt]);
                    }
                    const int tf = dir ? (18 - s) : (s - 1);
                    const float vv0[6] = {f0a[0]+f0b[0], f0a[1]+f0b[1], f1a[0]+f1b[0],
                                          f1a[1]+f1b[1], f2a[0]+f2b[0], f2a[1]+f2b[1]};
                    const float vv8[6] = {f0a[2]+f0b[2], f0a[3]+f0b[3], f1a[2]+f1b[2],
                                          f1a[3]+f1b[3], f2a[2]+f2b[2], f2a[3]+f2b[3]};
                    #pragma unroll
                    for (int j = 0; j < 6; j++) {
                        const int n_ = tf * 24 + kk[j];
                        const int rr = n_ / 18;
                        const int jj = n_ - rr * 18;
                        const float2 w2 = fc2p[jj];
                        const float fb = dir ? 0.0f : fbv[j];
                        const float va = vv0[j] + fb;
                        const float vb = vv8[j] + fb;
                        float2 c0 = a2r0[rr];
                        c0.x += va * w2.x; c0.y += va * w2.y;
                        a2r0[rr] = c0;
                        float2 c8 = a2r8[rr];
                        c8.x += vb * w2.x; c8.y += vb * w2.y;
                        a2r8[rr] = c8;
                    }
                }

                #pragma unroll
                for (int kt = 0; kt < 4; kt++)
                    #pragma unroll
                    for (int i = 0; i < 4; i++) { Ahi[kt][i] = Anh[kt][i]; Alo[kt][i] = Anl[kt][i]; }
            } else {
                // ---- s=18: fc1 on h_17 + fused fc2 scatter ----
                float f0a[4] = {0,0,0,0}, f0b[4] = {0,0,0,0};
                float f1a[4] = {0,0,0,0}, f1b[4] = {0,0,0,0};
                float f2a[4] = {0,0,0,0}, f2b[4] = {0,0,0,0};
                #pragma unroll
                for (int kt = 0; kt < 4; kt++) {
                    tile_mma2(f0a, f0b, sW4th, 24, kt, Ahi[kt], Alo[kt]);
                    tile_mma2(f1a, f1b, sW4th, 25, kt, Ahi[kt], Alo[kt]);
                    tile_mma2(f2a, f2b, sW4th, 26, kt, Ahi[kt], Alo[kt]);
                }
                const int tf = dir ? 0 : 17;
                const float vv0[6] = {f0a[0]+f0b[0], f0a[1]+f0b[1], f1a[0]+f1b[0],
                                      f1a[1]+f1b[1], f2a[0]+f2b[0], f2a[1]+f2b[1]};
                const float vv8[6] = {f0a[2]+f0b[2], f0a[3]+f0b[3], f1a[2]+f1b[2],
                                      f1a[3]+f1b[3], f2a[2]+f2b[2], f2a[3]+f2b[3]};
                #pragma unroll
                for (int j = 0; j < 6; j++) {
                    const int n_ = tf * 24 + kk[j];
                    const int rr = n_ / 18;
                    const int jj = n_ - rr * 18;
                    const float2 w2 = fc2p[jj];
                    const float fb = dir ? 0.0f : fbv[j];
                    const float va = vv0[j] + fb;
                    const float vb = vv8[j] + fb;
                    float2 c0 = a2r0[rr];
                    c0.x += va * w2.x; c0.y += va * w2.y;
                    a2r0[rr] = c0;
                    float2 c8 = a2r8[rr];
                    c8.x += vb * w2.x; c8.y += vb * w2.y;
                    a2r8[rr] = c8;
                }
            }
        }
    }

    // ---- quad reduce + write (qd==0 lane per row) ----
    const float b0v = __ldg(fc2_b), b1v = __ldg(fc2_b + 1);
    float* o0 = out + (size_t)row0 * 48;
    float* o8 = out + (size_t)(row0 + 8) * 48;
    #pragma unroll
    for (int p = 0; p < 24; p++) {
        float2 v0 = a2r0[p];
        v0.x += __shfl_xor_sync(0xffffffffu, v0.x, 1);
        v0.x += __shfl_xor_sync(0xffffffffu, v0.x, 2);
        v0.y += __shfl_xor_sync(0xffffffffu, v0.y, 1);
        v0.y += __shfl_xor_sync(0xffffffffu, v0.y, 2);
        float2 v8 = a2r8[p];
        v8.x += __shfl_xor_sync(0xffffffffu, v8.x, 1);
        v8.x += __shfl_xor_sync(0xffffffffu, v8.x, 2);
        v8.y += __shfl_xor_sync(0xffffffffu, v8.y, 1);
        v8.y += __shfl_xor_sync(0xffffffffu, v8.y, 2);
        if (qd == 0) {
            o0[2*p]     = v0.x + b0v;
            o0[2*p + 1] = v0.y + b1v;
            o8[2*p]     = v8.x + b0v;
            o8[2*p + 1] = v8.y + b1v;
        }
    }
}

extern "C" void kernel_launch(void* const* d_in, const int* in_sizes, int n_in,
                              void* d_out, int out_size)
{
    const float* x      = (const float*)d_in[0];
    const float* w_ih_f = (const float*)d_in[1];
    const float* w_hh_f = (const float*)d_in[2];
    const float* b_ih_f = (const float*)d_in[3];
    const float* b_hh_f = (const float*)d_in[4];
    const float* w_ih_b = (const float*)d_in[5];
    const float* w_hh_b = (const float*)d_in[6];
    const float* b_ih_b = (const float*)d_in[7];
    const float* b_hh_b = (const float*)d_in[8];
    const float* fc1_w  = (const float*)d_in[9];
    const float* fc1_b  = (const float*)d_in[10];
    const float* fc2_w  = (const float*)d_in[11];
    const float* fc2_b  = (const float*)d_in[12];
    float* out = (float*)d_out;

    const int smem_bytes = W4SIZE * 16 + 3 * 64 * 16 + 18 * 8;   // ~72.3 KB
    cudaFuncSetAttribute(gru_mma_kernel,
                         cudaFuncAttributeMaxDynamicSharedMemorySize, smem_bytes);
    gru_mma_kernel<<<128, 512, smem_bytes>>>(
        x, w_ih_f, w_hh_f, b_ih_f, b_hh_f,
        w_ih_b, w_hh_b, b_ih_b, b_hh_b, fc1_w, fc1_b, fc2_w, fc2_b, out);
}

// round 10
// speedup vs baseline: 6.5674x; 1.2599x over previous
#include <cuda_runtime.h>
#include <cstdint>

// Bidirectional GRU (B=32768, T=18, I=2, H=64) + fc1(128->24) + reshape + fc2(18->2)
// R10: fp16 two-product split (fp16 has 11 mantissa bits; only the weight-rounding
// residual is dropped -> ~1e-4 output error). Per tile: 2 HMMA (was 3), r+z weight
// pairs share one uint4 LDS.128. Everything else as R9.

#define RZSTRIDE 20            // uint4 per rz-row (16 used + 4 pad; 80 u32 = 16 mod 32)
#define NHSTRIDE 20            // uint2 per nh/fc1 row (16 used + 4 pad; 40 u32 = 8 mod 32)

// ---------- helpers ----------
__device__ __forceinline__ uint32_t pack_f16x2(float a, float b) {
    uint32_t r;
    asm("{.reg .f16 l, h; cvt.rn.f16.f32 l, %1; cvt.rn.f16.f32 h, %2; mov.b32 %0, {l, h};}"
        : "=r"(r) : "f"(a), "f"(b));
    return r;
}
__device__ __forceinline__ float2 unpack_f16x2(uint32_t u) {
    float a, b;
    asm("{.reg .f16 l, h; mov.b32 {l, h}, %2; cvt.f32.f16 %0, l; cvt.f32.f16 %1, h;}"
        : "=f"(a), "=f"(b) : "r"(u));
    return make_float2(a, b);
}

__device__ __forceinline__ float sigf(float x) {
    float e, r;
    asm("ex2.approx.f32 %0, %1;" : "=f"(e) : "f"(x * -1.4426950408889634f));
    asm("rcp.approx.f32 %0, %1;" : "=f"(r) : "f"(1.0f + e));
    return r;
}
__device__ __forceinline__ float tanhf2(float x) { return 2.0f * sigf(2.0f * x) - 1.0f; }

__device__ __forceinline__ void mma_f16(float& c0, float& c1, float& c2, float& c3,
                                        uint32_t a0, uint32_t a1, uint32_t a2, uint32_t a3,
                                        uint32_t b0, uint32_t b1) {
    asm volatile("mma.sync.aligned.m16n8k16.row.col.f32.f16.f16.f32 "
                 "{%0,%1,%2,%3}, {%4,%5,%6,%7}, {%8,%9}, {%0,%1,%2,%3};"
                 : "+f"(c0), "+f"(c1), "+f"(c2), "+f"(c3)
                 : "r"(a0), "r"(a1), "r"(a2), "r"(a3), "r"(b0), "r"(b1));
}

// r+z pair tile: one LDS.128 -> 4 HMMA (2 products each for r and z)
__device__ __forceinline__ void rz_mma(float cr[4], float cz[4], const uint4* p,
                                       const uint32_t ah[4], const uint32_t al[4]) {
    const uint4 w = *p;
    mma_f16(cr[0], cr[1], cr[2], cr[3], ah[0], ah[1], ah[2], ah[3], w.x, w.y);
    mma_f16(cr[0], cr[1], cr[2], cr[3], al[0], al[1], al[2], al[3], w.x, w.y);
    mma_f16(cz[0], cz[1], cz[2], cz[3], ah[0], ah[1], ah[2], ah[3], w.z, w.w);
    mma_f16(cz[0], cz[1], cz[2], cz[3], al[0], al[1], al[2], al[3], w.z, w.w);
}
// single tile: one LDS.64 -> 2 HMMA
__device__ __forceinline__ void one_mma(float c[4], const uint2* p,
                                        const uint32_t ah[4], const uint32_t al[4]) {
    const uint2 w = *p;
    mma_f16(c[0], c[1], c[2], c[3], ah[0], ah[1], ah[2], ah[3], w.x, w.y);
    mma_f16(c[0], c[1], c[2], c[3], al[0], al[1], al[2], al[3], w.x, w.y);
}

// ---------- fused kernel: 512 threads, grid 128 ----------
extern __shared__ uint32_t smem_u[];

__global__ __launch_bounds__(512)
void gru_mma_kernel(const float* __restrict__ x,
                    const float* __restrict__ w_ih_f, const float* __restrict__ w_hh_f,
                    const float* __restrict__ b_ih_f, const float* __restrict__ b_hh_f,
                    const float* __restrict__ w_ih_b, const float* __restrict__ w_hh_b,
                    const float* __restrict__ b_ih_b, const float* __restrict__ b_hh_b,
                    const float* __restrict__ fc1_w, const float* __restrict__ fc1_b,
                    const float* __restrict__ fc2_w, const float* __restrict__ fc2_b,
                    float* __restrict__ out) {
    uint4*  sRZ  = (uint4*)smem_u;                       // 64*RZSTRIDE uint4 (20 KB)
    uint2*  sNH  = (uint2*)(sRZ + 64 * RZSTRIDE);        // 64*NHSTRIDE uint2 (10 KB)
    uint2*  sF1  = sNH + 64 * NHSTRIDE;                  // 24*NHSTRIDE uint2 (3.75 KB)
    float4* gcR  = (float4*)(sF1 + 24 * NHSTRIDE);       // 64
    float4* gcZ  = gcR + 64;                             // 64
    float4* gcN  = gcZ + 64;                             // 64 {w0,w1,bih_n,bhh_n}
    float2* fc2p = (float2*)(gcN + 64);                  // 18 {w_row0[j], w_row1[j]}

    const int tid  = threadIdx.x;
    const int warp = tid >> 5;
    const int lane = tid & 31;
    const int qd   = lane & 3;
    const int row0 = blockIdx.x * 256 + warp * 16 + (lane >> 2);   // rows row0, row0+8
    // per-thread fragment base pointers (row_off = lane>>2, quad = lane&3)
    const uint4* sRZth = sRZ + (lane >> 2) * RZSTRIDE + qd;
    const uint2* sNHth = sNH + (lane >> 2) * NHSTRIDE + qd;
    const uint2* sF1th = sF1 + (lane >> 2) * NHSTRIDE + qd;

    if (tid < 18) fc2p[tid] = make_float2(fc2_w[tid], fc2_w[18 + tid]);

    // per-thread fixed fc1 column indices + biases
    const int kk0 = qd * 2;
    int kk[6] = {kk0, kk0 + 1, kk0 + 8, kk0 + 9, kk0 + 16, kk0 + 17};
    float fbv[6];
    #pragma unroll
    for (int j = 0; j < 6; j++) fbv[j] = __ldg(fc1_b + kk[j]);

    // fc2 accumulators (dynamic-indexed -> local mem), float2 granularity
    float2 a2r0[24], a2r8[24];
    #pragma unroll
    for (int m = 0; m < 24; m++) {
        a2r0[m] = make_float2(0.0f, 0.0f);
        a2r8[m] = make_float2(0.0f, 0.0f);
    }

    #pragma unroll 1
    for (int dir = 0; dir < 2; ++dir) {
        const float* wih = dir ? w_ih_b : w_ih_f;
        const float* whh = dir ? w_hh_b : w_hh_f;
        const float* bih = dir ? b_ih_b : b_ih_f;
        const float* bhh = dir ? b_hh_b : b_hh_f;

        __syncthreads();
        // ---- pack W' into smem (fp16, B-fragment layout) ----
        // RZ: uint4 {r.b0, r.b1, z.b0, z.b1} per (n-row, kt, quad)
        #pragma unroll 1
        for (int i = tid; i < 64 * 16; i += 512) {
            const int n   = i >> 4;
            const int rem = i & 15;
            const int kt  = rem >> 2, q = rem & 3;
            const int kA  = 2 * (q + 8 * kt);
            const int kB  = kA + 8;
            uint4 w;
            w.x = pack_f16x2(whh[n * 64 + kA],        whh[n * 64 + kA + 1]);
            w.y = pack_f16x2(whh[n * 64 + kB],        whh[n * 64 + kB + 1]);
            w.z = pack_f16x2(whh[(64 + n) * 64 + kA], whh[(64 + n) * 64 + kA + 1]);
            w.w = pack_f16x2(whh[(64 + n) * 64 + kB], whh[(64 + n) * 64 + kB + 1]);
            sRZ[n * RZSTRIDE + kt * 4 + q] = w;
        }
        // NH: uint2 per (n-row, kt, quad)
        #pragma unroll 1
        for (int i = tid; i < 64 * 16; i += 512) {
            const int n   = i >> 4;
            const int rem = i & 15;
            const int kt  = rem >> 2, q = rem & 3;
            const int kA  = 2 * (q + 8 * kt);
            const int kB  = kA + 8;
            uint2 w;
            w.x = pack_f16x2(whh[(128 + n) * 64 + kA], whh[(128 + n) * 64 + kA + 1]);
            w.y = pack_f16x2(whh[(128 + n) * 64 + kB], whh[(128 + n) * 64 + kB + 1]);
            sNH[n * NHSTRIDE + kt * 4 + q] = w;
        }
        // FC1: 24 rows
        #pragma unroll 1
        for (int i = tid; i < 24 * 16; i += 512) {
            const int n   = i >> 4;
            const int rem = i & 15;
            const int kt  = rem >> 2, q = rem & 3;
            const int kA  = 2 * (q + 8 * kt);
            const int kB  = kA + 8;
            const float* fr = fc1_w + n * 128 + 64 * dir;
            uint2 w;
            w.x = pack_f16x2(fr[kA], fr[kA + 1]);
            w.y = pack_f16x2(fr[kB], fr[kB + 1]);
            sF1[n * NHSTRIDE + kt * 4 + q] = w;
        }
        // ---- per-column gate constant tables ----
        if (tid < 64) {
            const int c = tid;
            gcR[c] = make_float4(wih[2*c],       wih[2*c+1],       bih[c] + bhh[c], 0.0f);
            gcZ[c] = make_float4(wih[2*(64+c)],  wih[2*(64+c)+1],  bih[64+c] + bhh[64+c], 0.0f);
            gcN[c] = make_float4(wih[2*(128+c)], wih[2*(128+c)+1], bih[128+c], bhh[128+c]);
        }
        __syncthreads();

        float    hprev[8][4];
        uint32_t Ahi[4][4], Alo[4][4];
        #pragma unroll
        for (int g = 0; g < 8; g++)
            #pragma unroll
            for (int i = 0; i < 4; i++) hprev[g][i] = 0.0f;
        #pragma unroll
        for (int kt = 0; kt < 4; kt++)
            #pragma unroll
            for (int i = 0; i < 4; i++) { Ahi[kt][i] = 0u; Alo[kt][i] = 0u; }

        #pragma unroll 1
        for (int s = 0; s < 19; ++s) {
            const int t = dir ? (17 - s) : s;

            if (s < 18) {
                const float2 xa = *(const float2*)(x + (size_t)row0 * 36 + t * 2);
                const float2 xb = *(const float2*)(x + (size_t)(row0 + 8) * 36 + t * 2);
                uint32_t Anh[4][4], Anl[4][4];

                #pragma unroll
                for (int g = 0; g < 8; g++) {
                    const int c0 = g * 8 + qd * 2;
                    const float4 r0 = gcR[c0], r1 = gcR[c0 + 1];
                    const float4 z0 = gcZ[c0], z1 = gcZ[c0 + 1];
                    const float4 n0 = gcN[c0], n1 = gcN[c0 + 1];
                    float aR[4], aZ[4], aN[4];
                    aR[0] = r0.z + xa.x * r0.x + xa.y * r0.y;
                    aR[1] = r1.z + xa.x * r1.x + xa.y * r1.y;
                    aR[2] = r0.z + xb.x * r0.x + xb.y * r0.y;
                    aR[3] = r1.z + xb.x * r1.x + xb.y * r1.y;
                    aZ[0] = z0.z + xa.x * z0.x + xa.y * z0.y;
                    aZ[1] = z1.z + xa.x * z1.x + xa.y * z1.y;
                    aZ[2] = z0.z + xb.x * z0.x + xb.y * z0.y;
                    aZ[3] = z1.z + xb.x * z1.x + xb.y * z1.y;
                    aN[0] = n0.z + xa.x * n0.x + xa.y * n0.y;
                    aN[1] = n1.z + xa.x * n1.x + xa.y * n1.y;
                    aN[2] = n0.z + xb.x * n0.x + xb.y * n0.y;
                    aN[3] = n1.z + xb.x * n1.x + xb.y * n1.y;

                    float cr[4] = {0,0,0,0}, cz[4] = {0,0,0,0}, ch[4] = {0,0,0,0};
                    if (s > 0) {
                        #pragma unroll
                        for (int kt = 0; kt < 4; kt++)
                            rz_mma(cr, cz, sRZth + g * (8 * RZSTRIDE) + kt * 4,
                                   Ahi[kt], Alo[kt]);
                        #pragma unroll
                        for (int kt = 0; kt < 4; kt++)
                            one_mma(ch, sNHth + g * (8 * NHSTRIDE) + kt * 4,
                                    Ahi[kt], Alo[kt]);
                    }
                    #pragma unroll
                    for (int i = 0; i < 4; i++) {
                        const float bnhh = (i & 1) ? n1.w : n0.w;
                        const float r = sigf(cr[i] + aR[i]);
                        const float z = sigf(cz[i] + aZ[i]);
                        const float n = tanhf2(aN[i] + r * (ch[i] + bnhh));
                        hprev[g][i] = n + z * (hprev[g][i] - n);
                    }
                    // pack h_new into next-step A fragments (fp16 hi + residual lo)
                    const uint32_t ph01 = pack_f16x2(hprev[g][0], hprev[g][1]);
                    const float2   b01  = unpack_f16x2(ph01);
                    const uint32_t pl01 = pack_f16x2(hprev[g][0] - b01.x, hprev[g][1] - b01.y);
                    const uint32_t ph23 = pack_f16x2(hprev[g][2], hprev[g][3]);
                    const float2   b23  = unpack_f16x2(ph23);
                    const uint32_t pl23 = pack_f16x2(hprev[g][2] - b23.x, hprev[g][3] - b23.y);
                    if ((g & 1) == 0) {
                        Anh[g >> 1][0] = ph01; Anh[g >> 1][1] = ph23;
                        Anl[g >> 1][0] = pl01; Anl[g >> 1][1] = pl23;
                    } else {
                        Anh[g >> 1][2] = ph01; Anh[g >> 1][3] = ph23;
                        Anl[g >> 1][2] = pl01; Anl[g >> 1][3] = pl23;
                    }
                }

                // ---- fc1 tiles on h_{s-1} + fused fc2 scatter ----
                if (s >= 1) {
                    float f0[4] = {0,0,0,0}, f1[4] = {0,0,0,0}, f2[4] = {0,0,0,0};
                    #pragma unroll
                    for (int kt = 0; kt < 4; kt++) {
                        one_mma(f0, sF1th + 0 * (8 * NHSTRIDE) + kt * 4, Ahi[kt], Alo[kt]);
                        one_mma(f1, sF1th + 1 * (8 * NHSTRIDE) + kt * 4, Ahi[kt], Alo[kt]);
                        one_mma(f2, sF1th + 2 * (8 * NHSTRIDE) + kt * 4, Ahi[kt], Alo[kt]);
                    }
                    const int tf = dir ? (18 - s) : (s - 1);
                    const float vv0[6] = {f0[0], f0[1], f1[0], f1[1], f2[0], f2[1]};
                    const float vv8[6] = {f0[2], f0[3], f1[2], f1[3], f2[2], f2[3]};
                    #pragma unroll
                    for (int j = 0; j < 6; j++) {
                        const int n_ = tf * 24 + kk[j];
                        const int rr = n_ / 18;
                        const int jj = n_ - rr * 18;
                        const float2 w2 = fc2p[jj];
                        const float fb = dir ? 0.0f : fbv[j];
                        const float va = vv0[j] + fb;
                        const float vb = vv8[j] + fb;
                        float2 c0 = a2r0[rr];
                        c0.x += va * w2.x; c0.y += va * w2.y;
                        a2r0[rr] = c0;
                        float2 c8 = a2r8[rr];
                        c8.x += vb * w2.x; c8.y += vb * w2.y;
                        a2r8[rr] = c8;
                    }
                }

                #pragma unroll
                for (int kt = 0; kt < 4; kt++)
                    #pragma unroll
                    for (int i = 0; i < 4; i++) { Ahi[kt][i] = Anh[kt][i]; Alo[kt][i] = Anl[kt][i]; }
            } else {
                // ---- s=18: fc1 on h_17 + fused fc2 scatter ----
                float f0[4] = {0,0,0,0}, f1[4] = {0,0,0,0}, f2[4] = {0,0,0,0};
                #pragma unroll
                for (int kt = 0; kt < 4; kt++) {
                    one_mma(f0, sF1th + 0 * (8 * NHSTRIDE) + kt * 4, Ahi[kt], Alo[kt]);
                    one_mma(f1, sF1th + 1 * (8 * NHSTRIDE) + kt * 4, Ahi[kt], Alo[kt]);
                    one_mma(f2, sF1th + 2 * (8 * NHSTRIDE) + kt * 4, Ahi[kt], Alo[kt]);
                }
                const int tf = dir ? 0 : 17;
                const float vv0[6] = {f0[0], f0[1], f1[0], f1[1], f2[0], f2[1]};
                const float vv8[6] = {f0[2], f0[3], f1[2], f1[3], f2[2], f2[3]};
                #pragma unroll
                for (int j = 0; j < 6; j++) {
                    const int n_ = tf * 24 + kk[j];
                    const int rr = n_ / 18;
                    const int jj = n_ - rr * 18;
                    const float2 w2 = fc2p[jj];
                    const float fb = dir ? 0.0f : fbv[j];
                    const float va = vv0[j] + fb;
                    const float vb = vv8[j] + fb;
                    float2 c0 = a2r0[rr];
                    c0.x += va * w2.x; c0.y += va * w2.y;
                    a2r0[rr] = c0;
                    float2 c8 = a2r8[rr];
                    c8.x += vb * w2.x; c8.y += vb * w2.y;
                    a2r8[rr] = c8;
                }
            }
        }
    }

    // ---- quad reduce + write (qd==0 lane per row) ----
    const float b0v = __ldg(fc2_b), b1v = __ldg(fc2_b + 1);
    float* o0 = out + (size_t)row0 * 48;
    float* o8 = out + (size_t)(row0 + 8) * 48;
    #pragma unroll
    for (int p = 0; p < 24; p++) {
        float2 v0 = a2r0[p];
        v0.x += __shfl_xor_sync(0xffffffffu, v0.x, 1);
        v0.x += __shfl_xor_sync(0xffffffffu, v0.x, 2);
        v0.y += __shfl_xor_sync(0xffffffffu, v0.y, 1);
        v0.y += __shfl_xor_sync(0xffffffffu, v0.y, 2);
        float2 v8 = a2r8[p];
        v8.x += __shfl_xor_sync(0xffffffffu, v8.x, 1);
        v8.x += __shfl_xor_sync(0xffffffffu, v8.x, 2);
        v8.y += __shfl_xor_sync(0xffffffffu, v8.y, 1);
        v8.y += __shfl_xor_sync(0xffffffffu, v8.y, 2);
        if (qd == 0) {
            o0[2*p]     = v0.x + b0v;
            o0[2*p + 1] = v0.y + b1v;
            o8[2*p]     = v8.x + b0v;
            o8[2*p + 1] = v8.y + b1v;
        }
    }
}

extern "C" void kernel_launch(void* const* d_in, const int* in_sizes, int n_in,
                              void* d_out, int out_size)
{
    const float* x      = (const float*)d_in[0];
    const float* w_ih_f = (const float*)d_in[1];
    const float* w_hh_f = (const float*)d_in[2];
    const float* b_ih_f = (const float*)d_in[3];
    const float* b_hh_f = (const float*)d_in[4];
    const float* w_ih_b = (const float*)d_in[5];
    const float* w_hh_b = (const float*)d_in[6];
    const float* b_ih_b = (const float*)d_in[7];
    const float* b_hh_b = (const float*)d_in[8];
    const float* fc1_w  = (const float*)d_in[9];
    const float* fc1_b  = (const float*)d_in[10];
    const float* fc2_w  = (const float*)d_in[11];
    const float* fc2_b  = (const float*)d_in[12];
    float* out = (float*)d_out;

    const int smem_bytes = 64 * RZSTRIDE * 16        // sRZ
                         + 64 * NHSTRIDE * 8         // sNH
                         + 24 * NHSTRIDE * 8         // sF1
                         + 3 * 64 * 16               // gc tables
                         + 18 * 8;                   // fc2p
    cudaFuncSetAttribute(gru_mma_kernel,
                         cudaFuncAttributeMaxDynamicSharedMemorySize, smem_bytes);
    gru_mma_kernel<<<128, 512, smem_bytes>>>(
        x, w_ih_f, w_hh_f, b_ih_f, b_hh_f,
        w_ih_b, w_hh_b, b_ih_b, b_hh_b, fc1_w, fc1_b, fc2_w, fc2_b, out);
}

// round 11
// speedup vs baseline: 9.1571x; 1.3943x over previous
#include <cuda_runtime.h>
#include <cstdint>

// Bidirectional GRU (B=32768, T=18, I=2, H=64) + fc1(128->24) + reshape + fc2(18->2)
// R11: single-product fp16 (both h and W fp16-rounded; ~2e-4 output error).
// Per rz tile: 2 HMMA, per nh/fc1 tile: 1 HMMA. No residual fragments.

#define RZSTRIDE 20            // uint4 per rz-row (16 used + 4 pad)
#define NHSTRIDE 20            // uint2 per nh/fc1 row (16 used + 4 pad)

// ---------- helpers ----------
__device__ __forceinline__ uint32_t pack_f16x2(float a, float b) {
    uint32_t r;
    asm("{.reg .f16 l, h; cvt.rn.f16.f32 l, %1; cvt.rn.f16.f32 h, %2; mov.b32 %0, {l, h};}"
        : "=r"(r) : "f"(a), "f"(b));
    return r;
}

__device__ __forceinline__ float sigf(float x) {
    float e, r;
    asm("ex2.approx.f32 %0, %1;" : "=f"(e) : "f"(x * -1.4426950408889634f));
    asm("rcp.approx.f32 %0, %1;" : "=f"(r) : "f"(1.0f + e));
    return r;
}
__device__ __forceinline__ float tanhf2(float x) { return 2.0f * sigf(2.0f * x) - 1.0f; }

__device__ __forceinline__ void mma_f16(float& c0, float& c1, float& c2, float& c3,
                                        uint32_t a0, uint32_t a1, uint32_t a2, uint32_t a3,
                                        uint32_t b0, uint32_t b1) {
    asm volatile("mma.sync.aligned.m16n8k16.row.col.f32.f16.f16.f32 "
                 "{%0,%1,%2,%3}, {%4,%5,%6,%7}, {%8,%9}, {%0,%1,%2,%3};"
                 : "+f"(c0), "+f"(c1), "+f"(c2), "+f"(c3)
                 : "r"(a0), "r"(a1), "r"(a2), "r"(a3), "r"(b0), "r"(b1));
}

// r+z pair tile: one LDS.128 -> 2 HMMA
__device__ __forceinline__ void rz_mma(float cr[4], float cz[4], const uint4* p,
                                       const uint32_t ah[4]) {
    const uint4 w = *p;
    mma_f16(cr[0], cr[1], cr[2], cr[3], ah[0], ah[1], ah[2], ah[3], w.x, w.y);
    mma_f16(cz[0], cz[1], cz[2], cz[3], ah[0], ah[1], ah[2], ah[3], w.z, w.w);
}
// single tile: one LDS.64 -> 1 HMMA
__device__ __forceinline__ void one_mma(float c[4], const uint2* p,
                                        const uint32_t ah[4]) {
    const uint2 w = *p;
    mma_f16(c[0], c[1], c[2], c[3], ah[0], ah[1], ah[2], ah[3], w.x, w.y);
}

// ---------- fused kernel: 512 threads, grid 128 ----------
extern __shared__ uint32_t smem_u[];

__global__ __launch_bounds__(512)
void gru_mma_kernel(const float* __restrict__ x,
                    const float* __restrict__ w_ih_f, const float* __restrict__ w_hh_f,
                    const float* __restrict__ b_ih_f, const float* __restrict__ b_hh_f,
                    const float* __restrict__ w_ih_b, const float* __restrict__ w_hh_b,
                    const float* __restrict__ b_ih_b, const float* __restrict__ b_hh_b,
                    const float* __restrict__ fc1_w, const float* __restrict__ fc1_b,
                    const float* __restrict__ fc2_w, const float* __restrict__ fc2_b,
                    float* __restrict__ out) {
    uint4*  sRZ  = (uint4*)smem_u;                       // 64*RZSTRIDE uint4 (20 KB)
    uint2*  sNH  = (uint2*)(sRZ + 64 * RZSTRIDE);        // 64*NHSTRIDE uint2 (10 KB)
    uint2*  sF1  = sNH + 64 * NHSTRIDE;                  // 24*NHSTRIDE uint2 (3.75 KB)
    float4* gcR  = (float4*)(sF1 + 24 * NHSTRIDE);       // 64
    float4* gcZ  = gcR + 64;                             // 64
    float4* gcN  = gcZ + 64;                             // 64 {w0,w1,bih_n,bhh_n}
    float2* fc2p = (float2*)(gcN + 64);                  // 18 {w_row0[j], w_row1[j]}

    const int tid  = threadIdx.x;
    const int warp = tid >> 5;
    const int lane = tid & 31;
    const int qd   = lane & 3;
    const int row0 = blockIdx.x * 256 + warp * 16 + (lane >> 2);   // rows row0, row0+8
    const uint4* sRZth = sRZ + (lane >> 2) * RZSTRIDE + qd;
    const uint2* sNHth = sNH + (lane >> 2) * NHSTRIDE + qd;
    const uint2* sF1th = sF1 + (lane >> 2) * NHSTRIDE + qd;

    if (tid < 18) fc2p[tid] = make_float2(fc2_w[tid], fc2_w[18 + tid]);

    // per-thread fixed fc1 column indices + biases
    const int kk0 = qd * 2;
    int kk[6] = {kk0, kk0 + 1, kk0 + 8, kk0 + 9, kk0 + 16, kk0 + 17};
    float fbv[6];
    #pragma unroll
    for (int j = 0; j < 6; j++) fbv[j] = __ldg(fc1_b + kk[j]);

    // fc2 accumulators (dynamic-indexed -> local mem), float2 granularity
    float2 a2r0[24], a2r8[24];
    #pragma unroll
    for (int m = 0; m < 24; m++) {
        a2r0[m] = make_float2(0.0f, 0.0f);
        a2r8[m] = make_float2(0.0f, 0.0f);
    }

    #pragma unroll 1
    for (int dir = 0; dir < 2; ++dir) {
        const float* wih = dir ? w_ih_b : w_ih_f;
        const float* whh = dir ? w_hh_b : w_hh_f;
        const float* bih = dir ? b_ih_b : b_ih_f;
        const float* bhh = dir ? b_hh_b : b_hh_f;

        __syncthreads();
        // ---- pack W' into smem (fp16, B-fragment layout) ----
        #pragma unroll 1
        for (int i = tid; i < 64 * 16; i += 512) {
            const int n   = i >> 4;
            const int rem = i & 15;
            const int kt  = rem >> 2, q = rem & 3;
            const int kA  = 2 * (q + 8 * kt);
            const int kB  = kA + 8;
            uint4 w;
            w.x = pack_f16x2(whh[n * 64 + kA],        whh[n * 64 + kA + 1]);
            w.y = pack_f16x2(whh[n * 64 + kB],        whh[n * 64 + kB + 1]);
            w.z = pack_f16x2(whh[(64 + n) * 64 + kA], whh[(64 + n) * 64 + kA + 1]);
            w.w = pack_f16x2(whh[(64 + n) * 64 + kB], whh[(64 + n) * 64 + kB + 1]);
            sRZ[n * RZSTRIDE + kt * 4 + q] = w;

            uint2 v;
            v.x = pack_f16x2(whh[(128 + n) * 64 + kA], whh[(128 + n) * 64 + kA + 1]);
            v.y = pack_f16x2(whh[(128 + n) * 64 + kB], whh[(128 + n) * 64 + kB + 1]);
            sNH[n * NHSTRIDE + kt * 4 + q] = v;
        }
        #pragma unroll 1
        for (int i = tid; i < 24 * 16; i += 512) {
            const int n   = i >> 4;
            const int rem = i & 15;
            const int kt  = rem >> 2, q = rem & 3;
            const int kA  = 2 * (q + 8 * kt);
            const int kB  = kA + 8;
            const float* fr = fc1_w + n * 128 + 64 * dir;
            uint2 w;
            w.x = pack_f16x2(fr[kA], fr[kA + 1]);
            w.y = pack_f16x2(fr[kB], fr[kB + 1]);
            sF1[n * NHSTRIDE + kt * 4 + q] = w;
        }
        // ---- per-column gate constant tables ----
        if (tid < 64) {
            const int c = tid;
            gcR[c] = make_float4(wih[2*c],       wih[2*c+1],       bih[c] + bhh[c], 0.0f);
            gcZ[c] = make_float4(wih[2*(64+c)],  wih[2*(64+c)+1],  bih[64+c] + bhh[64+c], 0.0f);
            gcN[c] = make_float4(wih[2*(128+c)], wih[2*(128+c)+1], bih[128+c], bhh[128+c]);
        }
        __syncthreads();

        float    hprev[8][4];
        uint32_t Ahi[4][4];
        #pragma unroll
        for (int g = 0; g < 8; g++)
            #pragma unroll
            for (int i = 0; i < 4; i++) hprev[g][i] = 0.0f;
        #pragma unroll
        for (int kt = 0; kt < 4; kt++)
            #pragma unroll
            for (int i = 0; i < 4; i++) Ahi[kt][i] = 0u;

        #pragma unroll 1
        for (int s = 0; s < 19; ++s) {
            const int t = dir ? (17 - s) : s;

            if (s < 18) {
                const float2 xa = *(const float2*)(x + (size_t)row0 * 36 + t * 2);
                const float2 xb = *(const float2*)(x + (size_t)(row0 + 8) * 36 + t * 2);
                uint32_t Anh[4][4];

                #pragma unroll
                for (int g = 0; g < 8; g++) {
                    const int c0 = g * 8 + qd * 2;
                    const float4 r0 = gcR[c0], r1 = gcR[c0 + 1];
                    const float4 z0 = gcZ[c0], z1 = gcZ[c0 + 1];
                    const float4 n0 = gcN[c0], n1 = gcN[c0 + 1];
                    float aR[4], aZ[4], aN[4];
                    aR[0] = r0.z + xa.x * r0.x + xa.y * r0.y;
                    aR[1] = r1.z + xa.x * r1.x + xa.y * r1.y;
                    aR[2] = r0.z + xb.x * r0.x + xb.y * r0.y;
                    aR[3] = r1.z + xb.x * r1.x + xb.y * r1.y;
                    aZ[0] = z0.z + xa.x * z0.x + xa.y * z0.y;
                    aZ[1] = z1.z + xa.x * z1.x + xa.y * z1.y;
                    aZ[2] = z0.z + xb.x * z0.x + xb.y * z0.y;
                    aZ[3] = z1.z + xb.x * z1.x + xb.y * z1.y;
                    aN[0] = n0.z + xa.x * n0.x + xa.y * n0.y;
                    aN[1] = n1.z + xa.x * n1.x + xa.y * n1.y;
                    aN[2] = n0.z + xb.x * n0.x + xb.y * n0.y;
                    aN[3] = n1.z + xb.x * n1.x + xb.y * n1.y;

                    float cr[4] = {0,0,0,0}, cz[4] = {0,0,0,0}, ch[4] = {0,0,0,0};
                    if (s > 0) {
                        #pragma unroll
                        for (int kt = 0; kt < 4; kt++)
                            rz_mma(cr, cz, sRZth + g * (8 * RZSTRIDE) + kt * 4, Ahi[kt]);
                        #pragma unroll
                        for (int kt = 0; kt < 4; kt++)
                            one_mma(ch, sNHth + g * (8 * NHSTRIDE) + kt * 4, Ahi[kt]);
                    }
                    #pragma unroll
                    for (int i = 0; i < 4; i++) {
                        const float bnhh = (i & 1) ? n1.w : n0.w;
                        const float r = sigf(cr[i] + aR[i]);
                        const float z = sigf(cz[i] + aZ[i]);
                        const float n = tanhf2(aN[i] + r * (ch[i] + bnhh));
                        hprev[g][i] = n + z * (hprev[g][i] - n);
                    }
                    // pack h_new into next-step A fragments (fp16, single product)
                    const uint32_t ph01 = pack_f16x2(hprev[g][0], hprev[g][1]);
                    const uint32_t ph23 = pack_f16x2(hprev[g][2], hprev[g][3]);
                    if ((g & 1) == 0) {
                        Anh[g >> 1][0] = ph01; Anh[g >> 1][1] = ph23;
                    } else {
                        Anh[g >> 1][2] = ph01; Anh[g >> 1][3] = ph23;
                    }
                }

                // ---- fc1 tiles on h_{s-1} + fused fc2 scatter ----
                if (s >= 1) {
                    float f0[4] = {0,0,0,0}, f1[4] = {0,0,0,0}, f2[4] = {0,0,0,0};
                    #pragma unroll
                    for (int kt = 0; kt < 4; kt++) {
                        one_mma(f0, sF1th + 0 * (8 * NHSTRIDE) + kt * 4, Ahi[kt]);
                        one_mma(f1, sF1th + 1 * (8 * NHSTRIDE) + kt * 4, Ahi[kt]);
                        one_mma(f2, sF1th + 2 * (8 * NHSTRIDE) + kt * 4, Ahi[kt]);
                    }
                    const int tf = dir ? (18 - s) : (s - 1);
                    const float vv0[6] = {f0[0], f0[1], f1[0], f1[1], f2[0], f2[1]};
                    const float vv8[6] = {f0[2], f0[3], f1[2], f1[3], f2[2], f2[3]};
                    #pragma unroll
                    for (int j = 0; j < 6; j++) {
                        const int n_ = tf * 24 + kk[j];
                        const int rr = n_ / 18;
                        const int jj = n_ - rr * 18;
                        const float2 w2 = fc2p[jj];
                        const float fb = dir ? 0.0f : fbv[j];
                        const float va = vv0[j] + fb;
                        const float vb = vv8[j] + fb;
                        float2 c0 = a2r0[rr];
                        c0.x += va * w2.x; c0.y += va * w2.y;
                        a2r0[rr] = c0;
                        float2 c8 = a2r8[rr];
                        c8.x += vb * w2.x; c8.y += vb * w2.y;
                        a2r8[rr] = c8;
                    }
                }

                #pragma unroll
                for (int kt = 0; kt < 4; kt++)
                    #pragma unroll
                    for (int i = 0; i < 4; i++) Ahi[kt][i] = Anh[kt][i];
            } else {
                // ---- s=18: fc1 on h_17 + fused fc2 scatter ----
                float f0[4] = {0,0,0,0}, f1[4] = {0,0,0,0}, f2[4] = {0,0,0,0};
                #pragma unroll
                for (int kt = 0; kt < 4; kt++) {
                    one_mma(f0, sF1th + 0 * (8 * NHSTRIDE) + kt * 4, Ahi[kt]);
                    one_mma(f1, sF1th + 1 * (8 * NHSTRIDE) + kt * 4, Ahi[kt]);
                    one_mma(f2, sF1th + 2 * (8 * NHSTRIDE) + kt * 4, Ahi[kt]);
                }
                const int tf = dir ? 0 : 17;
                const float vv0[6] = {f0[0], f0[1], f1[0], f1[1], f2[0], f2[1]};
                const float vv8[6] = {f0[2], f0[3], f1[2], f1[3], f2[2], f2[3]};
                #pragma unroll
                for (int j = 0; j < 6; j++) {
                    const int n_ = tf * 24 + kk[j];
                    const int rr = n_ / 18;
                    const int jj = n_ - rr * 18;
                    const float2 w2 = fc2p[jj];
                    const float fb = dir ? 0.0f : fbv[j];
                    const float va = vv0[j] + fb;
                    const float vb = vv8[j] + fb;
                    float2 c0 = a2r0[rr];
                    c0.x += va * w2.x; c0.y += va * w2.y;
                    a2r0[rr] = c0;
                    float2 c8 = a2r8[rr];
                    c8.x += vb * w2.x; c8.y += vb * w2.y;
                    a2r8[rr] = c8;
                }
            }
        }
    }

    // ---- quad reduce + write (qd==0 lane per row) ----
    const float b0v = __ldg(fc2_b), b1v = __ldg(fc2_b + 1);
    float* o0 = out + (size_t)row0 * 48;
    float* o8 = out + (size_t)(row0 + 8) * 48;
    #pragma unroll
    for (int p = 0; p < 24; p++) {
        float2 v0 = a2r0[p];
        v0.x += __shfl_xor_sync(0xffffffffu, v0.x, 1);
        v0.x += __shfl_xor_sync(0xffffffffu, v0.x, 2);
        v0.y += __shfl_xor_sync(0xffffffffu, v0.y, 1);
        v0.y += __shfl_xor_sync(0xffffffffu, v0.y, 2);
        float2 v8 = a2r8[p];
        v8.x += __shfl_xor_sync(0xffffffffu, v8.x, 1);
        v8.x += __shfl_xor_sync(0xffffffffu, v8.x, 2);
        v8.y += __shfl_xor_sync(0xffffffffu, v8.y, 1);
        v8.y += __shfl_xor_sync(0xffffffffu, v8.y, 2);
        if (qd == 0) {
            o0[2*p]     = v0.x + b0v;
            o0[2*p + 1] = v0.y + b1v;
            o8[2*p]     = v8.x + b0v;
            o8[2*p + 1] = v8.y + b1v;
        }
    }
}

extern "C" void kernel_launch(void* const* d_in, const int* in_sizes, int n_in,
                              void* d_out, int out_size)
{
    const float* x      = (const float*)d_in[0];
    const float* w_ih_f = (const float*)d_in[1];
    const float* w_hh_f = (const float*)d_in[2];
    const float* b_ih_f = (const float*)d_in[3];
    const float* b_hh_f = (const float*)d_in[4];
    const float* w_ih_b = (const float*)d_in[5];
    const float* w_hh_b = (const float*)d_in[6];
    const float* b_ih_b = (const float*)d_in[7];
    const float* b_hh_b = (const float*)d_in[8];
    const float* fc1_w  = (const float*)d_in[9];
    const float* fc1_b  = (const float*)d_in[10];
    const float* fc2_w  = (const float*)d_in[11];
    const float* fc2_b  = (const float*)d_in[12];
    float* out = (float*)d_out;

    const int smem_bytes = 64 * RZSTRIDE * 16        // sRZ
                         + 64 * NHSTRIDE * 8         // sNH
                         + 24 * NHSTRIDE * 8         // sF1
                         + 3 * 64 * 16               // gc tables
                         + 18 * 8;                   // fc2p
    cudaFuncSetAttribute(gru_mma_kernel,
                         cudaFuncAttributeMaxDynamicSharedMemorySize, smem_bytes);
    gru_mma_kernel<<<128, 512, smem_bytes>>>(
        x, w_ih_f, w_hh_f, b_ih_f, b_hh_f,
        w_ih_b, w_hh_b, b_ih_b, b_hh_b, fc1_w, fc1_b, fc2_w, fc2_b, out);
}

// round 12
// speedup vs baseline: 11.5939x; 1.2661x over previous
#include <cuda_runtime.h>
#include <cstdint>

// Bidirectional GRU (B=32768, T=18, I=2, H=64) + fc1(128->24) + reshape + fc2(18->2)
// R12: R11 + hardware MUFU.TANH for all gate nonlinearities:
//   tanh(x) -> tanh.approx.f32 ; sigmoid(x) = 0.5 + 0.5*tanh(0.5x)
// MUFU per gate element: 6 -> 3; shorter dependency chains.

#define RZSTRIDE 20            // uint4 per rz-row (16 used + 4 pad)
#define NHSTRIDE 20            // uint2 per nh/fc1 row (16 used + 4 pad)

// ---------- helpers ----------
__device__ __forceinline__ uint32_t pack_f16x2(float a, float b) {
    uint32_t r;
    asm("{.reg .f16 l, h; cvt.rn.f16.f32 l, %1; cvt.rn.f16.f32 h, %2; mov.b32 %0, {l, h};}"
        : "=r"(r) : "f"(a), "f"(b));
    return r;
}

__device__ __forceinline__ float tanh_hw(float x) {
    float r;
    asm("tanh.approx.f32 %0, %1;" : "=f"(r) : "f"(x));
    return r;
}
__device__ __forceinline__ float sig_hw(float x) {
    return fmaf(0.5f, tanh_hw(0.5f * x), 0.5f);
}

__device__ __forceinline__ void mma_f16(float& c0, float& c1, float& c2, float& c3,
                                        uint32_t a0, uint32_t a1, uint32_t a2, uint32_t a3,
                                        uint32_t b0, uint32_t b1) {
    asm volatile("mma.sync.aligned.m16n8k16.row.col.f32.f16.f16.f32 "
                 "{%0,%1,%2,%3}, {%4,%5,%6,%7}, {%8,%9}, {%0,%1,%2,%3};"
                 : "+f"(c0), "+f"(c1), "+f"(c2), "+f"(c3)
                 : "r"(a0), "r"(a1), "r"(a2), "r"(a3), "r"(b0), "r"(b1));
}

// r+z pair tile: one LDS.128 -> 2 HMMA
__device__ __forceinline__ void rz_mma(float cr[4], float cz[4], const uint4* p,
                                       const uint32_t ah[4]) {
    const uint4 w = *p;
    mma_f16(cr[0], cr[1], cr[2], cr[3], ah[0], ah[1], ah[2], ah[3], w.x, w.y);
    mma_f16(cz[0], cz[1], cz[2], cz[3], ah[0], ah[1], ah[2], ah[3], w.z, w.w);
}
// single tile: one LDS.64 -> 1 HMMA
__device__ __forceinline__ void one_mma(float c[4], const uint2* p,
                                        const uint32_t ah[4]) {
    const uint2 w = *p;
    mma_f16(c[0], c[1], c[2], c[3], ah[0], ah[1], ah[2], ah[3], w.x, w.y);
}

// ---------- fused kernel: 512 threads, grid 128 ----------
extern __shared__ uint32_t smem_u[];

__global__ __launch_bounds__(512)
void gru_mma_kernel(const float* __restrict__ x,
                    const float* __restrict__ w_ih_f, const float* __restrict__ w_hh_f,
                    const float* __restrict__ b_ih_f, const float* __restrict__ b_hh_f,
                    const float* __restrict__ w_ih_b, const float* __restrict__ w_hh_b,
                    const float* __restrict__ b_ih_b, const float* __restrict__ b_hh_b,
                    const float* __restrict__ fc1_w, const float* __restrict__ fc1_b,
                    const float* __restrict__ fc2_w, const float* __restrict__ fc2_b,
                    float* __restrict__ out) {
    uint4*  sRZ  = (uint4*)smem_u;                       // 64*RZSTRIDE uint4 (20 KB)
    uint2*  sNH  = (uint2*)(sRZ + 64 * RZSTRIDE);        // 64*NHSTRIDE uint2 (10 KB)
    uint2*  sF1  = sNH + 64 * NHSTRIDE;                  // 24*NHSTRIDE uint2 (3.75 KB)
    float4* gcR  = (float4*)(sF1 + 24 * NHSTRIDE);       // 64
    float4* gcZ  = gcR + 64;                             // 64
    float4* gcN  = gcZ + 64;                             // 64 {w0,w1,bih_n,bhh_n}
    float2* fc2p = (float2*)(gcN + 64);                  // 18 {w_row0[j], w_row1[j]}

    const int tid  = threadIdx.x;
    const int warp = tid >> 5;
    const int lane = tid & 31;
    const int qd   = lane & 3;
    const int row0 = blockIdx.x * 256 + warp * 16 + (lane >> 2);   // rows row0, row0+8
    const uint4* sRZth = sRZ + (lane >> 2) * RZSTRIDE + qd;
    const uint2* sNHth = sNH + (lane >> 2) * NHSTRIDE + qd;
    const uint2* sF1th = sF1 + (lane >> 2) * NHSTRIDE + qd;

    if (tid < 18) fc2p[tid] = make_float2(fc2_w[tid], fc2_w[18 + tid]);

    // per-thread fixed fc1 column indices + biases
    const int kk0 = qd * 2;
    int kk[6] = {kk0, kk0 + 1, kk0 + 8, kk0 + 9, kk0 + 16, kk0 + 17};
    float fbv[6];
    #pragma unroll
    for (int j = 0; j < 6; j++) fbv[j] = __ldg(fc1_b + kk[j]);

    // fc2 accumulators (dynamic-indexed -> local mem), float2 granularity
    float2 a2r0[24], a2r8[24];
    #pragma unroll
    for (int m = 0; m < 24; m++) {
        a2r0[m] = make_float2(0.0f, 0.0f);
        a2r8[m] = make_float2(0.0f, 0.0f);
    }

    #pragma unroll 1
    for (int dir = 0; dir < 2; ++dir) {
        const float* wih = dir ? w_ih_b : w_ih_f;
        const float* whh = dir ? w_hh_b : w_hh_f;
        const float* bih = dir ? b_ih_b : b_ih_f;
        const float* bhh = dir ? b_hh_b : b_hh_f;

        __syncthreads();
        // ---- pack W' into smem (fp16, B-fragment layout) ----
        #pragma unroll 1
        for (int i = tid; i < 64 * 16; i += 512) {
            const int n   = i >> 4;
            const int rem = i & 15;
            const int kt  = rem >> 2, q = rem & 3;
            const int kA  = 2 * (q + 8 * kt);
            const int kB  = kA + 8;
            uint4 w;
            w.x = pack_f16x2(whh[n * 64 + kA],        whh[n * 64 + kA + 1]);
            w.y = pack_f16x2(whh[n * 64 + kB],        whh[n * 64 + kB + 1]);
            w.z = pack_f16x2(whh[(64 + n) * 64 + kA], whh[(64 + n) * 64 + kA + 1]);
            w.w = pack_f16x2(whh[(64 + n) * 64 + kB], whh[(64 + n) * 64 + kB + 1]);
            sRZ[n * RZSTRIDE + kt * 4 + q] = w;

            uint2 v;
            v.x = pack_f16x2(whh[(128 + n) * 64 + kA], whh[(128 + n) * 64 + kA + 1]);
            v.y = pack_f16x2(whh[(128 + n) * 64 + kB], whh[(128 + n) * 64 + kB + 1]);
            sNH[n * NHSTRIDE + kt * 4 + q] = v;
        }
        #pragma unroll 1
        for (int i = tid; i < 24 * 16; i += 512) {
            const int n   = i >> 4;
            const int rem = i & 15;
            const int kt  = rem >> 2, q = rem & 3;
            const int kA  = 2 * (q + 8 * kt);
            const int kB  = kA + 8;
            const float* fr = fc1_w + n * 128 + 64 * dir;
            uint2 w;
            w.x = pack_f16x2(fr[kA], fr[kA + 1]);
            w.y = pack_f16x2(fr[kB], fr[kB + 1]);
            sF1[n * NHSTRIDE + kt * 4 + q] = w;
        }
        // ---- per-column gate constant tables ----
        if (tid < 64) {
            const int c = tid;
            gcR[c] = make_float4(wih[2*c],       wih[2*c+1],       bih[c] + bhh[c], 0.0f);
            gcZ[c] = make_float4(wih[2*(64+c)],  wih[2*(64+c)+1],  bih[64+c] + bhh[64+c], 0.0f);
            gcN[c] = make_float4(wih[2*(128+c)], wih[2*(128+c)+1], bih[128+c], bhh[128+c]);
        }
        __syncthreads();

        float    hprev[8][4];
        uint32_t Ahi[4][4];
        #pragma unroll
        for (int g = 0; g < 8; g++)
            #pragma unroll
            for (int i = 0; i < 4; i++) hprev[g][i] = 0.0f;
        #pragma unroll
        for (int kt = 0; kt < 4; kt++)
            #pragma unroll
            for (int i = 0; i < 4; i++) Ahi[kt][i] = 0u;

        #pragma unroll 1
        for (int s = 0; s < 19; ++s) {
            const int t = dir ? (17 - s) : s;

            if (s < 18) {
                const float2 xa = *(const float2*)(x + (size_t)row0 * 36 + t * 2);
                const float2 xb = *(const float2*)(x + (size_t)(row0 + 8) * 36 + t * 2);
                uint32_t Anh[4][4];

                #pragma unroll
                for (int g = 0; g < 8; g++) {
                    const int c0 = g * 8 + qd * 2;
                    const float4 r0 = gcR[c0], r1 = gcR[c0 + 1];
                    const float4 z0 = gcZ[c0], z1 = gcZ[c0 + 1];
                    const float4 n0 = gcN[c0], n1 = gcN[c0 + 1];
                    float aR[4], aZ[4], aN[4];
                    aR[0] = r0.z + xa.x * r0.x + xa.y * r0.y;
                    aR[1] = r1.z + xa.x * r1.x + xa.y * r1.y;
                    aR[2] = r0.z + xb.x * r0.x + xb.y * r0.y;
                    aR[3] = r1.z + xb.x * r1.x + xb.y * r1.y;
                    aZ[0] = z0.z + xa.x * z0.x + xa.y * z0.y;
                    aZ[1] = z1.z + xa.x * z1.x + xa.y * z1.y;
                    aZ[2] = z0.z + xb.x * z0.x + xb.y * z0.y;
                    aZ[3] = z1.z + xb.x * z1.x + xb.y * z1.y;
                    aN[0] = n0.z + xa.x * n0.x + xa.y * n0.y;
                    aN[1] = n1.z + xa.x * n1.x + xa.y * n1.y;
                    aN[2] = n0.z + xb.x * n0.x + xb.y * n0.y;
                    aN[3] = n1.z + xb.x * n1.x + xb.y * n1.y;

                    float cr[4] = {0,0,0,0}, cz[4] = {0,0,0,0}, ch[4] = {0,0,0,0};
                    if (s > 0) {
                        #pragma unroll
                        for (int kt = 0; kt < 4; kt++)
                            rz_mma(cr, cz, sRZth + g * (8 * RZSTRIDE) + kt * 4, Ahi[kt]);
                        #pragma unroll
                        for (int kt = 0; kt < 4; kt++)
                            one_mma(ch, sNHth + g * (8 * NHSTRIDE) + kt * 4, Ahi[kt]);
                    }
                    #pragma unroll
                    for (int i = 0; i < 4; i++) {
                        const float bnhh = (i & 1) ? n1.w : n0.w;
                        const float r = sig_hw(cr[i] + aR[i]);
                        const float z = sig_hw(cz[i] + aZ[i]);
                        const float n = tanh_hw(aN[i] + r * (ch[i] + bnhh));
                        hprev[g][i] = n + z * (hprev[g][i] - n);
                    }
                    // pack h_new into next-step A fragments (fp16, single product)
                    const uint32_t ph01 = pack_f16x2(hprev[g][0], hprev[g][1]);
                    const uint32_t ph23 = pack_f16x2(hprev[g][2], hprev[g][3]);
                    if ((g & 1) == 0) {
                        Anh[g >> 1][0] = ph01; Anh[g >> 1][1] = ph23;
                    } else {
                        Anh[g >> 1][2] = ph01; Anh[g >> 1][3] = ph23;
                    }
                }

                // ---- fc1 tiles on h_{s-1} + fused fc2 scatter ----
                if (s >= 1) {
                    float f0[4] = {0,0,0,0}, f1[4] = {0,0,0,0}, f2[4] = {0,0,0,0};
                    #pragma unroll
                    for (int kt = 0; kt < 4; kt++) {
                        one_mma(f0, sF1th + 0 * (8 * NHSTRIDE) + kt * 4, Ahi[kt]);
                        one_mma(f1, sF1th + 1 * (8 * NHSTRIDE) + kt * 4, Ahi[kt]);
                        one_mma(f2, sF1th + 2 * (8 * NHSTRIDE) + kt * 4, Ahi[kt]);
                    }
                    const int tf = dir ? (18 - s) : (s - 1);
                    const float vv0[6] = {f0[0], f0[1], f1[0], f1[1], f2[0], f2[1]};
                    const float vv8[6] = {f0[2], f0[3], f1[2], f1[3], f2[2], f2[3]};
                    #pragma unroll
                    for (int j = 0; j < 6; j++) {
                        const int n_ = tf * 24 + kk[j];
                        const int rr = n_ / 18;
                        const int jj = n_ - rr * 18;
                        const float2 w2 = fc2p[jj];
                        const float fb = dir ? 0.0f : fbv[j];
                        const float va = vv0[j] + fb;
                        const float vb = vv8[j] + fb;
                        float2 c0 = a2r0[rr];
                        c0.x += va * w2.x; c0.y += va * w2.y;
                        a2r0[rr] = c0;
                        float2 c8 = a2r8[rr];
                        c8.x += vb * w2.x; c8.y += vb * w2.y;
                        a2r8[rr] = c8;
                    }
                }

                #pragma unroll
                for (int kt = 0; kt < 4; kt++)
                    #pragma unroll
                    for (int i = 0; i < 4; i++) Ahi[kt][i] = Anh[kt][i];
            } else {
                // ---- s=18: fc1 on h_17 + fused fc2 scatter ----
                float f0[4] = {0,0,0,0}, f1[4] = {0,0,0,0}, f2[4] = {0,0,0,0};
                #pragma unroll
                for (int kt = 0; kt < 4; kt++) {
                    one_mma(f0, sF1th + 0 * (8 * NHSTRIDE) + kt * 4, Ahi[kt]);
                    one_mma(f1, sF1th + 1 * (8 * NHSTRIDE) + kt * 4, Ahi[kt]);
                    one_mma(f2, sF1th + 2 * (8 * NHSTRIDE) + kt * 4, Ahi[kt]);
                }
                const int tf = dir ? 0 : 17;
                const float vv0[6] = {f0[0], f0[1], f1[0], f1[1], f2[0], f2[1]};
                const float vv8[6] = {f0[2], f0[3], f1[2], f1[3], f2[2], f2[3]};
                #pragma unroll
                for (int j = 0; j < 6; j++) {
                    const int n_ = tf * 24 + kk[j];
                    const int rr = n_ / 18;
                    const int jj = n_ - rr * 18;
                    const float2 w2 = fc2p[jj];
                    const float fb = dir ? 0.0f : fbv[j];
                    const float va = vv0[j] + fb;
                    const float vb = vv8[j] + fb;
                    float2 c0 = a2r0[rr];
                    c0.x += va * w2.x; c0.y += va * w2.y;
                    a2r0[rr] = c0;
                    float2 c8 = a2r8[rr];
                    c8.x += vb * w2.x; c8.y += vb * w2.y;
                    a2r8[rr] = c8;
                }
            }
        }
    }

    // ---- quad reduce + write (qd==0 lane per row) ----
    const float b0v = __ldg(fc2_b), b1v = __ldg(fc2_b + 1);
    float* o0 = out + (size_t)row0 * 48;
    float* o8 = out + (size_t)(row0 + 8) * 48;
    #pragma unroll
    for (int p = 0; p < 24; p++) {
        float2 v0 = a2r0[p];
        v0.x += __shfl_xor_sync(0xffffffffu, v0.x, 1);
        v0.x += __shfl_xor_sync(0xffffffffu, v0.x, 2);
        v0.y += __shfl_xor_sync(0xffffffffu, v0.y, 1);
        v0.y += __shfl_xor_sync(0xffffffffu, v0.y, 2);
        float2 v8 = a2r8[p];
        v8.x += __shfl_xor_sync(0xffffffffu, v8.x, 1);
        v8.x += __shfl_xor_sync(0xffffffffu, v8.x, 2);
        v8.y += __shfl_xor_sync(0xffffffffu, v8.y, 1);
        v8.y += __shfl_xor_sync(0xffffffffu, v8.y, 2);
        if (qd == 0) {
            o0[2*p]     = v0.x + b0v;
            o0[2*p + 1] = v0.y + b1v;
            o8[2*p]     = v8.x + b0v;
            o8[2*p + 1] = v8.y + b1v;
        }
    }
}

extern "C" void kernel_launch(void* const* d_in, const int* in_sizes, int n_in,
                              void* d_out, int out_size)
{
    const float* x      = (const float*)d_in[0];
    const float* w_ih_f = (const float*)d_in[1];
    const float* w_hh_f = (const float*)d_in[2];
    const float* b_ih_f = (const float*)d_in[3];
    const float* b_hh_f = (const float*)d_in[4];
    const float* w_ih_b = (const float*)d_in[5];
    const float* w_hh_b = (const float*)d_in[6];
    const float* b_ih_b = (const float*)d_in[7];
    const float* b_hh_b = (const float*)d_in[8];
    const float* fc1_w  = (const float*)d_in[9];
    const float* fc1_b  = (const float*)d_in[10];
    const float* fc2_w  = (const float*)d_in[11];
    const float* fc2_b  = (const float*)d_in[12];
    float* out = (float*)d_out;

    const int smem_bytes = 64 * RZSTRIDE * 16        // sRZ
                         + 64 * NHSTRIDE * 8         // sNH
                         + 24 * NHSTRIDE * 8         // sF1
                         + 3 * 64 * 16               // gc tables
                         + 18 * 8;                   // fc2p
    cudaFuncSetAttribute(gru_mma_kernel,
                         cudaFuncAttributeMaxDynamicSharedMemorySize, smem_bytes);
    gru_mma_kernel<<<128, 512, smem_bytes>>>(
        x, w_ih_f, w_hh_f, b_ih_f, b_hh_f,
        w_ih_b, w_hh_b, b_ih_b, b_hh_b, fc1_w, fc1_b, fc2_w, fc2_b, out);
}

// round 13
// speedup vs baseline: 11.6408x; 1.0040x over previous
#include <cuda_runtime.h>
#include <cstdint>

// Bidirectional GRU (B=32768, T=18, I=2, H=64) + fc1(128->24) + reshape + fc2(18->2)
// R13: two m16 row-tiles per warp (32 rows) -> every weight/table LDS feeds 2 tiles,
// halving per-row L1 traffic. 256-thr CTAs, grid 128, 1 CTA/SM, ~170 regs (cap 255).
// h state is pure fp16 (blend reads h_old from A-fragment). fc2 scatter float4 RMW.

#define RZSTRIDE 20            // uint4 per rz-row (16 used + 4 pad)
#define NHSTRIDE 20            // uint2 per nh/fc1 row (16 used + 4 pad)
#define NTHR     256

// ---------- helpers ----------
__device__ __forceinline__ uint32_t pack_f16x2(float a, float b) {
    uint32_t r;
    asm("{.reg .f16 l, h; cvt.rn.f16.f32 l, %1; cvt.rn.f16.f32 h, %2; mov.b32 %0, {l, h};}"
        : "=r"(r) : "f"(a), "f"(b));
    return r;
}
__device__ __forceinline__ float2 unpack_f16x2(uint32_t u) {
    float a, b;
    asm("{.reg .f16 l, h; mov.b32 {l, h}, %2; cvt.f32.f16 %0, l; cvt.f32.f16 %1, h;}"
        : "=f"(a), "=f"(b) : "r"(u));
    return make_float2(a, b);
}
__device__ __forceinline__ float tanh_hw(float x) {
    float r;
    asm("tanh.approx.f32 %0, %1;" : "=f"(r) : "f"(x));
    return r;
}
__device__ __forceinline__ float sig_hw(float x) {
    return fmaf(0.5f, tanh_hw(0.5f * x), 0.5f);
}
__device__ __forceinline__ void mma_f16(float& c0, float& c1, float& c2, float& c3,
                                        uint32_t a0, uint32_t a1, uint32_t a2, uint32_t a3,
                                        uint32_t b0, uint32_t b1) {
    asm volatile("mma.sync.aligned.m16n8k16.row.col.f32.f16.f16.f32 "
                 "{%0,%1,%2,%3}, {%4,%5,%6,%7}, {%8,%9}, {%0,%1,%2,%3};"
                 : "+f"(c0), "+f"(c1), "+f"(c2), "+f"(c3)
                 : "r"(a0), "r"(a1), "r"(a2), "r"(a3), "r"(b0), "r"(b1));
}
#define MMA4(c, A, b0, b1) mma_f16(c[0], c[1], c[2], c[3], A[0], A[1], A[2], A[3], b0, b1)

// ---------- fused kernel: 256 threads, grid 128 (1 CTA/SM) ----------
extern __shared__ uint32_t smem_u[];

__global__ __launch_bounds__(NTHR)
void gru_mma_kernel(const float* __restrict__ x,
                    const float* __restrict__ w_ih_f, const float* __restrict__ w_hh_f,
                    const float* __restrict__ b_ih_f, const float* __restrict__ b_hh_f,
                    const float* __restrict__ w_ih_b, const float* __restrict__ w_hh_b,
                    const float* __restrict__ b_ih_b, const float* __restrict__ b_hh_b,
                    const float* __restrict__ fc1_w, const float* __restrict__ fc1_b,
                    const float* __restrict__ fc2_w, const float* __restrict__ fc2_b,
                    float* __restrict__ out) {
    uint4*  sRZ  = (uint4*)smem_u;                       // 64*RZSTRIDE uint4 (20 KB)
    uint2*  sNH  = (uint2*)(sRZ + 64 * RZSTRIDE);        // 64*NHSTRIDE uint2 (10 KB)
    uint2*  sF1  = sNH + 64 * NHSTRIDE;                  // 24*NHSTRIDE uint2 (3.75 KB)
    float4* gcR  = (float4*)(sF1 + 24 * NHSTRIDE);       // 64
    float4* gcZ  = gcR + 64;                             // 64
    float4* gcN  = gcZ + 64;                             // 64 {w0,w1,bih_n,bhh_n}
    float2* fc2p = (float2*)(gcN + 64);                  // 18 {w_row0[j], w_row1[j]}

    const int tid  = threadIdx.x;
    const int warp = tid >> 5;
    const int lane = tid & 31;
    const int qd   = lane & 3;
    const int row0 = blockIdx.x * 256 + warp * 32 + (lane >> 2);  // rows row0,+8,+16,+24
    const uint4* sRZth = sRZ + (lane >> 2) * RZSTRIDE + qd;
    const uint2* sNHth = sNH + (lane >> 2) * NHSTRIDE + qd;
    const uint2* sF1th = sF1 + (lane >> 2) * NHSTRIDE + qd;

    if (tid < 18) fc2p[tid] = make_float2(fc2_w[tid], fc2_w[18 + tid]);

    // per-thread fixed fc1 column indices + biases
    const int kk0 = qd * 2;
    int kk[6] = {kk0, kk0 + 1, kk0 + 8, kk0 + 9, kk0 + 16, kk0 + 17};
    float fbv[6];
    #pragma unroll
    for (int j = 0; j < 6; j++) fbv[j] = __ldg(fc1_b + kk[j]);

    // fc2 accumulators: float4 component = row {row0, +8, +16, +24}; A=out col0, B=col1
    float4 accA[24], accB[24];
    #pragma unroll
    for (int m = 0; m < 24; m++) {
        accA[m] = make_float4(0.f, 0.f, 0.f, 0.f);
        accB[m] = make_float4(0.f, 0.f, 0.f, 0.f);
    }

    #pragma unroll 1
    for (int dir = 0; dir < 2; ++dir) {
        const float* wih = dir ? w_ih_b : w_ih_f;
        const float* whh = dir ? w_hh_b : w_hh_f;
        const float* bih = dir ? b_ih_b : b_ih_f;
        const float* bhh = dir ? b_hh_b : b_hh_f;

        __syncthreads();
        // ---- pack W' into smem (fp16, B-fragment layout) ----
        #pragma unroll 1
        for (int i = tid; i < 64 * 16; i += NTHR) {
            const int n   = i >> 4;
            const int rem = i & 15;
            const int kt  = rem >> 2, q = rem & 3;
            const int kA  = 2 * (q + 8 * kt);
            const int kB  = kA + 8;
            uint4 w;
            w.x = pack_f16x2(whh[n * 64 + kA],        whh[n * 64 + kA + 1]);
            w.y = pack_f16x2(whh[n * 64 + kB],        whh[n * 64 + kB + 1]);
            w.z = pack_f16x2(whh[(64 + n) * 64 + kA], whh[(64 + n) * 64 + kA + 1]);
            w.w = pack_f16x2(whh[(64 + n) * 64 + kB], whh[(64 + n) * 64 + kB + 1]);
            sRZ[n * RZSTRIDE + kt * 4 + q] = w;

            uint2 v;
            v.x = pack_f16x2(whh[(128 + n) * 64 + kA], whh[(128 + n) * 64 + kA + 1]);
            v.y = pack_f16x2(whh[(128 + n) * 64 + kB], whh[(128 + n) * 64 + kB + 1]);
            sNH[n * NHSTRIDE + kt * 4 + q] = v;
        }
        #pragma unroll 1
        for (int i = tid; i < 24 * 16; i += NTHR) {
            const int n   = i >> 4;
            const int rem = i & 15;
            const int kt  = rem >> 2, q = rem & 3;
            const int kA  = 2 * (q + 8 * kt);
            const int kB  = kA + 8;
            const float* fr = fc1_w + n * 128 + 64 * dir;
            uint2 w;
            w.x = pack_f16x2(fr[kA], fr[kA + 1]);
            w.y = pack_f16x2(fr[kB], fr[kB + 1]);
            sF1[n * NHSTRIDE + kt * 4 + q] = w;
        }
        if (tid < 64) {
            const int c = tid;
            gcR[c] = make_float4(wih[2*c],       wih[2*c+1],       bih[c] + bhh[c], 0.0f);
            gcZ[c] = make_float4(wih[2*(64+c)],  wih[2*(64+c)+1],  bih[64+c] + bhh[64+c], 0.0f);
            gcN[c] = make_float4(wih[2*(128+c)], wih[2*(128+c)+1], bih[128+c], bhh[128+c]);
        }
        __syncthreads();

        uint32_t A0[4][4], A1[4][4];    // tile0 = rows row0/row0+8, tile1 = +16/+24
        #pragma unroll
        for (int kt = 0; kt < 4; kt++)
            #pragma unroll
            for (int i = 0; i < 4; i++) { A0[kt][i] = 0u; A1[kt][i] = 0u; }

        #pragma unroll 1
        for (int s = 0; s < 19; ++s) {
            const int t = dir ? (17 - s) : s;

            // ---- fc1 tiles on h_{s-1} = current A (skip s==0) + fc2 scatter ----
            if (s >= 1) {
                float f00[4] = {0,0,0,0}, f01[4] = {0,0,0,0};
                float f10[4] = {0,0,0,0}, f11[4] = {0,0,0,0};
                float f20[4] = {0,0,0,0}, f21[4] = {0,0,0,0};
                #pragma unroll
                for (int kt = 0; kt < 4; kt++) {
                    const uint2 w0 = sF1th[0 * (8 * NHSTRIDE) + kt * 4];
                    MMA4(f00, A0[kt], w0.x, w0.y);
                    MMA4(f01, A1[kt], w0.x, w0.y);
                    const uint2 w1 = sF1th[1 * (8 * NHSTRIDE) + kt * 4];
                    MMA4(f10, A0[kt], w1.x, w1.y);
                    MMA4(f11, A1[kt], w1.x, w1.y);
                    const uint2 w2 = sF1th[2 * (8 * NHSTRIDE) + kt * 4];
                    MMA4(f20, A0[kt], w2.x, w2.y);
                    MMA4(f21, A1[kt], w2.x, w2.y);
                }
                const int tf = dir ? (18 - s) : (s - 1);
                // vv[j][row]: rows = row0, +8, +16, +24
                const float vr0[6] = {f00[0], f00[1], f10[0], f10[1], f20[0], f20[1]};
                const float vr1[6] = {f00[2], f00[3], f10[2], f10[3], f20[2], f20[3]};
                const float vr2[6] = {f01[0], f01[1], f11[0], f11[1], f21[0], f21[1]};
                const float vr3[6] = {f01[2], f01[3], f11[2], f11[3], f21[2], f21[3]};
                #pragma unroll
                for (int j = 0; j < 6; j++) {
                    const int n_ = tf * 24 + kk[j];
                    const int rr = n_ / 18;
                    const int jj = n_ - rr * 18;
                    const float2 w2 = fc2p[jj];
                    const float fb = dir ? 0.0f : fbv[j];
                    const float v0 = vr0[j] + fb, v1 = vr1[j] + fb;
                    const float v2 = vr2[j] + fb, v3 = vr3[j] + fb;
                    float4 a = accA[rr];
                    a.x += v0 * w2.x; a.y += v1 * w2.x; a.z += v2 * w2.x; a.w += v3 * w2.x;
                    accA[rr] = a;
                    float4 b = accB[rr];
                    b.x += v0 * w2.y; b.y += v1 * w2.y; b.z += v2 * w2.y; b.w += v3 * w2.y;
                    accB[rr] = b;
                }
            }

            if (s >= 18) break;   // s==18: only the fc1/fc2 epilogue above

            // ---- gate update ----
            const float2 xv0 = *(const float2*)(x + (size_t)row0 * 36 + t * 2);
            const float2 xv1 = *(const float2*)(x + (size_t)(row0 + 8)  * 36 + t * 2);
            const float2 xv2 = *(const float2*)(x + (size_t)(row0 + 16) * 36 + t * 2);
            const float2 xv3 = *(const float2*)(x + (size_t)(row0 + 24) * 36 + t * 2);
            uint32_t N0[4][4], N1[4][4];

            #pragma unroll
            for (int g = 0; g < 8; g++) {
                const int c0 = g * 8 + qd * 2;
                const float4 r0 = gcR[c0], r1 = gcR[c0 + 1];
                const float4 z0 = gcZ[c0], z1 = gcZ[c0 + 1];
                const float4 n0 = gcN[c0], n1 = gcN[c0 + 1];

                float cr0[4] = {0,0,0,0}, cz0[4] = {0,0,0,0}, ch0[4] = {0,0,0,0};
                float cr1[4] = {0,0,0,0}, cz1[4] = {0,0,0,0}, ch1[4] = {0,0,0,0};
                if (s > 0) {
                    #pragma unroll
                    for (int kt = 0; kt < 4; kt++) {
                        const uint4 wrz = sRZth[g * (8 * RZSTRIDE) + kt * 4];
                        MMA4(cr0, A0[kt], wrz.x, wrz.y);
                        MMA4(cz0, A0[kt], wrz.z, wrz.w);
                        MMA4(cr1, A1[kt], wrz.x, wrz.y);
                        MMA4(cz1, A1[kt], wrz.z, wrz.w);
                        const uint2 wnh = sNHth[g * (8 * NHSTRIDE) + kt * 4];
                        MMA4(ch0, A0[kt], wnh.x, wnh.y);
                        MMA4(ch1, A1[kt], wnh.x, wnh.y);
                    }
                }
                const int kt_ = g >> 1, sl = (g & 1) * 2;

                // ---- tile 0 (rows row0, row0+8) ----
                {
                    float aR[4], aZ[4], aN[4];
                    aR[0] = r0.z + xv0.x * r0.x + xv0.y * r0.y;
                    aR[1] = r1.z + xv0.x * r1.x + xv0.y * r1.y;
                    aR[2] = r0.z + xv1.x * r0.x + xv1.y * r0.y;
                    aR[3] = r1.z + xv1.x * r1.x + xv1.y * r1.y;
                    aZ[0] = z0.z + xv0.x * z0.x + xv0.y * z0.y;
                    aZ[1] = z1.z + xv0.x * z1.x + xv0.y * z1.y;
                    aZ[2] = z0.z + xv1.x * z0.x + xv1.y * z0.y;
                    aZ[3] = z1.z + xv1.x * z1.x + xv1.y * z1.y;
                    aN[0] = n0.z + xv0.x * n0.x + xv0.y * n0.y;
                    aN[1] = n1.z + xv0.x * n1.x + xv0.y * n1.y;
                    aN[2] = n0.z + xv1.x * n0.x + xv1.y * n0.y;
                    aN[3] = n1.z + xv1.x * n1.x + xv1.y * n1.y;
                    const float2 ho01 = unpack_f16x2(A0[kt_][sl]);
                    const float2 ho23 = unpack_f16x2(A0[kt_][sl + 1]);
                    const float hold[4] = {ho01.x, ho01.y, ho23.x, ho23.y};
                    float hn[4];
                    #pragma unroll
                    for (int i = 0; i < 4; i++) {
                        const float bnhh = (i & 1) ? n1.w : n0.w;
                        const float r = sig_hw(cr0[i] + aR[i]);
                        const float z = sig_hw(cz0[i] + aZ[i]);
                        const float n = tanh_hw(aN[i] + r * (ch0[i] + bnhh));
                        hn[i] = n + z * (hold[i] - n);
                    }
                    N0[kt_][sl]     = pack_f16x2(hn[0], hn[1]);
                    N0[kt_][sl + 1] = pack_f16x2(hn[2], hn[3]);
                }
                // ---- tile 1 (rows row0+16, row0+24) ----
                {
                    float aR[4], aZ[4], aN[4];
                    aR[0] = r0.z + xv2.x * r0.x + xv2.y * r0.y;
                    aR[1] = r1.z + xv2.x * r1.x + xv2.y * r1.y;
                    aR[2] = r0.z + xv3.x * r0.x + xv3.y * r0.y;
                    aR[3] = r1.z + xv3.x * r1.x + xv3.y * r1.y;
                    aZ[0] = z0.z + xv2.x * z0.x + xv2.y * z0.y;
                    aZ[1] = z1.z + xv2.x * z1.x + xv2.y * z1.y;
                    aZ[2] = z0.z + xv3.x * z0.x + xv3.y * z0.y;
                    aZ[3] = z1.z + xv3.x * z1.x + xv3.y * z1.y;
                    aN[0] = n0.z + xv2.x * n0.x + xv2.y * n0.y;
                    aN[1] = n1.z + xv2.x * n1.x + xv2.y * n1.y;
                    aN[2] = n0.z + xv3.x * n0.x + xv3.y * n0.y;
                    aN[3] = n1.z + xv3.x * n1.x + xv3.y * n1.y;
                    const float2 ho01 = unpack_f16x2(A1[kt_][sl]);
                    const float2 ho23 = unpack_f16x2(A1[kt_][sl + 1]);
                    const float hold[4] = {ho01.x, ho01.y, ho23.x, ho23.y};
                    float hn[4];
                    #pragma unroll
                    for (int i = 0; i < 4; i++) {
                        const float bnhh = (i & 1) ? n1.w : n0.w;
                        const float r = sig_hw(cr1[i] + aR[i]);
                        const float z = sig_hw(cz1[i] + aZ[i]);
                        const float n = tanh_hw(aN[i] + r * (ch1[i] + bnhh));
                        hn[i] = n + z * (hold[i] - n);
                    }
                    N1[kt_][sl]     = pack_f16x2(hn[0], hn[1]);
                    N1[kt_][sl + 1] = pack_f16x2(hn[2], hn[3]);
                }
            }

            // ---- rotate ----
            #pragma unroll
            for (int kt = 0; kt < 4; kt++)
                #pragma unroll
                for (int i = 0; i < 4; i++) { A0[kt][i] = N0[kt][i]; A1[kt][i] = N1[kt][i]; }
        }
    }

    // ---- quad reduce + write (qd==0 lane per row) ----
    const float b0v = __ldg(fc2_b), b1v = __ldg(fc2_b + 1);
    #pragma unroll
    for (int p = 0; p < 24; p++) {
        float4 a = accA[p], b = accB[p];
        #pragma unroll
        for (int d = 1; d <= 2; d <<= 1) {
            a.x += __shfl_xor_sync(0xffffffffu, a.x, d);
            a.y += __shfl_xor_sync(0xffffffffu, a.y, d);
            a.z += __shfl_xor_sync(0xffffffffu, a.z, d);
            a.w += __shfl_xor_sync(0xffffffffu, a.w, d);
            b.x += __shfl_xor_sync(0xffffffffu, b.x, d);
            b.y += __shfl_xor_sync(0xffffffffu, b.y, d);
            b.z += __shfl_xor_sync(0xffffffffu, b.z, d);
            b.w += __shfl_xor_sync(0xffffffffu, b.w, d);
        }
        if (qd == 0) {
            out[(size_t)(row0)      * 48 + 2*p]     = a.x + b0v;
            out[(size_t)(row0)      * 48 + 2*p + 1] = b.x + b1v;
            out[(size_t)(row0 + 8)  * 48 + 2*p]     = a.y + b0v;
            out[(size_t)(row0 + 8)  * 48 + 2*p + 1] = b.y + b1v;
            out[(size_t)(row0 + 16) * 48 + 2*p]     = a.z + b0v;
            out[(size_t)(row0 + 16) * 48 + 2*p + 1] = b.z + b1v;
            out[(size_t)(row0 + 24) * 48 + 2*p]     = a.w + b0v;
            out[(size_t)(row0 + 24) * 48 + 2*p + 1] = b.w + b1v;
        }
    }
}

extern "C" void kernel_launch(void* const* d_in, const int* in_sizes, int n_in,
                              void* d_out, int out_size)
{
    const float* x      = (const float*)d_in[0];
    const float* w_ih_f = (const float*)d_in[1];
    const float* w_hh_f = (const float*)d_in[2];
    const float* b_ih_f = (const float*)d_in[3];
    const float* b_hh_f = (const float*)d_in[4];
    const float* w_ih_b = (const float*)d_in[5];
    const float* w_hh_b = (const float*)d_in[6];
    const float* b_ih_b = (const float*)d_in[7];
    const float* b_hh_b = (const float*)d_in[8];
    const float* fc1_w  = (const float*)d_in[9];
    const float* fc1_b  = (const float*)d_in[10];
    const float* fc2_w  = (const float*)d_in[11];
    const float* fc2_b  = (const float*)d_in[12];
    float* out = (float*)d_out;

    const int smem_bytes = 64 * RZSTRIDE * 16        // sRZ
                         + 64 * NHSTRIDE * 8         // sNH
                         + 24 * NHSTRIDE * 8         // sF1
                         + 3 * 64 * 16               // gc tables
                         + 18 * 8;                   // fc2p
    cudaFuncSetAttribute(gru_mma_kernel,
                         cudaFuncAttributeMaxDynamicSharedMemorySize, smem_bytes);
    gru_mma_kernel<<<128, NTHR, smem_bytes>>>(
        x, w_ih_f, w_hh_f, b_ih_f, b_hh_f,
        w_ih_b, w_hh_b, b_ih_b, b_hh_b, fc1_w, fc1_b, fc2_w, fc2_b, out);
}

// round 14
// speedup vs baseline: 12.9840x; 1.1154x over previous
#include <cuda_runtime.h>
#include <cstdint>

// Bidirectional GRU (B=32768, T=18, I=2, H=64) + fc1(128->24) + reshape + fc2(18->2)
// R14: R12 shape (512 thr, grid 128, 1 m16-tile/warp) + x/bias folded into a kt=4
// MMA tile (deletes ~190 scalar FFMA + table LDS per step). fp16 h-hold (no fp32
// shadow). Only bnhh remains scalar (inside the tanh argument).

#define RZSTRIDE 20            // uint4 per rz-row, kt0-3 (16 used + 4 pad)
#define NHSTRIDE 20            // uint2 per nh/fc1 row, kt0-3 (16 used + 4 pad)
#define NTHR     512

// ---------- helpers ----------
__device__ __forceinline__ uint32_t pack_f16x2(float a, float b) {
    uint32_t r;
    asm("{.reg .f16 l, h; cvt.rn.f16.f32 l, %1; cvt.rn.f16.f32 h, %2; mov.b32 %0, {l, h};}"
        : "=r"(r) : "f"(a), "f"(b));
    return r;
}
__device__ __forceinline__ float2 unpack_f16x2(uint32_t u) {
    float a, b;
    asm("{.reg .f16 l, h; mov.b32 {l, h}, %2; cvt.f32.f16 %0, l; cvt.f32.f16 %1, h;}"
        : "=f"(a), "=f"(b) : "r"(u));
    return make_float2(a, b);
}
__device__ __forceinline__ float tanh_hw(float x) {
    float r;
    asm("tanh.approx.f32 %0, %1;" : "=f"(r) : "f"(x));
    return r;
}
__device__ __forceinline__ float sig_hw(float x) {
    return fmaf(0.5f, tanh_hw(0.5f * x), 0.5f);
}
__device__ __forceinline__ void mma_f16(float& c0, float& c1, float& c2, float& c3,
                                        uint32_t a0, uint32_t a1, uint32_t a2, uint32_t a3,
                                        uint32_t b0, uint32_t b1) {
    asm volatile("mma.sync.aligned.m16n8k16.row.col.f32.f16.f16.f32 "
                 "{%0,%1,%2,%3}, {%4,%5,%6,%7}, {%8,%9}, {%0,%1,%2,%3};"
                 : "+f"(c0), "+f"(c1), "+f"(c2), "+f"(c3)
                 : "r"(a0), "r"(a1), "r"(a2), "r"(a3), "r"(b0), "r"(b1));
}
#define MMA4(c, A, b0, b1) mma_f16(c[0], c[1], c[2], c[3], A[0], A[1], A[2], A[3], b0, b1)

// ---------- fused kernel: 512 threads, grid 128 ----------
extern __shared__ uint32_t smem_u[];

__global__ __launch_bounds__(NTHR)
void gru_mma_kernel(const float* __restrict__ x,
                    const float* __restrict__ w_ih_f, const float* __restrict__ w_hh_f,
                    const float* __restrict__ b_ih_f, const float* __restrict__ b_hh_f,
                    const float* __restrict__ w_ih_b, const float* __restrict__ w_hh_b,
                    const float* __restrict__ b_ih_b, const float* __restrict__ b_hh_b,
                    const float* __restrict__ fc1_w, const float* __restrict__ fc1_b,
                    const float* __restrict__ fc2_w, const float* __restrict__ fc2_b,
                    float* __restrict__ out) {
    uint4*  sRZ   = (uint4*)smem_u;                      // 64*RZSTRIDE uint4, kt0-3
    uint2*  sNH   = (uint2*)(sRZ + 64 * RZSTRIDE);       // 64*NHSTRIDE uint2, kt0-3
    uint2*  sF1   = sNH + 64 * NHSTRIDE;                 // 24*NHSTRIDE uint2
    uint4*  sRZ4  = (uint4*)(sF1 + 24 * NHSTRIDE);       // 64 cols x 4 q  (kt4 r+z)
    uint2*  sNH4  = (uint2*)(sRZ4 + 256);                // 64 cols x 4 q  (kt4 n)
    float2* gcB   = (float2*)(sNH4 + 256);               // 32 (bnhh pairs)
    float2* fc2p  = gcB + 32;                            // 18 {w_row0[j], w_row1[j]}

    const int tid  = threadIdx.x;
    const int warp = tid >> 5;
    const int lane = tid & 31;
    const int qd   = lane & 3;
    const int row0 = blockIdx.x * 256 + warp * 16 + (lane >> 2);   // rows row0, row0+8
    const uint4* sRZth  = sRZ  + (lane >> 2) * RZSTRIDE + qd;
    const uint2* sNHth  = sNH  + (lane >> 2) * NHSTRIDE + qd;
    const uint2* sF1th  = sF1  + (lane >> 2) * NHSTRIDE + qd;
    const uint4* sRZ4th = sRZ4 + (lane >> 2) * 4 + qd;
    const uint2* sNH4th = sNH4 + (lane >> 2) * 4 + qd;

    if (tid < 18) fc2p[tid] = make_float2(fc2_w[tid], fc2_w[18 + tid]);

    // per-thread fixed fc1 column indices + biases
    const int kk0 = qd * 2;
    int kk[6] = {kk0, kk0 + 1, kk0 + 8, kk0 + 9, kk0 + 16, kk0 + 17};
    float fbv[6];
    #pragma unroll
    for (int j = 0; j < 6; j++) fbv[j] = __ldg(fc1_b + kk[j]);

    // fc2 accumulators (dynamic-indexed -> local mem), float2 granularity
    float2 a2r0[24], a2r8[24];
    #pragma unroll
    for (int m = 0; m < 24; m++) {
        a2r0[m] = make_float2(0.0f, 0.0f);
        a2r8[m] = make_float2(0.0f, 0.0f);
    }

    #pragma unroll 1
    for (int dir = 0; dir < 2; ++dir) {
        const float* wih = dir ? w_ih_b : w_ih_f;
        const float* whh = dir ? w_hh_b : w_hh_f;
        const float* bih = dir ? b_ih_b : b_ih_f;
        const float* bhh = dir ? b_hh_b : b_hh_f;

        __syncthreads();
        // ---- pack W' kt0-3 (h-part) into smem ----
        #pragma unroll 1
        for (int i = tid; i < 64 * 16; i += NTHR) {
            const int n   = i >> 4;
            const int rem = i & 15;
            const int kt  = rem >> 2, q = rem & 3;
            const int kA  = 2 * (q + 8 * kt);
            const int kB  = kA + 8;
            uint4 w;
            w.x = pack_f16x2(whh[n * 64 + kA],        whh[n * 64 + kA + 1]);
            w.y = pack_f16x2(whh[n * 64 + kB],        whh[n * 64 + kB + 1]);
            w.z = pack_f16x2(whh[(64 + n) * 64 + kA], whh[(64 + n) * 64 + kA + 1]);
            w.w = pack_f16x2(whh[(64 + n) * 64 + kB], whh[(64 + n) * 64 + kB + 1]);
            sRZ[n * RZSTRIDE + kt * 4 + q] = w;

            uint2 v;
            v.x = pack_f16x2(whh[(128 + n) * 64 + kA], whh[(128 + n) * 64 + kA + 1]);
            v.y = pack_f16x2(whh[(128 + n) * 64 + kB], whh[(128 + n) * 64 + kB + 1]);
            sNH[n * NHSTRIDE + kt * 4 + q] = v;
        }
        #pragma unroll 1
        for (int i = tid; i < 24 * 16; i += NTHR) {
            const int n   = i >> 4;
            const int rem = i & 15;
            const int kt  = rem >> 2, q = rem & 3;
            const int kA  = 2 * (q + 8 * kt);
            const int kB  = kA + 8;
            const float* fr = fc1_w + n * 128 + 64 * dir;
            uint2 w;
            w.x = pack_f16x2(fr[kA], fr[kA + 1]);
            w.y = pack_f16x2(fr[kB], fr[kB + 1]);
            sF1[n * NHSTRIDE + kt * 4 + q] = w;
        }
        // ---- pack kt4 tiles: local k0=wih0, k1=wih1, k2=bias, rest 0 ----
        if (tid < 256) {
            const int n = tid >> 2, q = tid & 3;
            uint4 w = make_uint4(0u, 0u, 0u, 0u);
            uint2 v = make_uint2(0u, 0u);
            if (q == 0) {
                w.x = pack_f16x2(wih[2*n],          wih[2*n + 1]);
                w.z = pack_f16x2(wih[2*(64 + n)],   wih[2*(64 + n) + 1]);
                v.x = pack_f16x2(wih[2*(128 + n)],  wih[2*(128 + n) + 1]);
            } else if (q == 1) {
                w.x = pack_f16x2(bih[n] + bhh[n], 0.0f);
                w.z = pack_f16x2(bih[64 + n] + bhh[64 + n], 0.0f);
                v.x = pack_f16x2(bih[128 + n], 0.0f);
            }
            sRZ4[n * 4 + q] = w;
            sNH4[n * 4 + q] = v;
        }
        if (tid < 32) gcB[tid] = make_float2(bhh[128 + 2*tid], bhh[128 + 2*tid + 1]);
        __syncthreads();

        uint32_t A[4][4];
        #pragma unroll
        for (int kt = 0; kt < 4; kt++)
            #pragma unroll
            for (int i = 0; i < 4; i++) A[kt][i] = 0u;

        #pragma unroll 1
        for (int s = 0; s < 19; ++s) {
            const int t = dir ? (17 - s) : s;

            if (s < 18) {
                const float2 xa = *(const float2*)(x + (size_t)row0 * 36 + t * 2);
                const float2 xb = *(const float2*)(x + (size_t)(row0 + 8) * 36 + t * 2);

                // ---- kt4 A fragment: k0=x0, k1=x1, k2=1 ----
                uint32_t a4[4] = {0u, 0u, 0u, 0u};
                if (qd == 0) {
                    a4[0] = pack_f16x2(xa.x, xa.y);
                    a4[1] = pack_f16x2(xb.x, xb.y);
                } else if (qd == 1) {
                    a4[0] = 0x00003C00u;   // (1.0h, 0h)
                    a4[1] = 0x00003C00u;
                }

                uint32_t N[4][4];
                #pragma unroll
                for (int g = 0; g < 8; g++) {
                    float cr[4] = {0,0,0,0}, cz[4] = {0,0,0,0};
                    float ch[4] = {0,0,0,0}, cnx[4] = {0,0,0,0};
                    // kt4 (x + bias) — always
                    {
                        const uint4 w4 = sRZ4th[g * 32];
                        MMA4(cr, a4, w4.x, w4.y);
                        MMA4(cz, a4, w4.z, w4.w);
                        const uint2 v4 = sNH4th[g * 32];
                        MMA4(cnx, a4, v4.x, v4.y);
                    }
                    if (s > 0) {
                        #pragma unroll
                        for (int kt = 0; kt < 4; kt++) {
                            const uint4 wrz = sRZth[g * (8 * RZSTRIDE) + kt * 4];
                            MMA4(cr, A[kt], wrz.x, wrz.y);
                            MMA4(cz, A[kt], wrz.z, wrz.w);
                            const uint2 wnh = sNHth[g * (8 * NHSTRIDE) + kt * 4];
                            MMA4(ch, A[kt], wnh.x, wnh.y);
                        }
                    }
                    const float2 bn = gcB[g * 4 + qd];
                    const int kt_ = g >> 1, sl = (g & 1) * 2;
                    const float2 ho01 = unpack_f16x2(A[kt_][sl]);
                    const float2 ho23 = unpack_f16x2(A[kt_][sl + 1]);
                    const float hold[4] = {ho01.x, ho01.y, ho23.x, ho23.y};
                    float hn[4];
                    #pragma unroll
                    for (int i = 0; i < 4; i++) {
                        const float bnhh = (i & 1) ? bn.y : bn.x;
                        const float r = sig_hw(cr[i]);
                        const float z = sig_hw(cz[i]);
                        const float n = tanh_hw(cnx[i] + r * (ch[i] + bnhh));
                        hn[i] = n + z * (hold[i] - n);
                    }
                    N[kt_][sl]     = pack_f16x2(hn[0], hn[1]);
                    N[kt_][sl + 1] = pack_f16x2(hn[2], hn[3]);
                }

                // ---- fc1 tiles on h_{s-1} = current A + fused fc2 scatter ----
                if (s >= 1) {
                    float f0[4] = {0,0,0,0}, f1[4] = {0,0,0,0}, f2[4] = {0,0,0,0};
                    #pragma unroll
                    for (int kt = 0; kt < 4; kt++) {
                        const uint2 w0 = sF1th[0 * (8 * NHSTRIDE) + kt * 4];
                        MMA4(f0, A[kt], w0.x, w0.y);
                        const uint2 w1 = sF1th[1 * (8 * NHSTRIDE) + kt * 4];
                        MMA4(f1, A[kt], w1.x, w1.y);
                        const uint2 w2 = sF1th[2 * (8 * NHSTRIDE) + kt * 4];
                        MMA4(f2, A[kt], w2.x, w2.y);
                    }
                    const int tf = dir ? (18 - s) : (s - 1);
                    const float vv0[6] = {f0[0], f0[1], f1[0], f1[1], f2[0], f2[1]};
                    const float vv8[6] = {f0[2], f0[3], f1[2], f1[3], f2[2], f2[3]};
                    #pragma unroll
                    for (int j = 0; j < 6; j++) {
                        const int n_ = tf * 24 + kk[j];
                        const int rr = n_ / 18;
                        const int jj = n_ - rr * 18;
                        const float2 w2 = fc2p[jj];
                        const float fb = dir ? 0.0f : fbv[j];
                        const float va = vv0[j] + fb;
                        const float vb = vv8[j] + fb;
                        float2 c0 = a2r0[rr];
                        c0.x += va * w2.x; c0.y += va * w2.y;
                        a2r0[rr] = c0;
                        float2 c8 = a2r8[rr];
                        c8.x += vb * w2.x; c8.y += vb * w2.y;
                        a2r8[rr] = c8;
                    }
                }

                #pragma unroll
                for (int kt = 0; kt < 4; kt++)
                    #pragma unroll
                    for (int i = 0; i < 4; i++) A[kt][i] = N[kt][i];
            } else {
                // ---- s=18: fc1 on h_17 + fused fc2 scatter ----
                float f0[4] = {0,0,0,0}, f1[4] = {0,0,0,0}, f2[4] = {0,0,0,0};
                #pragma unroll
                for (int kt = 0; kt < 4; kt++) {
                    const uint2 w0 = sF1th[0 * (8 * NHSTRIDE) + kt * 4];
                    MMA4(f0, A[kt], w0.x, w0.y);
                    const uint2 w1 = sF1th[1 * (8 * NHSTRIDE) + kt * 4];
                    MMA4(f1, A[kt], w1.x, w1.y);
                    const uint2 w2 = sF1th[2 * (8 * NHSTRIDE) + kt * 4];
                    MMA4(f2, A[kt], w2.x, w2.y);
                }
                const int tf = dir ? 0 : 17;
                const float vv0[6] = {f0[0], f0[1], f1[0], f1[1], f2[0], f2[1]};
                const float vv8[6] = {f0[2], f0[3], f1[2], f1[3], f2[2], f2[3]};
                #pragma unroll
                for (int j = 0; j < 6; j++) {
                    const int n_ = tf * 24 + kk[j];
                    const int rr = n_ / 18;
                    const int jj = n_ - rr * 18;
                    const float2 w2 = fc2p[jj];
                    const float fb = dir ? 0.0f : fbv[j];
                    const float va = vv0[j] + fb;
                    const float vb = vv8[j] + fb;
                    float2 c0 = a2r0[rr];
                    c0.x += va * w2.x; c0.y += va * w2.y;
                    a2r0[rr] = c0;
                    float2 c8 = a2r8[rr];
                    c8.x += vb * w2.x; c8.y += vb * w2.y;
                    a2r8[rr] = c8;
                }
            }
        }
    }

    // ---- quad reduce + write (qd==0 lane per row) ----
    const float b0v = __ldg(fc2_b), b1v = __ldg(fc2_b + 1);
    float* o0 = out + (size_t)row0 * 48;
    float* o8 = out + (size_t)(row0 + 8) * 48;
    #pragma unroll
    for (int p = 0; p < 24; p++) {
        float2 v0 = a2r0[p];
        v0.x += __shfl_xor_sync(0xffffffffu, v0.x, 1);
        v0.x += __shfl_xor_sync(0xffffffffu, v0.x, 2);
        v0.y += __shfl_xor_sync(0xffffffffu, v0.y, 1);
        v0.y += __shfl_xor_sync(0xffffffffu, v0.y, 2);
        float2 v8 = a2r8[p];
        v8.x += __shfl_xor_sync(0xffffffffu, v8.x, 1);
        v8.x += __shfl_xor_sync(0xffffffffu, v8.x, 2);
        v8.y += __shfl_xor_sync(0xffffffffu, v8.y, 1);
        v8.y += __shfl_xor_sync(0xffffffffu, v8.y, 2);
        if (qd == 0) {
            o0[2*p]     = v0.x + b0v;
            o0[2*p + 1] = v0.y + b1v;
            o8[2*p]     = v8.x + b0v;
            o8[2*p + 1] = v8.y + b1v;
        }
    }
}

extern "C" void kernel_launch(void* const* d_in, const int* in_sizes, int n_in,
                              void* d_out, int out_size)
{
    const float* x      = (const float*)d_in[0];
    const float* w_ih_f = (const float*)d_in[1];
    const float* w_hh_f = (const float*)d_in[2];
    const float* b_ih_f = (const float*)d_in[3];
    const float* b_hh_f = (const float*)d_in[4];
    const float* w_ih_b = (const float*)d_in[5];
    const float* w_hh_b = (const float*)d_in[6];
    const float* b_ih_b = (const float*)d_in[7];
    const float* b_hh_b = (const float*)d_in[8];
    const float* fc1_w  = (const float*)d_in[9];
    const float* fc1_b  = (const float*)d_in[10];
    const float* fc2_w  = (const float*)d_in[11];
    const float* fc2_b  = (const float*)d_in[12];
    float* out = (float*)d_out;

    const int smem_bytes = 64 * RZSTRIDE * 16        // sRZ
                         + 64 * NHSTRIDE * 8         // sNH
                         + 24 * NHSTRIDE * 8         // sF1
                         + 256 * 16                  // sRZ4
                         + 256 * 8                   // sNH4
                         + 32 * 8                    // gcB
                         + 18 * 8;                   // fc2p
    cudaFuncSetAttribute(gru_mma_kernel,
                         cudaFuncAttributeMaxDynamicSharedMemorySize, smem_bytes);
    gru_mma_kernel<<<128, NTHR, smem_bytes>>>(
        x, w_ih_f, w_hh_f, b_ih_f, b_hh_f,
        w_ih_b, w_hh_b, b_ih_b, b_hh_b, fc1_w, fc1_b, fc2_w, fc2_b, out);
}

// round 15
// speedup vs baseline: 13.5506x; 1.0436x over previous
#include <cuda_runtime.h>
#include <cstdint>

// Bidirectional GRU (B=32768, T=18, I=2, H=64) + fc1(128->24) + reshape + fc2(18->2)
// R15: R14 + half2 gate math. tanh.approx.f16x2 for r/z/n (MUFU halved), r/z
// weights pre-scaled by 0.5 (sigmoid = 0.5*tanh2+0.5 with no runtime scale),
// blend fully in f16x2 (A-fragment slots consumed/produced directly, no packs).

#define RZSTRIDE 20            // uint4 per rz-row, kt0-3 (16 used + 4 pad)
#define NHSTRIDE 20            // uint2 per nh/fc1 row, kt0-3 (16 used + 4 pad)
#define NTHR     512

// ---------- helpers ----------
__device__ __forceinline__ uint32_t pack_f16x2(float a, float b) {
    uint32_t r;
    asm("{.reg .f16 l, h; cvt.rn.f16.f32 l, %1; cvt.rn.f16.f32 h, %2; mov.b32 %0, {l, h};}"
        : "=r"(r) : "f"(a), "f"(b));
    return r;
}
__device__ __forceinline__ uint32_t cvt2(float hi, float lo) {   // lo -> low half
    uint32_t r;
    asm("cvt.rn.f16x2.f32 %0, %1, %2;" : "=r"(r) : "f"(hi), "f"(lo));
    return r;
}
__device__ __forceinline__ uint32_t tanh2(uint32_t x) {
    uint32_t r;
    asm("tanh.approx.f16x2 %0, %1;" : "=r"(r) : "r"(x));
    return r;
}
__device__ __forceinline__ uint32_t hfma2_(uint32_t a, uint32_t b, uint32_t c) {
    uint32_t r;
    asm("fma.rn.f16x2 %0, %1, %2, %3;" : "=r"(r) : "r"(a), "r"(b), "r"(c));
    return r;
}
__device__ __forceinline__ uint32_t hadd2_(uint32_t a, uint32_t b) {
    uint32_t r;
    asm("add.rn.f16x2 %0, %1, %2;" : "=r"(r) : "r"(a), "r"(b));
    return r;
}
__device__ __forceinline__ uint32_t hsub2_(uint32_t a, uint32_t b) {
    uint32_t r;
    asm("sub.rn.f16x2 %0, %1, %2;" : "=r"(r) : "r"(a), "r"(b));
    return r;
}
#define K05 0x38003800u        // (0.5h, 0.5h)

__device__ __forceinline__ void mma_f16(float& c0, float& c1, float& c2, float& c3,
                                        uint32_t a0, uint32_t a1, uint32_t a2, uint32_t a3,
                                        uint32_t b0, uint32_t b1) {
    asm volatile("mma.sync.aligned.m16n8k16.row.col.f32.f16.f16.f32 "
                 "{%0,%1,%2,%3}, {%4,%5,%6,%7}, {%8,%9}, {%0,%1,%2,%3};"
                 : "+f"(c0), "+f"(c1), "+f"(c2), "+f"(c3)
                 : "r"(a0), "r"(a1), "r"(a2), "r"(a3), "r"(b0), "r"(b1));
}
#define MMA4(c, A, b0, b1) mma_f16(c[0], c[1], c[2], c[3], A[0], A[1], A[2], A[3], b0, b1)

// ---------- fused kernel: 512 threads, grid 128 ----------
extern __shared__ uint32_t smem_u[];

__global__ __launch_bounds__(NTHR)
void gru_mma_kernel(const float* __restrict__ x,
                    const float* __restrict__ w_ih_f, const float* __restrict__ w_hh_f,
                    const float* __restrict__ b_ih_f, const float* __restrict__ b_hh_f,
                    const float* __restrict__ w_ih_b, const float* __restrict__ w_hh_b,
                    const float* __restrict__ b_ih_b, const float* __restrict__ b_hh_b,
                    const float* __restrict__ fc1_w, const float* __restrict__ fc1_b,
                    const float* __restrict__ fc2_w, const float* __restrict__ fc2_b,
                    float* __restrict__ out) {
    uint4*    sRZ   = (uint4*)smem_u;                    // 64*RZSTRIDE uint4, kt0-3
    uint2*    sNH   = (uint2*)(sRZ + 64 * RZSTRIDE);     // 64*NHSTRIDE uint2, kt0-3
    uint2*    sF1   = sNH + 64 * NHSTRIDE;               // 24*NHSTRIDE uint2
    uint4*    sRZ4  = (uint4*)(sF1 + 24 * NHSTRIDE);     // 64 cols x 4 q (kt4 r+z)
    uint2*    sNH4  = (uint2*)(sRZ4 + 256);              // 64 cols x 4 q (kt4 n)
    uint32_t* gcBu  = (uint32_t*)(sNH4 + 256);           // 32 (bnhh f16x2 pairs)
    float2*   fc2p  = (float2*)(gcBu + 32);              // 18 {w_row0[j], w_row1[j]}

    const int tid  = threadIdx.x;
    const int warp = tid >> 5;
    const int lane = tid & 31;
    const int qd   = lane & 3;
    const int row0 = blockIdx.x * 256 + warp * 16 + (lane >> 2);   // rows row0, row0+8
    const uint4* sRZth  = sRZ  + (lane >> 2) * RZSTRIDE + qd;
    const uint2* sNHth  = sNH  + (lane >> 2) * NHSTRIDE + qd;
    const uint2* sF1th  = sF1  + (lane >> 2) * NHSTRIDE + qd;
    const uint4* sRZ4th = sRZ4 + (lane >> 2) * 4 + qd;
    const uint2* sNH4th = sNH4 + (lane >> 2) * 4 + qd;

    if (tid < 18) fc2p[tid] = make_float2(fc2_w[tid], fc2_w[18 + tid]);

    // per-thread fixed fc1 column indices + biases
    const int kk0 = qd * 2;
    int kk[6] = {kk0, kk0 + 1, kk0 + 8, kk0 + 9, kk0 + 16, kk0 + 17};
    float fbv[6];
    #pragma unroll
    for (int j = 0; j < 6; j++) fbv[j] = __ldg(fc1_b + kk[j]);

    // fc2 accumulators (dynamic-indexed -> local mem), float2 granularity
    float2 a2r0[24], a2r8[24];
    #pragma unroll
    for (int m = 0; m < 24; m++) {
        a2r0[m] = make_float2(0.0f, 0.0f);
        a2r8[m] = make_float2(0.0f, 0.0f);
    }

    #pragma unroll 1
    for (int dir = 0; dir < 2; ++dir) {
        const float* wih = dir ? w_ih_b : w_ih_f;
        const float* whh = dir ? w_hh_b : w_hh_f;
        const float* bih = dir ? b_ih_b : b_ih_f;
        const float* bhh = dir ? b_hh_b : b_hh_f;

        __syncthreads();
        // ---- pack W' kt0-3 into smem; r/z rows pre-scaled by 0.5 ----
        #pragma unroll 1
        for (int i = tid; i < 64 * 16; i += NTHR) {
            const int n   = i >> 4;
            const int rem = i & 15;
            const int kt  = rem >> 2, q = rem & 3;
            const int kA  = 2 * (q + 8 * kt);
            const int kB  = kA + 8;
            uint4 w;
            w.x = pack_f16x2(0.5f * whh[n * 64 + kA],        0.5f * whh[n * 64 + kA + 1]);
            w.y = pack_f16x2(0.5f * whh[n * 64 + kB],        0.5f * whh[n * 64 + kB + 1]);
            w.z = pack_f16x2(0.5f * whh[(64 + n) * 64 + kA], 0.5f * whh[(64 + n) * 64 + kA + 1]);
            w.w = pack_f16x2(0.5f * whh[(64 + n) * 64 + kB], 0.5f * whh[(64 + n) * 64 + kB + 1]);
            sRZ[n * RZSTRIDE + kt * 4 + q] = w;

            uint2 v;
            v.x = pack_f16x2(whh[(128 + n) * 64 + kA], whh[(128 + n) * 64 + kA + 1]);
            v.y = pack_f16x2(whh[(128 + n) * 64 + kB], whh[(128 + n) * 64 + kB + 1]);
            sNH[n * NHSTRIDE + kt * 4 + q] = v;
        }
        #pragma unroll 1
        for (int i = tid; i < 24 * 16; i += NTHR) {
            const int n   = i >> 4;
            const int rem = i & 15;
            const int kt  = rem >> 2, q = rem & 3;
            const int kA  = 2 * (q + 8 * kt);
            const int kB  = kA + 8;
            const float* fr = fc1_w + n * 128 + 64 * dir;
            uint2 w;
            w.x = pack_f16x2(fr[kA], fr[kA + 1]);
            w.y = pack_f16x2(fr[kB], fr[kB + 1]);
            sF1[n * NHSTRIDE + kt * 4 + q] = w;
        }
        // ---- kt4 tiles (x + bias); r/z entries pre-scaled by 0.5 ----
        if (tid < 256) {
            const int n = tid >> 2, q = tid & 3;
            uint4 w = make_uint4(0u, 0u, 0u, 0u);
            uint2 v = make_uint2(0u, 0u);
            if (q == 0) {
                w.x = pack_f16x2(0.5f * wih[2*n],        0.5f * wih[2*n + 1]);
                w.z = pack_f16x2(0.5f * wih[2*(64 + n)], 0.5f * wih[2*(64 + n) + 1]);
                v.x = pack_f16x2(wih[2*(128 + n)],       wih[2*(128 + n) + 1]);
            } else if (q == 1) {
                w.x = pack_f16x2(0.5f * (bih[n] + bhh[n]), 0.0f);
                w.z = pack_f16x2(0.5f * (bih[64 + n] + bhh[64 + n]), 0.0f);
                v.x = pack_f16x2(bih[128 + n], 0.0f);
            }
            sRZ4[n * 4 + q] = w;
            sNH4[n * 4 + q] = v;
        }
        if (tid < 32)
            gcBu[tid] = pack_f16x2(bhh[128 + 2*tid], bhh[128 + 2*tid + 1]);
        __syncthreads();

        uint32_t A[4][4];
        #pragma unroll
        for (int kt = 0; kt < 4; kt++)
            #pragma unroll
            for (int i = 0; i < 4; i++) A[kt][i] = 0u;

        #pragma unroll 1
        for (int s = 0; s < 19; ++s) {
            const int t = dir ? (17 - s) : s;

            if (s < 18) {
                const float2 xa = *(const float2*)(x + (size_t)row0 * 36 + t * 2);
                const float2 xb = *(const float2*)(x + (size_t)(row0 + 8) * 36 + t * 2);

                // ---- kt4 A fragment: k0=x0, k1=x1, k2=1 ----
                uint32_t a4[4] = {0u, 0u, 0u, 0u};
                if (qd == 0) {
                    a4[0] = pack_f16x2(xa.x, xa.y);
                    a4[1] = pack_f16x2(xb.x, xb.y);
                } else if (qd == 1) {
                    a4[0] = 0x00003C00u;   // (1.0h, 0h)
                    a4[1] = 0x00003C00u;
                }

                uint32_t N[4][4];
                #pragma unroll
                for (int g = 0; g < 8; g++) {
                    float cr[4] = {0,0,0,0}, cz[4] = {0,0,0,0};
                    float ch[4] = {0,0,0,0}, cnx[4] = {0,0,0,0};
                    // kt4 (x + bias) — always
                    {
                        const uint4 w4 = sRZ4th[g * 32];
                        MMA4(cr, a4, w4.x, w4.y);
                        MMA4(cz, a4, w4.z, w4.w);
                        const uint2 v4 = sNH4th[g * 32];
                        MMA4(cnx, a4, v4.x, v4.y);
                    }
                    if (s > 0) {
                        #pragma unroll
                        for (int kt = 0; kt < 4; kt++) {
                            const uint4 wrz = sRZth[g * (8 * RZSTRIDE) + kt * 4];
                            MMA4(cr, A[kt], wrz.x, wrz.y);
                            MMA4(cz, A[kt], wrz.z, wrz.w);
                            const uint2 wnh = sNHth[g * (8 * NHSTRIDE) + kt * 4];
                            MMA4(ch, A[kt], wnh.x, wnh.y);
                        }
                    }
                    // ---- half2 gate tail ----
                    const uint32_t bn2 = gcBu[g * 4 + qd];
                    const int kt_ = g >> 1, sl = (g & 1) * 2;
                    // r = 0.5*tanh(arg) + 0.5  (arg pre-scaled by weights)
                    const uint32_t r2a = hfma2_(tanh2(cvt2(cr[1], cr[0])), K05, K05);
                    const uint32_t r2b = hfma2_(tanh2(cvt2(cr[3], cr[2])), K05, K05);
                    const uint32_t z2a = hfma2_(tanh2(cvt2(cz[1], cz[0])), K05, K05);
                    const uint32_t z2b = hfma2_(tanh2(cvt2(cz[3], cz[2])), K05, K05);
                    const uint32_t ch2a = hadd2_(cvt2(ch[1], ch[0]), bn2);
                    const uint32_t ch2b = hadd2_(cvt2(ch[3], ch[2]), bn2);
                    const uint32_t na = tanh2(hfma2_(r2a, ch2a, cvt2(cnx[1], cnx[0])));
                    const uint32_t nb = tanh2(hfma2_(r2b, ch2b, cvt2(cnx[3], cnx[2])));
                    const uint32_t holda = A[kt_][sl];
                    const uint32_t holdb = A[kt_][sl + 1];
                    N[kt_][sl]     = hfma2_(z2a, hsub2_(holda, na), na);
                    N[kt_][sl + 1] = hfma2_(z2b, hsub2_(holdb, nb), nb);
                }

                // ---- fc1 tiles on h_{s-1} = current A + fused fc2 scatter ----
                if (s >= 1) {
                    float f0[4] = {0,0,0,0}, f1[4] = {0,0,0,0}, f2[4] = {0,0,0,0};
                    #pragma unroll
                    for (int kt = 0; kt < 4; kt++) {
                        const uint2 w0 = sF1th[0 * (8 * NHSTRIDE) + kt * 4];
                        MMA4(f0, A[kt], w0.x, w0.y);
                        const uint2 w1 = sF1th[1 * (8 * NHSTRIDE) + kt * 4];
                        MMA4(f1, A[kt], w1.x, w1.y);
                        const uint2 w2 = sF1th[2 * (8 * NHSTRIDE) + kt * 4];
                        MMA4(f2, A[kt], w2.x, w2.y);
                    }
                    const int tf = dir ? (18 - s) : (s - 1);
                    const float vv0[6] = {f0[0], f0[1], f1[0], f1[1], f2[0], f2[1]};
                    const float vv8[6] = {f0[2], f0[3], f1[2], f1[3], f2[2], f2[3]};
                    #pragma unroll
                    for (int j = 0; j < 6; j++) {
                        const int n_ = tf * 24 + kk[j];
                        const int rr = n_ / 18;
                        const int jj = n_ - rr * 18;
                        const float2 w2 = fc2p[jj];
                        const float fb = dir ? 0.0f : fbv[j];
                        const float va = vv0[j] + fb;
                        const float vb = vv8[j] + fb;
                        float2 c0 = a2r0[rr];
                        c0.x += va * w2.x; c0.y += va * w2.y;
                        a2r0[rr] = c0;
                        float2 c8 = a2r8[rr];
                        c8.x += vb * w2.x; c8.y += vb * w2.y;
                        a2r8[rr] = c8;
                    }
                }

                #pragma unroll
                for (int kt = 0; kt < 4; kt++)
                    #pragma unroll
                    for (int i = 0; i < 4; i++) A[kt][i] = N[kt][i];
            } else {
                // ---- s=18: fc1 on h_17 + fused fc2 scatter ----
                float f0[4] = {0,0,0,0}, f1[4] = {0,0,0,0}, f2[4] = {0,0,0,0};
                #pragma unroll
                for (int kt = 0; kt < 4; kt++) {
                    const uint2 w0 = sF1th[0 * (8 * NHSTRIDE) + kt * 4];
                    MMA4(f0, A[kt], w0.x, w0.y);
                    const uint2 w1 = sF1th[1 * (8 * NHSTRIDE) + kt * 4];
                    MMA4(f1, A[kt], w1.x, w1.y);
                    const uint2 w2 = sF1th[2 * (8 * NHSTRIDE) + kt * 4];
                    MMA4(f2, A[kt], w2.x, w2.y);
                }
                const int tf = dir ? 0 : 17;
                const float vv0[6] = {f0[0], f0[1], f1[0], f1[1], f2[0], f2[1]};
                const float vv8[6] = {f0[2], f0[3], f1[2], f1[3], f2[2], f2[3]};
                #pragma unroll
                for (int j = 0; j < 6; j++) {
                    const int n_ = tf * 24 + kk[j];
                    const int rr = n_ / 18;
                    const int jj = n_ - rr * 18;
                    const float2 w2 = fc2p[jj];
                    const float fb = dir ? 0.0f : fbv[j];
                    const float va = vv0[j] + fb;
                    const float vb = vv8[j] + fb;
                    float2 c0 = a2r0[rr];
                    c0.x += va * w2.x; c0.y += va * w2.y;
                    a2r0[rr] = c0;
                    float2 c8 = a2r8[rr];
                    c8.x += vb * w2.x; c8.y += vb * w2.y;
                    a2r8[rr] = c8;
                }
            }
        }
    }

    // ---- quad reduce + write (qd==0 lane per row) ----
    const float b0v = __ldg(fc2_b), b1v = __ldg(fc2_b + 1);
    float* o0 = out + (size_t)row0 * 48;
    float* o8 = out + (size_t)(row0 + 8) * 48;
    #pragma unroll
    for (int p = 0; p < 24; p++) {
        float2 v0 = a2r0[p];
        v0.x += __shfl_xor_sync(0xffffffffu, v0.x, 1);
        v0.x += __shfl_xor_sync(0xffffffffu, v0.x, 2);
        v0.y += __shfl_xor_sync(0xffffffffu, v0.y, 1);
        v0.y += __shfl_xor_sync(0xffffffffu, v0.y, 2);
        float2 v8 = a2r8[p];
        v8.x += __shfl_xor_sync(0xffffffffu, v8.x, 1);
        v8.x += __shfl_xor_sync(0xffffffffu, v8.x, 2);
        v8.y += __shfl_xor_sync(0xffffffffu, v8.y, 1);
        v8.y += __shfl_xor_sync(0xffffffffu, v8.y, 2);
        if (qd == 0) {
            o0[2*p]     = v0.x + b0v;
            o0[2*p + 1] = v0.y + b1v;
            o8[2*p]     = v8.x + b0v;
            o8[2*p + 1] = v8.y + b1v;
        }
    }
}

extern "C" void kernel_launch(void* const* d_in, const int* in_sizes, int n_in,
                              void* d_out, int out_size)
{
    const float* x      = (const float*)d_in[0];
    const float* w_ih_f = (const float*)d_in[1];
    const float* w_hh_f = (const float*)d_in[2];
    const float* b_ih_f = (const float*)d_in[3];
    const float* b_hh_f = (const float*)d_in[4];
    const float* w_ih_b = (const float*)d_in[5];
    const float* w_hh_b = (const float*)d_in[6];
    const float* b_ih_b = (const float*)d_in[7];
    const float* b_hh_b = (const float*)d_in[8];
    const float* fc1_w  = (const float*)d_in[9];
    const float* fc1_b  = (const float*)d_in[10];
    const float* fc2_w  = (const float*)d_in[11];
    const float* fc2_b  = (const float*)d_in[12];
    float* out = (float*)d_out;

    const int smem_bytes = 64 * RZSTRIDE * 16        // sRZ
                         + 64 * NHSTRIDE * 8         // sNH
                         + 24 * NHSTRIDE * 8         // sF1
                         + 256 * 16                  // sRZ4
                         + 256 * 8                   // sNH4
                         + 32 * 4                    // gcBu
                         + 18 * 8;                   // fc2p
    cudaFuncSetAttribute(gru_mma_kernel,
                         cudaFuncAttributeMaxDynamicSharedMemorySize, smem_bytes);
    gru_mma_kernel<<<128, NTHR, smem_bytes>>>(
        x, w_ih_f, w_hh_f, b_ih_f, b_hh_f,
        w_ih_b, w_hh_b, b_ih_b, b_hh_b, fc1_w, fc1_b, fc2_w, fc2_b, out);
}

// round 16
// speedup vs baseline: 13.9812x; 1.0318x over previous
#include <cuda_runtime.h>
#include <cstdint>

// Bidirectional GRU (B=32768, T=18, I=2, H=64) + fc1(128->24) + reshape + fc2(18->2)
// R16: both directions interleaved per step (2x independent chains per warp for
// latency hiding). Weights for both dirs packed once (~82 KB smem), no mid-kernel
// repack/barrier. Gate math in half2 (R15), single-product fp16 MMA.

#define RZSTRIDE 20            // uint4 per rz-row, kt0-3 (16 used + 4 pad)
#define NHSTRIDE 20            // uint2 per nh/fc1 row, kt0-3 (16 used + 4 pad)
#define NTHR     512

// ---------- helpers ----------
__device__ __forceinline__ uint32_t pack_f16x2(float a, float b) {
    uint32_t r;
    asm("{.reg .f16 l, h; cvt.rn.f16.f32 l, %1; cvt.rn.f16.f32 h, %2; mov.b32 %0, {l, h};}"
        : "=r"(r) : "f"(a), "f"(b));
    return r;
}
__device__ __forceinline__ uint32_t cvt2(float hi, float lo) {   // lo -> low half
    uint32_t r;
    asm("cvt.rn.f16x2.f32 %0, %1, %2;" : "=r"(r) : "f"(hi), "f"(lo));
    return r;
}
__device__ __forceinline__ uint32_t tanh2(uint32_t x) {
    uint32_t r;
    asm("tanh.approx.f16x2 %0, %1;" : "=r"(r) : "r"(x));
    return r;
}
__device__ __forceinline__ uint32_t hfma2_(uint32_t a, uint32_t b, uint32_t c) {
    uint32_t r;
    asm("fma.rn.f16x2 %0, %1, %2, %3;" : "=r"(r) : "r"(a), "r"(b), "r"(c));
    return r;
}
__device__ __forceinline__ uint32_t hadd2_(uint32_t a, uint32_t b) {
    uint32_t r;
    asm("add.rn.f16x2 %0, %1, %2;" : "=r"(r) : "r"(a), "r"(b));
    return r;
}
__device__ __forceinline__ uint32_t hsub2_(uint32_t a, uint32_t b) {
    uint32_t r;
    asm("sub.rn.f16x2 %0, %1, %2;" : "=r"(r) : "r"(a), "r"(b));
    return r;
}
#define K05 0x38003800u        // (0.5h, 0.5h)

__device__ __forceinline__ void mma_f16(float& c0, float& c1, float& c2, float& c3,
                                        uint32_t a0, uint32_t a1, uint32_t a2, uint32_t a3,
                                        uint32_t b0, uint32_t b1) {
    asm volatile("mma.sync.aligned.m16n8k16.row.col.f32.f16.f16.f32 "
                 "{%0,%1,%2,%3}, {%4,%5,%6,%7}, {%8,%9}, {%0,%1,%2,%3};"
                 : "+f"(c0), "+f"(c1), "+f"(c2), "+f"(c3)
                 : "r"(a0), "r"(a1), "r"(a2), "r"(a3), "r"(b0), "r"(b1));
}
#define MMA4(c, A, b0, b1) mma_f16(c[0], c[1], c[2], c[3], A[0], A[1], A[2], A[3], b0, b1)

// ---------- per-direction step helpers ----------
__device__ __forceinline__ void gate_step(uint32_t A[4][4], uint32_t N[4][4],
                                          const uint32_t a4[4],
                                          const uint4* sRZth, const uint2* sNHth,
                                          const uint4* sRZ4th, const uint2* sNH4th,
                                          const uint32_t* gcB, int qd, bool hasH) {
    #pragma unroll
    for (int g = 0; g < 8; g++) {
        float cr[4] = {0,0,0,0}, cz[4] = {0,0,0,0};
        float ch[4] = {0,0,0,0}, cnx[4] = {0,0,0,0};
        {
            const uint4 w4 = sRZ4th[g * 32];
            MMA4(cr, a4, w4.x, w4.y);
            MMA4(cz, a4, w4.z, w4.w);
            const uint2 v4 = sNH4th[g * 32];
            MMA4(cnx, a4, v4.x, v4.y);
        }
        if (hasH) {
            #pragma unroll
            for (int kt = 0; kt < 4; kt++) {
                const uint4 wrz = sRZth[g * (8 * RZSTRIDE) + kt * 4];
                MMA4(cr, A[kt], wrz.x, wrz.y);
                MMA4(cz, A[kt], wrz.z, wrz.w);
                const uint2 wnh = sNHth[g * (8 * NHSTRIDE) + kt * 4];
                MMA4(ch, A[kt], wnh.x, wnh.y);
            }
        }
        const uint32_t bn2 = gcB[g * 4 + qd];
        const int kt_ = g >> 1, sl = (g & 1) * 2;
        const uint32_t r2a = hfma2_(tanh2(cvt2(cr[1], cr[0])), K05, K05);
        const uint32_t r2b = hfma2_(tanh2(cvt2(cr[3], cr[2])), K05, K05);
        const uint32_t z2a = hfma2_(tanh2(cvt2(cz[1], cz[0])), K05, K05);
        const uint32_t z2b = hfma2_(tanh2(cvt2(cz[3], cz[2])), K05, K05);
        const uint32_t ch2a = hadd2_(cvt2(ch[1], ch[0]), bn2);
        const uint32_t ch2b = hadd2_(cvt2(ch[3], ch[2]), bn2);
        const uint32_t na = tanh2(hfma2_(r2a, ch2a, cvt2(cnx[1], cnx[0])));
        const uint32_t nb = tanh2(hfma2_(r2b, ch2b, cvt2(cnx[3], cnx[2])));
        const uint32_t holda = A[kt_][sl];
        const uint32_t holdb = A[kt_][sl + 1];
        N[kt_][sl]     = hfma2_(z2a, hsub2_(holda, na), na);
        N[kt_][sl + 1] = hfma2_(z2b, hsub2_(holdb, nb), nb);
    }
}

__device__ __forceinline__ void fc1_step(float f[3][4], const uint32_t A[4][4],
                                         const uint2* sF1th) {
    #pragma unroll
    for (int q = 0; q < 3; q++)
        #pragma unroll
        for (int i = 0; i < 4; i++) f[q][i] = 0.0f;
    #pragma unroll
    for (int kt = 0; kt < 4; kt++) {
        const uint2 w0 = sF1th[0 * (8 * NHSTRIDE) + kt * 4];
        MMA4(f[0], A[kt], w0.x, w0.y);
        const uint2 w1 = sF1th[1 * (8 * NHSTRIDE) + kt * 4];
        MMA4(f[1], A[kt], w1.x, w1.y);
        const uint2 w2 = sF1th[2 * (8 * NHSTRIDE) + kt * 4];
        MMA4(f[2], A[kt], w2.x, w2.y);
    }
}

__device__ __forceinline__ void fc2_scatter(float2* a2r0, float2* a2r8,
                                            const float f[3][4], int tf,
                                            const int kk[6], const float* fbv, bool addb,
                                            const float2* fc2p) {
    const float vv0[6] = {f[0][0], f[0][1], f[1][0], f[1][1], f[2][0], f[2][1]};
    const float vv8[6] = {f[0][2], f[0][3], f[1][2], f[1][3], f[2][2], f[2][3]};
    #pragma unroll
    for (int j = 0; j < 6; j++) {
        const int n_ = tf * 24 + kk[j];
        const int rr = n_ / 18;
        const int jj = n_ - rr * 18;
        const float2 w2 = fc2p[jj];
        const float fb = addb ? fbv[j] : 0.0f;
        const float va = vv0[j] + fb;
        const float vb = vv8[j] + fb;
        float2 c0 = a2r0[rr];
        c0.x += va * w2.x; c0.y += va * w2.y;
        a2r0[rr] = c0;
        float2 c8 = a2r8[rr];
        c8.x += vb * w2.x; c8.y += vb * w2.y;
        a2r8[rr] = c8;
    }
}

// ---------- fused kernel: 512 threads, grid 128 ----------
extern __shared__ uint32_t smem_u[];

__global__ __launch_bounds__(NTHR)
void gru_mma_kernel(const float* __restrict__ x,
                    const float* __restrict__ w_ih_f, const float* __restrict__ w_hh_f,
                    const float* __restrict__ b_ih_f, const float* __restrict__ b_hh_f,
                    const float* __restrict__ w_ih_b, const float* __restrict__ w_hh_b,
                    const float* __restrict__ b_ih_b, const float* __restrict__ b_hh_b,
                    const float* __restrict__ fc1_w, const float* __restrict__ fc1_b,
                    const float* __restrict__ fc2_w, const float* __restrict__ fc2_b,
                    float* __restrict__ out) {
    // per-dir smem regions
    uint4*    sRZ   = (uint4*)smem_u;                     // [2][64*RZSTRIDE]
    uint2*    sNH   = (uint2*)(sRZ + 2 * 64 * RZSTRIDE);  // [2][64*NHSTRIDE]
    uint2*    sF1   = sNH + 2 * 64 * NHSTRIDE;            // [2][24*NHSTRIDE]
    uint4*    sRZ4  = (uint4*)(sF1 + 2 * 24 * NHSTRIDE);  // [2][256]
    uint2*    sNH4  = (uint2*)(sRZ4 + 2 * 256);           // [2][256]
    uint32_t* gcBu  = (uint32_t*)(sNH4 + 2 * 256);        // [2][32]
    float2*   fc2p  = (float2*)(gcBu + 64);               // 18

    const int tid  = threadIdx.x;
    const int warp = tid >> 5;
    const int lane = tid & 31;
    const int qd   = lane & 3;
    const int row0 = blockIdx.x * 256 + warp * 16 + (lane >> 2);   // rows row0, row0+8
    const int thro = (lane >> 2);

    if (tid < 18) fc2p[tid] = make_float2(fc2_w[tid], fc2_w[18 + tid]);

    const int kk0 = qd * 2;
    int kk[6] = {kk0, kk0 + 1, kk0 + 8, kk0 + 9, kk0 + 16, kk0 + 17};
    float fbv[6];
    #pragma unroll
    for (int j = 0; j < 6; j++) fbv[j] = __ldg(fc1_b + kk[j]);

    float2 a2r0[24], a2r8[24];
    #pragma unroll
    for (int m = 0; m < 24; m++) {
        a2r0[m] = make_float2(0.0f, 0.0f);
        a2r8[m] = make_float2(0.0f, 0.0f);
    }

    // ---- pack BOTH directions' weights once ----
    #pragma unroll 1
    for (int dir = 0; dir < 2; ++dir) {
        const float* wih = dir ? w_ih_b : w_ih_f;
        const float* whh = dir ? w_hh_b : w_hh_f;
        const float* bih = dir ? b_ih_b : b_ih_f;
        const float* bhh = dir ? b_hh_b : b_hh_f;
        uint4* dRZ  = sRZ  + dir * 64 * RZSTRIDE;
        uint2* dNH  = sNH  + dir * 64 * NHSTRIDE;
        uint2* dF1  = sF1  + dir * 24 * NHSTRIDE;
        uint4* dRZ4 = sRZ4 + dir * 256;
        uint2* dNH4 = sNH4 + dir * 256;

        #pragma unroll 1
        for (int i = tid; i < 64 * 16; i += NTHR) {
            const int n   = i >> 4;
            const int rem = i & 15;
            const int kt  = rem >> 2, q = rem & 3;
            const int kA  = 2 * (q + 8 * kt);
            const int kB  = kA + 8;
            uint4 w;
            w.x = pack_f16x2(0.5f * whh[n * 64 + kA],        0.5f * whh[n * 64 + kA + 1]);
            w.y = pack_f16x2(0.5f * whh[n * 64 + kB],        0.5f * whh[n * 64 + kB + 1]);
            w.z = pack_f16x2(0.5f * whh[(64 + n) * 64 + kA], 0.5f * whh[(64 + n) * 64 + kA + 1]);
            w.w = pack_f16x2(0.5f * whh[(64 + n) * 64 + kB], 0.5f * whh[(64 + n) * 64 + kB + 1]);
            dRZ[n * RZSTRIDE + kt * 4 + q] = w;

            uint2 v;
            v.x = pack_f16x2(whh[(128 + n) * 64 + kA], whh[(128 + n) * 64 + kA + 1]);
            v.y = pack_f16x2(whh[(128 + n) * 64 + kB], whh[(128 + n) * 64 + kB + 1]);
            dNH[n * NHSTRIDE + kt * 4 + q] = v;
        }
        #pragma unroll 1
        for (int i = tid; i < 24 * 16; i += NTHR) {
            const int n   = i >> 4;
            const int rem = i & 15;
            const int kt  = rem >> 2, q = rem & 3;
            const int kA  = 2 * (q + 8 * kt);
            const int kB  = kA + 8;
            const float* fr = fc1_w + n * 128 + 64 * dir;
            uint2 w;
            w.x = pack_f16x2(fr[kA], fr[kA + 1]);
            w.y = pack_f16x2(fr[kB], fr[kB + 1]);
            dF1[n * NHSTRIDE + kt * 4 + q] = w;
        }
        if (tid < 256) {
            const int n = tid >> 2, q = tid & 3;
            uint4 w = make_uint4(0u, 0u, 0u, 0u);
            uint2 v = make_uint2(0u, 0u);
            if (q == 0) {
                w.x = pack_f16x2(0.5f * wih[2*n],        0.5f * wih[2*n + 1]);
                w.z = pack_f16x2(0.5f * wih[2*(64 + n)], 0.5f * wih[2*(64 + n) + 1]);
                v.x = pack_f16x2(wih[2*(128 + n)],       wih[2*(128 + n) + 1]);
            } else if (q == 1) {
                w.x = pack_f16x2(0.5f * (bih[n] + bhh[n]), 0.0f);
                w.z = pack_f16x2(0.5f * (bih[64 + n] + bhh[64 + n]), 0.0f);
                v.x = pack_f16x2(bih[128 + n], 0.0f);
            }
            dRZ4[n * 4 + q] = w;
            dNH4[n * 4 + q] = v;
        }
        if (tid < 32)
            gcBu[dir * 32 + tid] = pack_f16x2(bhh[128 + 2*tid], bhh[128 + 2*tid + 1]);
    }
    __syncthreads();

    // per-thread fragment pointers, both dirs
    const uint4*    sRZ0  = sRZ  + thro * RZSTRIDE + qd;
    const uint4*    sRZ1  = sRZ0 + 64 * RZSTRIDE;
    const uint2*    sNH0  = sNH  + thro * NHSTRIDE + qd;
    const uint2*    sNH1  = sNH0 + 64 * NHSTRIDE;
    const uint2*    sF10  = sF1  + thro * NHSTRIDE + qd;
    const uint2*    sF11  = sF10 + 24 * NHSTRIDE;
    const uint4*    sRZ40 = sRZ4 + thro * 4 + qd;
    const uint4*    sRZ41 = sRZ40 + 256;
    const uint2*    sNH40 = sNH4 + thro * 4 + qd;
    const uint2*    sNH41 = sNH40 + 256;
    const uint32_t* gcB0  = gcBu;
    const uint32_t* gcB1  = gcBu + 32;

    uint32_t A0[4][4], A1[4][4];
    #pragma unroll
    for (int kt = 0; kt < 4; kt++)
        #pragma unroll
        for (int i = 0; i < 4; i++) { A0[kt][i] = 0u; A1[kt][i] = 0u; }

    const float* xr0 = x + (size_t)row0 * 36;
    const float* xr8 = x + (size_t)(row0 + 8) * 36;

    #pragma unroll 1
    for (int s = 0; s < 18; ++s) {
        const int t0 = s;
        const int t1 = 17 - s;

        // ---- build kt4 A fragments for both dirs ----
        uint32_t a40[4] = {0u, 0u, 0u, 0u};
        uint32_t a41[4] = {0u, 0u, 0u, 0u};
        if (qd == 0) {
            const float2 xa0 = *(const float2*)(xr0 + t0 * 2);
            const float2 xb0 = *(const float2*)(xr8 + t0 * 2);
            const float2 xa1 = *(const float2*)(xr0 + t1 * 2);
            const float2 xb1 = *(const float2*)(xr8 + t1 * 2);
            a40[0] = pack_f16x2(xa0.x, xa0.y);
            a40[1] = pack_f16x2(xb0.x, xb0.y);
            a41[0] = pack_f16x2(xa1.x, xa1.y);
            a41[1] = pack_f16x2(xb1.x, xb1.y);
        } else if (qd == 1) {
            a40[0] = a40[1] = 0x00003C00u;   // (1.0h, 0h)
            a41[0] = a41[1] = 0x00003C00u;
        }

        // ---- fc1 on h_{s-1} (old A) for both dirs, then scatter ----
        if (s >= 1) {
            float f0[3][4], f1[3][4];
            fc1_step(f0, A0, sF10);
            fc1_step(f1, A1, sF11);
            fc2_scatter(a2r0, a2r8, f0, s - 1,  kk, fbv, true,  fc2p);
            fc2_scatter(a2r0, a2r8, f1, 18 - s, kk, fbv, false, fc2p);
        }

        // ---- gate updates, both dirs ----
        uint32_t N0[4][4], N1[4][4];
        gate_step(A0, N0, a40, sRZ0, sNH0, sRZ40, sNH40, gcB0, qd, s > 0);
        gate_step(A1, N1, a41, sRZ1, sNH1, sRZ41, sNH41, gcB1, qd, s > 0);

        #pragma unroll
        for (int kt = 0; kt < 4; kt++)
            #pragma unroll
            for (int i = 0; i < 4; i++) { A0[kt][i] = N0[kt][i]; A1[kt][i] = N1[kt][i]; }
    }

    // ---- s=18: fc1 on h_17 for both dirs ----
    {
        float f0[3][4], f1[3][4];
        fc1_step(f0, A0, sF10);
        fc1_step(f1, A1, sF11);
        fc2_scatter(a2r0, a2r8, f0, 17, kk, fbv, true,  fc2p);
        fc2_scatter(a2r0, a2r8, f1, 0,  kk, fbv, false, fc2p);
    }

    // ---- quad reduce + write (qd==0 lane per row) ----
    const float b0v = __ldg(fc2_b), b1v = __ldg(fc2_b + 1);
    float* o0 = out + (size_t)row0 * 48;
    float* o8 = out + (size_t)(row0 + 8) * 48;
    #pragma unroll
    for (int p = 0; p < 24; p++) {
        float2 v0 = a2r0[p];
        v0.x += __shfl_xor_sync(0xffffffffu, v0.x, 1);
        v0.x += __shfl_xor_sync(0xffffffffu, v0.x, 2);
        v0.y += __shfl_xor_sync(0xffffffffu, v0.y, 1);
        v0.y += __shfl_xor_sync(0xffffffffu, v0.y, 2);
        float2 v8 = a2r8[p];
        v8.x += __shfl_xor_sync(0xffffffffu, v8.x, 1);
        v8.x += __shfl_xor_sync(0xffffffffu, v8.x, 2);
        v8.y += __shfl_xor_sync(0xffffffffu, v8.y, 1);
        v8.y += __shfl_xor_sync(0xffffffffu, v8.y, 2);
        if (qd == 0) {
            o0[2*p]     = v0.x + b0v;
            o0[2*p + 1] = v0.y + b1v;
            o8[2*p]     = v8.x + b0v;
            o8[2*p + 1] = v8.y + b1v;
        }
    }
}

extern "C" void kernel_launch(void* const* d_in, const int* in_sizes, int n_in,
                              void* d_out, int out_size)
{
    const float* x      = (const float*)d_in[0];
    const float* w_ih_f = (const float*)d_in[1];
    const float* w_hh_f = (const float*)d_in[2];
    const float* b_ih_f = (const float*)d_in[3];
    const float* b_hh_f = (const float*)d_in[4];
    const float* w_ih_b = (const float*)d_in[5];
    const float* w_hh_b = (const float*)d_in[6];
    const float* b_ih_b = (const float*)d_in[7];
    const float* b_hh_b = (const float*)d_in[8];
    const float* fc1_w  = (const float*)d_in[9];
    const float* fc1_b  = (const float*)d_in[10];
    const float* fc2_w  = (const float*)d_in[11];
    const float* fc2_b  = (const float*)d_in[12];
    float* out = (float*)d_out;

    const int smem_bytes = 2 * 64 * RZSTRIDE * 16    // sRZ
                         + 2 * 64 * NHSTRIDE * 8     // sNH
                         + 2 * 24 * NHSTRIDE * 8     // sF1
                         + 2 * 256 * 16              // sRZ4
                         + 2 * 256 * 8               // sNH4
                         + 2 * 32 * 4                // gcBu
                         + 18 * 8;                   // fc2p
    cudaFuncSetAttribute(gru_mma_kernel,
                         cudaFuncAttributeMaxDynamicSharedMemorySize, smem_bytes);
    gru_mma_kernel<<<128, NTHR, smem_bytes>>>(
        x, w_ih_f, w_hh_f, b_ih_f, b_hh_f,
        w_ih_b, w_hh_b, b_ih_b, b_hh_b, fc1_w, fc1_b, fc2_w, fc2_b, out);
}